// round 2
// baseline (speedup 1.0000x reference)
#include <cuda_runtime.h>
#include <math.h>

#define HW2 2304
#define HH 48
#define WW 48

// ---------------- device scratch (no allocations allowed) ----------------
__device__ float g_xenc  [2*64 *HW2];
__device__ float g_yenc  [2*64 *HW2];
__device__ float g_f512a [2*512*HW2];
__device__ float g_f512b [2*512*HW2];
__device__ float g_cols  [2*4608*HW2];   // reused for every im2col
__device__ float g_offb  [2*18 *HW2];
__device__ float g_cpart [8*2*18*HW2];   // conv18 channel-split partials
__device__ float g_f177  [2*177*HW2];
__device__ float g_f177b [2*177*HW2];
__device__ float g_wb1   [2*64*576];
__device__ float g_wb2   [2*64*144];
__device__ float g_wb3   [2*256*36];
__device__ float g_fwb   [2*256];
__device__ float g_adw   [2*256*HW2];
__device__ float g_def0  [2*256*HW2];
__device__ float g_def1  [2*256*HW2];
__device__ float g_s1o   [2*128*HW2];
__device__ float g_s2o   [2*64*HW2];
__device__ float g_swa   [2*HW2];
__device__ float g_swb   [2*HW2];

// ---------------- 128x128 tiled fp32 GEMM: C[M,N] = A[M,K]*B[K,N] ----------------
// 256 threads, 8x8 per thread, KT=8, double-buffered smem, register-staged loads.
__global__ __launch_bounds__(256, 2)
void gemm128(const float* __restrict__ A, const float* __restrict__ B,
             float* __restrict__ C, int M, int N, int K,
             long long sA, long long sB, long long sC,
             const float* __restrict__ bias, int relu)
{
    A += (long long)blockIdx.z * sA;
    B += (long long)blockIdx.z * sB;
    C += (long long)blockIdx.z * sC;

    __shared__ float As[2][8][128];
    __shared__ float Bs[2][8][128];

    const int tid = threadIdx.x;
    const int tx = tid & 15;          // 0..15  (cols)
    const int ty = tid >> 4;          // 0..15  (rows)
    const int m0 = blockIdx.y * 128, n0 = blockIdx.x * 128;

    // load roles
    const int ar = tid >> 1;              // A row 0..127
    const int ak = (tid & 1) * 4;         // A k-offset 0 or 4
    const int bk = tid >> 5;              // B k-row 0..7
    const int bn = (tid & 31) * 4;        // B n-offset

    float acc[8][8];
#pragma unroll
    for (int i = 0; i < 8; i++)
#pragma unroll
        for (int j = 0; j < 8; j++) acc[i][j] = 0.f;

    // prologue: tile 0 -> buffer 0
    {
#pragma unroll
        for (int i = 0; i < 4; i++) {
            int k = ak + i;
            As[0][ak + i][ar] = (m0 + ar < M && k < K) ? A[(long long)(m0 + ar) * K + k] : 0.f;
        }
#pragma unroll
        for (int i = 0; i < 4; i++) {
            int n = n0 + bn + i;
            Bs[0][bk][bn + i] = (bk < K && n < N) ? B[(long long)bk * N + n] : 0.f;
        }
    }
    __syncthreads();

    int buf = 0;
    for (int k0 = 0; k0 < K; k0 += 8) {
        const int kn = k0 + 8;
        const bool has = kn < K;
        float la[4], lb[4];
        if (has) {
#pragma unroll
            for (int i = 0; i < 4; i++) {
                int k = kn + ak + i;
                la[i] = (m0 + ar < M && k < K) ? A[(long long)(m0 + ar) * K + k] : 0.f;
            }
#pragma unroll
            for (int i = 0; i < 4; i++) {
                int n = n0 + bn + i;
                lb[i] = (kn + bk < K && n < N) ? B[(long long)(kn + bk) * N + n] : 0.f;
            }
        }

#pragma unroll
        for (int kk = 0; kk < 8; kk++) {
            float a[8], b[8];
            float4 t0 = *(const float4*)&As[buf][kk][ty * 4];
            float4 t1 = *(const float4*)&As[buf][kk][64 + ty * 4];
            float4 u0 = *(const float4*)&Bs[buf][kk][tx * 4];
            float4 u1 = *(const float4*)&Bs[buf][kk][64 + tx * 4];
            a[0]=t0.x; a[1]=t0.y; a[2]=t0.z; a[3]=t0.w;
            a[4]=t1.x; a[5]=t1.y; a[6]=t1.z; a[7]=t1.w;
            b[0]=u0.x; b[1]=u0.y; b[2]=u0.z; b[3]=u0.w;
            b[4]=u1.x; b[5]=u1.y; b[6]=u1.z; b[7]=u1.w;
#pragma unroll
            for (int i = 0; i < 8; i++)
#pragma unroll
                for (int j = 0; j < 8; j++) acc[i][j] += a[i] * b[j];
        }

        if (has) {
            int nb = buf ^ 1;
#pragma unroll
            for (int i = 0; i < 4; i++) As[nb][ak + i][ar] = la[i];
#pragma unroll
            for (int i = 0; i < 4; i++) Bs[nb][bk][bn + i] = lb[i];
        }
        __syncthreads();
        buf ^= 1;
    }

#pragma unroll
    for (int ii = 0; ii < 8; ii++) {
        int m = m0 + ((ii < 4) ? (ty * 4 + ii) : (64 + ty * 4 + ii - 4));
        if (m >= M) continue;
        float bv = bias ? bias[m] : 0.f;
#pragma unroll
        for (int jj = 0; jj < 8; jj++) {
            int n = n0 + ((jj < 4) ? (tx * 4 + jj) : (64 + tx * 4 + jj - 4));
            if (n >= N) continue;
            float v = acc[ii][jj] + bv;
            if (relu) v = fmaxf(v, 0.f);
            C[(long long)m * N + n] = v;
        }
    }
}

// ---------------- 512->18 offset-head 3x3 conv, channel-split partials ----------------
// grid: (9 hw-tiles, 8 channel chunks of 64, batch 2), block 256 (one hw each).
__global__ void conv18_k(const float* __restrict__ in, long long inB,
                         const float* __restrict__ w, float* __restrict__ part, int C)
{
    const int t = blockIdx.x, cc = blockIdx.y, b = blockIdx.z;
    const int tid = threadIdx.x;
    const int hw = t * 256 + tid;
    const int h = hw / WW, x = hw % WW;
    const int hf = (t * 256) / WW;          // first row in this tile

    __shared__ float sIn[4][9 * WW];        // 4 channels x 9 rows
    __shared__ float sW[4][18 * 9];

    float acc[18];
#pragma unroll
    for (int o = 0; o < 18; o++) acc[o] = 0.f;

    const float* ib = in + (long long)b * inB + (long long)(cc * 64) * HW2;
    const int lr = h - (hf - 1);            // local center row: 1..7

    for (int cs = 0; cs < 64; cs += 4) {
        for (int i = tid; i < 4 * 9 * WW; i += 256) {
            int c = i / (9 * WW), r = i % (9 * WW);
            int row = hf - 1 + r / WW, col = r % WW;
            float v = 0.f;
            if (row >= 0 && row < HH) v = ib[(long long)(cs + c) * HW2 + row * WW + col];
            sIn[c][r] = v;
        }
        for (int i = tid; i < 4 * 162; i += 256) {
            int c = i / 162, r = i % 162;   // r = o*9+q
            int o = r / 9, q = r % 9;
            sW[c][r] = w[((long long)o * C + (cc * 64 + cs + c)) * 9 + q];
        }
        __syncthreads();

#pragma unroll
        for (int c = 0; c < 4; c++) {
            float tap[9];
#pragma unroll
            for (int ki = 0; ki < 3; ki++)
#pragma unroll
                for (int kj = 0; kj < 3; kj++) {
                    int xx = x - 1 + kj;
                    float v = 0.f;
                    if (xx >= 0 && xx < WW) v = sIn[c][(lr - 1 + ki) * WW + xx];
                    tap[ki * 3 + kj] = v;
                }
#pragma unroll
            for (int o = 0; o < 18; o++) {
                float s = acc[o];
#pragma unroll
                for (int q = 0; q < 9; q++) s += sW[c][o * 9 + q] * tap[q];
                acc[o] = s;
            }
        }
        __syncthreads();
    }

    float* pp = part + ((long long)cc * 2 + b) * 18 * HW2;
#pragma unroll
    for (int o = 0; o < 18; o++) pp[(long long)o * HW2 + hw] = acc[o];
}

__global__ void reduce18_k(const float* __restrict__ part, float* __restrict__ out)
{
    int idx = blockIdx.x * 256 + threadIdx.x;
    if (idx >= 2 * 18 * HW2) return;
    int b = idx / (18 * HW2);
    int r = idx % (18 * HW2);
    float s = 0.f;
#pragma unroll
    for (int c = 0; c < 8; c++) s += part[((long long)c * 2 + b) * 18 * HW2 + r];
    out[(long long)b * 18 * HW2 + r] = s;
}

// ---------------- deformable (or plain) 3x3 s1 p1 im2col over 48x48 ----------------
__global__ void deform_im2col_k(const float* __restrict__ src, long long srcB,
                                const float* __restrict__ off,
                                float* __restrict__ cols, int C)
{
    int hw = blockIdx.x * 256 + threadIdx.x;
    if (hw >= HW2) return;
    int bq = blockIdx.y;
    int b = bq / 9, q = bq % 9;
    int ki = q / 3, kj = q % 3;
    int h = hw / WW, w = hw % WW;
    const float* sb = src + (long long)b * srcB;
    float* cb = cols + (long long)b * C * 9 * HW2;
    int c0 = blockIdx.z * 64;
    int c1 = c0 + 64; if (c1 > C) c1 = C;

    if (off == nullptr) {
        int y = h - 1 + ki, x = w - 1 + kj;
        bool vin = (y >= 0 && y < HH && x >= 0 && x < WW);
        int idx = vin ? (y * WW + x) : 0;
        for (int c = c0; c < c1; c++) {
            float v = vin ? sb[(long long)c * HW2 + idx] : 0.f;
            cb[((long long)c * 9 + q) * HW2 + hw] = v;
        }
    } else {
        float py = (float)(h - 1 + ki) + off[((long long)b * 18 + 2 * q) * HW2 + hw];
        float px = (float)(w - 1 + kj) + off[((long long)b * 18 + 2 * q + 1) * HW2 + hw];
        float fy = floorf(py), fx = floorf(px);
        float ay = py - fy, ax = px - fx;
        int y0 = (int)fy, x0 = (int)fx;
        int y1 = y0 + 1, x1 = x0 + 1;
        bool by0 = (y0 >= 0 && y0 < HH), by1 = (y1 >= 0 && y1 < HH);
        bool bx0 = (x0 >= 0 && x0 < WW), bx1 = (x1 >= 0 && x1 < WW);
        int yc0 = min(max(y0, 0), HH - 1), yc1 = min(max(y1, 0), HH - 1);
        int xc0 = min(max(x0, 0), WW - 1), xc1 = min(max(x1, 0), WW - 1);
        float w00 = (by0 && bx0) ? (1.f - ay) * (1.f - ax) : 0.f;
        float w01 = (by0 && bx1) ? (1.f - ay) * ax : 0.f;
        float w10 = (by1 && bx0) ? ay * (1.f - ax) : 0.f;
        float w11 = (by1 && bx1) ? ay * ax : 0.f;
        int i00 = yc0 * WW + xc0, i01 = yc0 * WW + xc1;
        int i10 = yc1 * WW + xc0, i11 = yc1 * WW + xc1;
        for (int c = c0; c < c1; c++) {
            const float* s = sb + (long long)c * HW2;
            float v = w00 * s[i00] + w01 * s[i01] + w10 * s[i10] + w11 * s[i11];
            cb[((long long)c * 9 + q) * HW2 + hw] = v;
        }
    }
}

// ---------------- generic strided im2col (5x5 s2 p2 and 3x3 s2 p1) ----------------
__global__ void im2col_g(const float* __restrict__ src, long long srcB,
                         float* __restrict__ cols,
                         int C, int H, int W, int KH, int KW,
                         int stride, int pad, int OH, int OW)
{
    int ohw = blockIdx.x * 256 + threadIdx.x;
    int OHW = OH * OW;
    if (ohw >= OHW) return;
    int row = blockIdx.y;
    int b = blockIdx.z;
    int kk = row % (KH * KW);
    int c = row / (KH * KW);
    int kh = kk / KW, kw = kk % KW;
    int oh = ohw / OW, ow = ohw % OW;
    int ih = oh * stride - pad + kh;
    int iw = ow * stride - pad + kw;
    float v = 0.f;
    if (ih >= 0 && ih < H && iw >= 0 && iw < W)
        v = src[(long long)b * srcB + ((long long)c * H + ih) * W + iw];
    cols[((long long)b * C * KH * KW + row) * OHW + ohw] = v;
}

// ---------------- direct 3x3 s1 p1 conv (kept only for tiny s3: 64->1) ----------------
__global__ void conv3x3_direct(const float* __restrict__ in, long long inB,
                               const float* __restrict__ w, float* __restrict__ out,
                               long long outB, int C, int relu)
{
    int hw = blockIdx.x * 256 + threadIdx.x;
    if (hw >= HW2) return;
    int o = blockIdx.y, b = blockIdx.z;
    int h = hw / WW, x = hw % WW;
    const float* ib = in + (long long)b * inB;
    const float* wo = w + (long long)o * C * 9;
    float acc = 0.f;
    for (int c = 0; c < C; c++) {
        const float* ic = ib + (long long)c * HW2;
        const float* wc = wo + c * 9;
#pragma unroll
        for (int kh = 0; kh < 3; kh++) {
            int ih = h + kh - 1;
            if (ih < 0 || ih >= HH) continue;
#pragma unroll
            for (int kw = 0; kw < 3; kw++) {
                int iw = x + kw - 1;
                if (iw < 0 || iw >= WW) continue;
                acc += ic[ih * WW + iw] * wc[kh * 3 + kw];
            }
        }
    }
    if (relu) acc = fmaxf(acc, 0.f);
    out[(long long)b * outB + (long long)o * HW2 + hw] = acc;
}

// ---------------- elementwise kernels ----------------
__global__ void concat_k(const float* __restrict__ a, const float* __restrict__ b_,
                         float* __restrict__ o, long long imgStride)
{
    int idx = blockIdx.x * 256 + threadIdx.x;
    if (idx >= 2 * 512 * HW2) return;
    int bb = idx / (512 * HW2);
    int c = (idx / HW2) % 512;
    int hw = idx % HW2;
    float v = (c < 256) ? a[bb * imgStride + (long long)c * HW2 + hw]
                        : b_[bb * imgStride + (long long)(c - 256) * HW2 + hw];
    o[idx] = v;
}

__global__ void corr_k(const float* __restrict__ Ra, const float* __restrict__ Tb,
                       float* __restrict__ f177)
{
    int idx = blockIdx.x * 256 + threadIdx.x;
    if (idx >= 2 * 49 * HW2) return;
    int b = idx / (49 * HW2);
    int q = (idx / HW2) % 49;
    int hw = idx % HW2;
    int h = hw / WW, w = hw % WW;
    int dy = 2 * ((q / 7) - 3), dx = 2 * ((q % 7) - 3);
    int hh = h + dy, ww = w + dx;
    float s = 0.f;
    if (hh >= 0 && hh < HH && ww >= 0 && ww < WW) {
        const float* a = Ra + (long long)b * (2 * 64 * HW2) + hw;
        const float* bp = Tb + (long long)b * (2 * 64 * HW2) + hh * WW + ww;
        for (int c = 0; c < 64; c++) s += a[c * HW2] * bp[c * HW2];
    }
    f177[((long long)b * 177 + q) * HW2 + hw] = s * (1.f / 64.f);
}

__global__ void pack_k(const float* __restrict__ eA, const float* __restrict__ eB,
                       float* __restrict__ f177)
{
    int idx = blockIdx.x * 256 + threadIdx.x;
    if (idx >= 2 * 64 * HW2) return;
    int b = idx / (64 * HW2);
    int c = (idx / HW2) % 64;
    int hw = idx % HW2;
    f177[((long long)b * 177 + 49 + c) * HW2 + hw] = eA[idx];
    f177[((long long)b * 177 + 113 + c) * HW2 + hw] = eB[idx];
}

__global__ void mean36_k(const float* __restrict__ in, float* __restrict__ fw, int total)
{
    int i = blockIdx.x * 256 + threadIdx.x;
    if (i >= total) return;
    float s = 0.f;
#pragma unroll
    for (int j = 0; j < 36; j++) s += in[i * 36 + j];
    fw[i] = s * (1.f / 36.f);
}

__global__ void mkw_k(const float* __restrict__ fw, const float* __restrict__ Wt,
                      const float* __restrict__ Bi, float* __restrict__ adw,
                      int M, int Kc, int total)
{
    int idx = blockIdx.x * 256 + threadIdx.x;
    if (idx >= total) return;
    int b = idx / (M * Kc);
    int r = idx - b * M * Kc;
    int o = r / Kc;
    adw[idx] = fw[b * M + o] * Wt[r] + Bi[r];
}

__global__ void final_k(const float* __restrict__ d0, const float* __restrict__ d1,
                        const float* __restrict__ s0p, const float* __restrict__ s1p,
                        float* __restrict__ out, int total)
{
    int idx = blockIdx.x * 256 + threadIdx.x;
    if (idx >= total) return;
    int b = idx / (256 * HW2);
    int hw = idx % HW2;
    float s0 = s0p[b * HW2 + hw];
    float s1 = s1p[b * HW2 + hw];
    const float eps = 1e-8f;
    float wx = (s0 * s1) / (fmaxf(fabsf(s0), eps) * fmaxf(fabsf(s1), eps));
    float wy = (s1 * s1) / (fmaxf(fabsf(s1), eps) * fmaxf(fabsf(s1), eps));
    float mx = fmaxf(wx, wy);
    float e0 = expf(wx - mx), e1 = expf(wy - mx);
    float inv = 1.f / (e0 + e1);
    out[idx] = d0[idx] * (e0 * inv) + d1[idx] * (e1 * inv);
}

// ---------------- host orchestration ----------------
extern "C" void kernel_launch(void* const* d_in, const int* in_sizes, int n_in,
                              void* d_out, int out_size)
{
    (void)in_sizes; (void)n_in; (void)out_size;
    const float* R0     = (const float*)d_in[0];
    const float* T0     = (const float*)d_in[1];
    const float* inp    = (const float*)d_in[2];
    const float* enc0_w = (const float*)d_in[3];
    const float* enc0_b = (const float*)d_in[4];
    const float* enc1_w = (const float*)d_in[5];
    const float* enc1_b = (const float*)d_in[6];
    const float* offw[4] = {(const float*)d_in[7], (const float*)d_in[8],
                            (const float*)d_in[9], (const float*)d_in[10]};
    const float* defw[3] = {(const float*)d_in[11], (const float*)d_in[12],
                            (const float*)d_in[13]};
    const float* w0a = (const float*)d_in[14];
    const float* w0b = (const float*)d_in[15];
    const float* w0c = (const float*)d_in[16];
    const float* w1a = (const float*)d_in[17];
    const float* w1b = (const float*)d_in[18];
    const float* w1c = (const float*)d_in[19];
    const float* wx_w  = (const float*)d_in[20];
    const float* wx_b  = (const float*)d_in[21];
    const float* wxf_w = (const float*)d_in[22];
    const float* wxf_b = (const float*)d_in[23];
    const float* s1w = (const float*)d_in[24];
    const float* s2w = (const float*)d_in[25];
    const float* s3w = (const float*)d_in[26];
    float* out = (float*)d_out;

    float *xenc, *yenc, *f512a, *f512b, *cols, *off, *cpart, *f177, *f177b;
    float *wb1, *wb2, *wb3, *fw, *adw, *def0, *def1, *s1o, *s2o, *swa, *swb;
    cudaGetSymbolAddress((void**)&xenc,  g_xenc);
    cudaGetSymbolAddress((void**)&yenc,  g_yenc);
    cudaGetSymbolAddress((void**)&f512a, g_f512a);
    cudaGetSymbolAddress((void**)&f512b, g_f512b);
    cudaGetSymbolAddress((void**)&cols,  g_cols);
    cudaGetSymbolAddress((void**)&off,   g_offb);
    cudaGetSymbolAddress((void**)&cpart, g_cpart);
    cudaGetSymbolAddress((void**)&f177,  g_f177);
    cudaGetSymbolAddress((void**)&f177b, g_f177b);
    cudaGetSymbolAddress((void**)&wb1,   g_wb1);
    cudaGetSymbolAddress((void**)&wb2,   g_wb2);
    cudaGetSymbolAddress((void**)&wb3,   g_wb3);
    cudaGetSymbolAddress((void**)&fw,    g_fwb);
    cudaGetSymbolAddress((void**)&adw,   g_adw);
    cudaGetSymbolAddress((void**)&def0,  g_def0);
    cudaGetSymbolAddress((void**)&def1,  g_def1);
    cudaGetSymbolAddress((void**)&s1o,   g_s1o);
    cudaGetSymbolAddress((void**)&s2o,   g_s2o);
    cudaGetSymbolAddress((void**)&swa,   g_swa);
    cudaGetSymbolAddress((void**)&swb,   g_swb);

    const long long imgStride = 2LL * 256 * HW2;

    auto GEMM = [&](const float* A, const float* Bm, float* C, int M, int N, int K,
                    long long sA, long long sB, long long sC,
                    const float* bias, int relu) {
        dim3 g((N + 127) / 128, (M + 127) / 128, 2);
        gemm128<<<g, 256>>>(A, Bm, C, M, N, K, sA, sB, sC, bias, relu);
    };
    auto DIM2COL = [&](const float* src, long long sB, const float* offp, int C) {
        dim3 g((HW2 + 255) / 256, 18, (C + 63) / 64);
        deform_im2col_k<<<g, 256>>>(src, sB, offp, cols, C);
    };
    auto IM2COL = [&](const float* src, long long sB, int C, int H, int W,
                      int KH, int KW, int st, int pad, int OH, int OW) {
        dim3 g((OH * OW + 255) / 256, C * KH * KW, 2);
        im2col_g<<<g, 256>>>(src, sB, cols, C, H, W, KH, KW, st, pad, OH, OW);
    };
    auto CONV18 = [&](const float* in, long long inB, const float* w, float* o) {
        conv18_k<<<dim3(9, 8, 2), 256>>>(in, inB, w, cpart, 512);
        reduce18_k<<<(2 * 18 * HW2 + 255) / 256, 256>>>(cpart, o);
    };
    auto WBRANCH = [&](const float* feat, const float* wa, const float* wb,
                       const float* wc, int Mc) {
        IM2COL(feat, 177LL * HW2, 177, 48, 48, 5, 5, 2, 2, 24, 24);
        GEMM(wa, cols, wb1, 64, 576, 4425, 0, 4425LL * 576, 64LL * 576, nullptr, 1);
        IM2COL(wb1, 64LL * 576, 64, 24, 24, 5, 5, 2, 2, 12, 12);
        GEMM(wb, cols, wb2, 64, 144, 1600, 0, 1600LL * 144, 64LL * 144, nullptr, 1);
        IM2COL(wb2, 64LL * 144, 64, 12, 12, 3, 3, 2, 1, 6, 6);
        GEMM(wc, cols, wb3, Mc, 36, 576, 0, 576LL * 36, (long long)Mc * 36, nullptr, 0);
        int tot = 2 * Mc;
        mean36_k<<<(tot + 255) / 256, 256>>>(wb3, fw, tot);
    };

    // ---- encoders (1x1 conv == GEMM on NCHW directly) ----
    GEMM(enc0_w, inp,             xenc, 64, HW2, 256, 0, imgStride, 64LL * HW2, enc0_b, 0);
    GEMM(enc1_w, inp + 256 * HW2, yenc, 64, HW2, 256, 0, imgStride, 64LL * HW2, enc1_b, 0);

    auto BRANCH = [&](int br, float* gdef, float* gsw) {
        const float* imgA = (br == 0) ? inp : inp + 256 * HW2;
        const float* imgB = inp + 256 * HW2;   // y for both branches

        // ---- stsn_offset ----
        {
            int tot = 2 * 512 * HW2;
            concat_k<<<(tot + 255) / 256, 256>>>(imgA, imgB, f512a, imgStride);
        }
        float* cur = f512a; float* oth = f512b;
        for (int i = 0; i < 3; i++) {
            CONV18(cur, 512LL * HW2, offw[i], off);
            DIM2COL(cur, 512LL * HW2, off, 512);
            GEMM(defw[i], cols, oth, 512, HW2, 4608, 0, 4608LL * HW2, 512LL * HW2, nullptr, 0);
            float* t = cur; cur = oth; oth = t;
        }
        CONV18(cur, 512LL * HW2, offw[3], off);  // final offsets -> g_offb

        // ---- astsn_weight ----
        const float* Ra = R0 + (br == 0 ? 0 : 64 * HW2);   // R_pre / R_cur
        const float* Tb = T0 + 64 * HW2;                    // T_cur
        const float* eA = (br == 0) ? xenc : yenc;
        const float* eB = yenc;
        {
            int tot = 2 * 49 * HW2;
            corr_k<<<(tot + 255) / 256, 256>>>(Ra, Tb, f177);
        }
        {
            int tot = 2 * 64 * HW2;
            pack_k<<<(tot + 255) / 256, 256>>>(eA, eB, f177);
        }
        WBRANCH(f177, w0a, w0b, w0c, 177);
        {
            int tot = 2 * 177 * 1593;
            mkw_k<<<(tot + 255) / 256, 256>>>(fw, wx_w, wx_b, adw, 177, 1593, tot);
        }
        DIM2COL(f177, 177LL * HW2, nullptr, 177);
        GEMM(adw, cols, f177b, 177, HW2, 1593, 177LL * 1593, 1593LL * HW2, 177LL * HW2,
             nullptr, 1);
        WBRANCH(f177b, w1a, w1b, w1c, 256);
        {
            int tot = 2 * 256 * 2304;
            mkw_k<<<(tot + 255) / 256, 256>>>(fw, wxf_w, wxf_b, adw, 256, 2304, tot);
        }

        // ---- adaptive deform conv ----
        DIM2COL(imgA, imgStride, off, 256);
        GEMM(adw, cols, gdef, 256, HW2, 2304, 256LL * 2304, 2304LL * HW2, 256LL * HW2,
             nullptr, 0);

        // ---- s_net ----
        DIM2COL(gdef, 256LL * HW2, nullptr, 256);
        GEMM(s1w, cols, s1o, 128, HW2, 2304, 0, 2304LL * HW2, 128LL * HW2, nullptr, 1);
        DIM2COL(s1o, 128LL * HW2, nullptr, 128);
        GEMM(s2w, cols, s2o, 64, HW2, 1152, 0, 1152LL * HW2, 64LL * HW2, nullptr, 1);
        conv3x3_direct<<<dim3(9, 1, 2), 256>>>(s2o, 64LL * HW2, s3w, gsw,
                                               (long long)HW2, 64, 1);
    };

    BRANCH(0, def0, swa);
    BRANCH(1, def1, swb);

    {
        int tot = 2 * 256 * HW2;
        final_k<<<(tot + 255) / 256, 256>>>(def0, def1, swa, swb, out, tot);
    }
}

// round 3
// speedup vs baseline: 1.7036x; 1.7036x over previous
#include <cuda_runtime.h>
#include <math.h>

#define HW2 2304
#define HH 48
#define WW 48

// ---------------- device scratch (no allocations allowed) ----------------
__device__ float g_xenc  [2*64 *HW2];
__device__ float g_yenc  [2*64 *HW2];
__device__ float g_f512a [2*512*HW2];
__device__ float g_f512b [2*512*HW2];
__device__ float g_cols  [2*4608*HW2];   // reused for every im2col
__device__ float g_offb  [2*18 *HW2];
__device__ float g_cpart [8*2*18*HW2];   // conv18 channel-split partials
__device__ float g_f177  [2*177*HW2];
__device__ float g_f177b [2*177*HW2];
__device__ float g_wb1   [2*64*576];
__device__ float g_wb2   [2*64*144];
__device__ float g_wb3   [2*256*36];
__device__ float g_fwb   [2*256];
__device__ float g_adw   [2*256*HW2];
__device__ float g_def0  [2*256*HW2];
__device__ float g_def1  [2*256*HW2];
__device__ float g_s1o   [2*128*HW2];
__device__ float g_s2o   [2*64*HW2];
__device__ float g_swa   [2*HW2];
__device__ float g_swb   [2*HW2];

// ---------------- aligned fast GEMM: 64 x TN tile, KT=16, double buffered ----------------
// Requires M%64==0, N%TN==0, K%16==0. 256 threads, each computes 4 x RN.
template<int RN>   // TN = 16*RN  (RN=4 -> 64, RN=8 -> 128)
__global__ __launch_bounds__(256)
void gemm_al(const float* __restrict__ A, const float* __restrict__ B,
             float* __restrict__ C, int M, int N, int K,
             long long sA, long long sB, long long sC,
             const float* __restrict__ bias, int relu)
{
    constexpr int TN = 16 * RN;
    A += (long long)blockIdx.z * sA;
    B += (long long)blockIdx.z * sB;
    C += (long long)blockIdx.z * sC;

    __shared__ float As[2][16][68];    // padded (2-way max on store, aligned frag reads)
    __shared__ float Bs[2][16][TN];

    const int tid = threadIdx.x;
    const int tx = tid & 15, ty = tid >> 4;
    const int m0 = blockIdx.y * 64, n0 = blockIdx.x * TN;

    const int ar = tid >> 2;               // A row 0..63
    const int ak = (tid & 3) * 4;          // A k offset 0/4/8/12
    const int bk = tid >> 4;               // B k row 0..15
    const int bn = (tid & 15) * RN;        // B n offset

    const float* Ap = A + (long long)(m0 + ar) * K + ak;
    const float* Bp = B + (long long)bk * N + n0 + bn;

    float acc[4][RN];
#pragma unroll
    for (int i = 0; i < 4; i++)
#pragma unroll
        for (int j = 0; j < RN; j++) acc[i][j] = 0.f;

    // prologue
    {
        float4 av = *(const float4*)Ap;
        As[0][ak + 0][ar] = av.x; As[0][ak + 1][ar] = av.y;
        As[0][ak + 2][ar] = av.z; As[0][ak + 3][ar] = av.w;
#pragma unroll
        for (int h = 0; h < RN / 4; h++)
            *(float4*)&Bs[0][bk][bn + h * 4] = *(const float4*)(Bp + h * 4);
    }
    __syncthreads();

    int buf = 0;
    for (int k0 = 0; k0 < K; k0 += 16) {
        const bool has = (k0 + 16) < K;
        float4 la;
        float4 lb[RN / 4];
        if (has) {
            la = *(const float4*)(Ap + k0 + 16);
#pragma unroll
            for (int h = 0; h < RN / 4; h++)
                lb[h] = *(const float4*)(Bp + (long long)(k0 + 16) * N + h * 4);
        }

#pragma unroll
        for (int kk = 0; kk < 16; kk++) {
            float4 a4 = *(const float4*)&As[buf][kk][ty * 4];
            float a[4] = {a4.x, a4.y, a4.z, a4.w};
            float b[RN];
#pragma unroll
            for (int h = 0; h < RN / 4; h++) {
                float4 b4 = *(const float4*)&Bs[buf][kk][h * 64 + tx * 4];
                b[h * 4 + 0] = b4.x; b[h * 4 + 1] = b4.y;
                b[h * 4 + 2] = b4.z; b[h * 4 + 3] = b4.w;
            }
#pragma unroll
            for (int i = 0; i < 4; i++)
#pragma unroll
                for (int j = 0; j < RN; j++) acc[i][j] += a[i] * b[j];
        }

        if (has) {
            int nb = buf ^ 1;
            As[nb][ak + 0][ar] = la.x; As[nb][ak + 1][ar] = la.y;
            As[nb][ak + 2][ar] = la.z; As[nb][ak + 3][ar] = la.w;
#pragma unroll
            for (int h = 0; h < RN / 4; h++)
                *(float4*)&Bs[nb][bk][bn + h * 4] = lb[h];
        }
        __syncthreads();
        buf ^= 1;
    }

#pragma unroll
    for (int i = 0; i < 4; i++) {
        int m = m0 + ty * 4 + i;
        float bv = bias ? bias[m] : 0.f;
#pragma unroll
        for (int h = 0; h < RN / 4; h++) {
            float4 v;
            v.x = acc[i][h * 4 + 0] + bv;
            v.y = acc[i][h * 4 + 1] + bv;
            v.z = acc[i][h * 4 + 2] + bv;
            v.w = acc[i][h * 4 + 3] + bv;
            if (relu) {
                v.x = fmaxf(v.x, 0.f); v.y = fmaxf(v.y, 0.f);
                v.z = fmaxf(v.z, 0.f); v.w = fmaxf(v.w, 0.f);
            }
            *(float4*)&C[(long long)m * N + n0 + h * 64 + tx * 4] = v;
        }
    }
}

// ---------------- fallback 64x64 GEMM (any shape; known-good) ----------------
__global__ void gemm64(const float* __restrict__ A, const float* __restrict__ B,
                       float* __restrict__ C, int M, int N, int K,
                       long long sA, long long sB, long long sC,
                       const float* __restrict__ bias, int relu)
{
    A += (long long)blockIdx.z * sA;
    B += (long long)blockIdx.z * sB;
    C += (long long)blockIdx.z * sC;
    __shared__ float As[16][64];
    __shared__ float Bs[16][68];
    int tx = threadIdx.x, ty = threadIdx.y;
    int tid = ty * 16 + tx;
    int m0 = blockIdx.y * 64, n0 = blockIdx.x * 64;
    int mA = tid >> 2, kA = (tid & 3) * 4;
    int kB = tid >> 4, nB = (tid & 15) * 4;
    float acc[4][4];
#pragma unroll
    for (int i = 0; i < 4; i++)
#pragma unroll
        for (int j = 0; j < 4; j++) acc[i][j] = 0.f;

    for (int k0 = 0; k0 < K; k0 += 16) {
#pragma unroll
        for (int i = 0; i < 4; i++) {
            int k = k0 + kA + i;
            As[kA + i][mA] = (m0 + mA < M && k < K) ? A[(long long)(m0 + mA) * K + k] : 0.f;
        }
#pragma unroll
        for (int i = 0; i < 4; i++) {
            int n = n0 + nB + i;
            Bs[kB][nB + i] = (k0 + kB < K && n < N) ? B[(long long)(k0 + kB) * N + n] : 0.f;
        }
        __syncthreads();
#pragma unroll
        for (int kk = 0; kk < 16; kk++) {
            float a[4], b[4];
#pragma unroll
            for (int i = 0; i < 4; i++) a[i] = As[kk][ty * 4 + i];
#pragma unroll
            for (int j = 0; j < 4; j++) b[j] = Bs[kk][tx * 4 + j];
#pragma unroll
            for (int i = 0; i < 4; i++)
#pragma unroll
                for (int j = 0; j < 4; j++) acc[i][j] += a[i] * b[j];
        }
        __syncthreads();
    }
#pragma unroll
    for (int i = 0; i < 4; i++) {
        int m = m0 + ty * 4 + i;
        if (m >= M) continue;
        float bv = bias ? bias[m] : 0.f;
#pragma unroll
        for (int j = 0; j < 4; j++) {
            int n = n0 + tx * 4 + j;
            if (n >= N) continue;
            float v = acc[i][j] + bv;
            if (relu) v = fmaxf(v, 0.f);
            C[(long long)m * N + n] = v;
        }
    }
}

// ---------------- 512->18 offset-head 3x3 conv, channel-split partials ----------------
__global__ void conv18_k(const float* __restrict__ in, long long inB,
                         const float* __restrict__ w, float* __restrict__ part, int C)
{
    const int t = blockIdx.x, cc = blockIdx.y, b = blockIdx.z;
    const int tid = threadIdx.x;
    const int hw = t * 256 + tid;
    const int h = hw / WW, x = hw % WW;
    const int hf = (t * 256) / WW;

    __shared__ float sIn[4][9 * WW];
    __shared__ float sW[4][18 * 9];

    float acc[18];
#pragma unroll
    for (int o = 0; o < 18; o++) acc[o] = 0.f;

    const float* ib = in + (long long)b * inB + (long long)(cc * 64) * HW2;
    const int lr = h - (hf - 1);

    for (int cs = 0; cs < 64; cs += 4) {
        for (int i = tid; i < 4 * 9 * WW; i += 256) {
            int c = i / (9 * WW), r = i % (9 * WW);
            int row = hf - 1 + r / WW, col = r % WW;
            float v = 0.f;
            if (row >= 0 && row < HH) v = ib[(long long)(cs + c) * HW2 + row * WW + col];
            sIn[c][r] = v;
        }
        for (int i = tid; i < 4 * 162; i += 256) {
            int c = i / 162, r = i % 162;
            int o = r / 9, q = r % 9;
            sW[c][r] = w[((long long)o * C + (cc * 64 + cs + c)) * 9 + q];
        }
        __syncthreads();

#pragma unroll
        for (int c = 0; c < 4; c++) {
            float tap[9];
#pragma unroll
            for (int ki = 0; ki < 3; ki++)
#pragma unroll
                for (int kj = 0; kj < 3; kj++) {
                    int xx = x - 1 + kj;
                    float v = 0.f;
                    if (xx >= 0 && xx < WW) v = sIn[c][(lr - 1 + ki) * WW + xx];
                    tap[ki * 3 + kj] = v;
                }
#pragma unroll
            for (int o = 0; o < 18; o++) {
                float s = acc[o];
#pragma unroll
                for (int q = 0; q < 9; q++) s += sW[c][o * 9 + q] * tap[q];
                acc[o] = s;
            }
        }
        __syncthreads();
    }

    float* pp = part + ((long long)cc * 2 + b) * 18 * HW2;
#pragma unroll
    for (int o = 0; o < 18; o++) pp[(long long)o * HW2 + hw] = acc[o];
}

__global__ void reduce18_k(const float* __restrict__ part, float* __restrict__ out)
{
    int idx = blockIdx.x * 256 + threadIdx.x;
    if (idx >= 2 * 18 * HW2) return;
    int b = idx / (18 * HW2);
    int r = idx % (18 * HW2);
    float s = 0.f;
#pragma unroll
    for (int c = 0; c < 8; c++) s += part[((long long)c * 2 + b) * 18 * HW2 + r];
    out[(long long)b * 18 * HW2 + r] = s;
}

// ---------------- deformable (or plain) 3x3 s1 p1 im2col over 48x48 ----------------
__global__ void deform_im2col_k(const float* __restrict__ src, long long srcB,
                                const float* __restrict__ off,
                                float* __restrict__ cols, int C)
{
    int hw = blockIdx.x * 256 + threadIdx.x;
    if (hw >= HW2) return;
    int bq = blockIdx.y;
    int b = bq / 9, q = bq % 9;
    int ki = q / 3, kj = q % 3;
    int h = hw / WW, w = hw % WW;
    const float* sb = src + (long long)b * srcB;
    float* cb = cols + (long long)b * C * 9 * HW2;
    int c0 = blockIdx.z * 64;
    int c1 = c0 + 64; if (c1 > C) c1 = C;

    if (off == nullptr) {
        int y = h - 1 + ki, x = w - 1 + kj;
        bool vin = (y >= 0 && y < HH && x >= 0 && x < WW);
        int idx = vin ? (y * WW + x) : 0;
        for (int c = c0; c < c1; c++) {
            float v = vin ? sb[(long long)c * HW2 + idx] : 0.f;
            cb[((long long)c * 9 + q) * HW2 + hw] = v;
        }
    } else {
        float py = (float)(h - 1 + ki) + off[((long long)b * 18 + 2 * q) * HW2 + hw];
        float px = (float)(w - 1 + kj) + off[((long long)b * 18 + 2 * q + 1) * HW2 + hw];
        float fy = floorf(py), fx = floorf(px);
        float ay = py - fy, ax = px - fx;
        int y0 = (int)fy, x0 = (int)fx;
        int y1 = y0 + 1, x1 = x0 + 1;
        bool by0 = (y0 >= 0 && y0 < HH), by1 = (y1 >= 0 && y1 < HH);
        bool bx0 = (x0 >= 0 && x0 < WW), bx1 = (x1 >= 0 && x1 < WW);
        int yc0 = min(max(y0, 0), HH - 1), yc1 = min(max(y1, 0), HH - 1);
        int xc0 = min(max(x0, 0), WW - 1), xc1 = min(max(x1, 0), WW - 1);
        float w00 = (by0 && bx0) ? (1.f - ay) * (1.f - ax) : 0.f;
        float w01 = (by0 && bx1) ? (1.f - ay) * ax : 0.f;
        float w10 = (by1 && bx0) ? ay * (1.f - ax) : 0.f;
        float w11 = (by1 && bx1) ? ay * ax : 0.f;
        int i00 = yc0 * WW + xc0, i01 = yc0 * WW + xc1;
        int i10 = yc1 * WW + xc0, i11 = yc1 * WW + xc1;
        for (int c = c0; c < c1; c++) {
            const float* s = sb + (long long)c * HW2;
            float v = w00 * s[i00] + w01 * s[i01] + w10 * s[i10] + w11 * s[i11];
            cb[((long long)c * 9 + q) * HW2 + hw] = v;
        }
    }
}

// ---------------- generic strided im2col (5x5 s2 p2 and 3x3 s2 p1) ----------------
__global__ void im2col_g(const float* __restrict__ src, long long srcB,
                         float* __restrict__ cols,
                         int C, int H, int W, int KH, int KW,
                         int stride, int pad, int OH, int OW)
{
    int ohw = blockIdx.x * 256 + threadIdx.x;
    int OHW = OH * OW;
    if (ohw >= OHW) return;
    int row = blockIdx.y;
    int b = blockIdx.z;
    int kk = row % (KH * KW);
    int c = row / (KH * KW);
    int kh = kk / KW, kw = kk % KW;
    int oh = ohw / OW, ow = ohw % OW;
    int ih = oh * stride - pad + kh;
    int iw = ow * stride - pad + kw;
    float v = 0.f;
    if (ih >= 0 && ih < H && iw >= 0 && iw < W)
        v = src[(long long)b * srcB + ((long long)c * H + ih) * W + iw];
    cols[((long long)b * C * KH * KW + row) * OHW + ohw] = v;
}

// ---------------- direct 3x3 s1 p1 conv (tiny s3: 64->1) ----------------
__global__ void conv3x3_direct(const float* __restrict__ in, long long inB,
                               const float* __restrict__ w, float* __restrict__ out,
                               long long outB, int C, int relu)
{
    int hw = blockIdx.x * 256 + threadIdx.x;
    if (hw >= HW2) return;
    int o = blockIdx.y, b = blockIdx.z;
    int h = hw / WW, x = hw % WW;
    const float* ib = in + (long long)b * inB;
    const float* wo = w + (long long)o * C * 9;
    float acc = 0.f;
    for (int c = 0; c < C; c++) {
        const float* ic = ib + (long long)c * HW2;
        const float* wc = wo + c * 9;
#pragma unroll
        for (int kh = 0; kh < 3; kh++) {
            int ih = h + kh - 1;
            if (ih < 0 || ih >= HH) continue;
#pragma unroll
            for (int kw = 0; kw < 3; kw++) {
                int iw = x + kw - 1;
                if (iw < 0 || iw >= WW) continue;
                acc += ic[ih * WW + iw] * wc[kh * 3 + kw];
            }
        }
    }
    if (relu) acc = fmaxf(acc, 0.f);
    out[(long long)b * outB + (long long)o * HW2 + hw] = acc;
}

// ---------------- elementwise kernels ----------------
__global__ void concat_k(const float* __restrict__ a, const float* __restrict__ b_,
                         float* __restrict__ o, long long imgStride)
{
    int idx = blockIdx.x * 256 + threadIdx.x;
    if (idx >= 2 * 512 * HW2) return;
    int bb = idx / (512 * HW2);
    int c = (idx / HW2) % 512;
    int hw = idx % HW2;
    float v = (c < 256) ? a[bb * imgStride + (long long)c * HW2 + hw]
                        : b_[bb * imgStride + (long long)(c - 256) * HW2 + hw];
    o[idx] = v;
}

__global__ void corr_k(const float* __restrict__ Ra, const float* __restrict__ Tb,
                       float* __restrict__ f177)
{
    int idx = blockIdx.x * 256 + threadIdx.x;
    if (idx >= 2 * 49 * HW2) return;
    int b = idx / (49 * HW2);
    int q = (idx / HW2) % 49;
    int hw = idx % HW2;
    int h = hw / WW, w = hw % WW;
    int dy = 2 * ((q / 7) - 3), dx = 2 * ((q % 7) - 3);
    int hh = h + dy, ww = w + dx;
    float s = 0.f;
    if (hh >= 0 && hh < HH && ww >= 0 && ww < WW) {
        const float* a = Ra + (long long)b * (2 * 64 * HW2) + hw;
        const float* bp = Tb + (long long)b * (2 * 64 * HW2) + hh * WW + ww;
        for (int c = 0; c < 64; c++) s += a[c * HW2] * bp[c * HW2];
    }
    f177[((long long)b * 177 + q) * HW2 + hw] = s * (1.f / 64.f);
}

__global__ void pack_k(const float* __restrict__ eA, const float* __restrict__ eB,
                       float* __restrict__ f177)
{
    int idx = blockIdx.x * 256 + threadIdx.x;
    if (idx >= 2 * 64 * HW2) return;
    int b = idx / (64 * HW2);
    int c = (idx / HW2) % 64;
    int hw = idx % HW2;
    f177[((long long)b * 177 + 49 + c) * HW2 + hw] = eA[idx];
    f177[((long long)b * 177 + 113 + c) * HW2 + hw] = eB[idx];
}

__global__ void mean36_k(const float* __restrict__ in, float* __restrict__ fw, int total)
{
    int i = blockIdx.x * 256 + threadIdx.x;
    if (i >= total) return;
    float s = 0.f;
#pragma unroll
    for (int j = 0; j < 36; j++) s += in[i * 36 + j];
    fw[i] = s * (1.f / 36.f);
}

__global__ void mkw_k(const float* __restrict__ fw, const float* __restrict__ Wt,
                      const float* __restrict__ Bi, float* __restrict__ adw,
                      int M, int Kc, int total)
{
    int idx = blockIdx.x * 256 + threadIdx.x;
    if (idx >= total) return;
    int b = idx / (M * Kc);
    int r = idx - b * M * Kc;
    int o = r / Kc;
    adw[idx] = fw[b * M + o] * Wt[r] + Bi[r];
}

__global__ void final_k(const float* __restrict__ d0, const float* __restrict__ d1,
                        const float* __restrict__ s0p, const float* __restrict__ s1p,
                        float* __restrict__ out, int total)
{
    int idx = blockIdx.x * 256 + threadIdx.x;
    if (idx >= total) return;
    int b = idx / (256 * HW2);
    int hw = idx % HW2;
    float s0 = s0p[b * HW2 + hw];
    float s1 = s1p[b * HW2 + hw];
    const float eps = 1e-8f;
    float wx = (s0 * s1) / (fmaxf(fabsf(s0), eps) * fmaxf(fabsf(s1), eps));
    float wy = (s1 * s1) / (fmaxf(fabsf(s1), eps) * fmaxf(fabsf(s1), eps));
    float mx = fmaxf(wx, wy);
    float e0 = expf(wx - mx), e1 = expf(wy - mx);
    float inv = 1.f / (e0 + e1);
    out[idx] = d0[idx] * (e0 * inv) + d1[idx] * (e1 * inv);
}

// ---------------- host orchestration ----------------
extern "C" void kernel_launch(void* const* d_in, const int* in_sizes, int n_in,
                              void* d_out, int out_size)
{
    (void)in_sizes; (void)n_in; (void)out_size;
    const float* R0     = (const float*)d_in[0];
    const float* T0     = (const float*)d_in[1];
    const float* inp    = (const float*)d_in[2];
    const float* enc0_w = (const float*)d_in[3];
    const float* enc0_b = (const float*)d_in[4];
    const float* enc1_w = (const float*)d_in[5];
    const float* enc1_b = (const float*)d_in[6];
    const float* offw[4] = {(const float*)d_in[7], (const float*)d_in[8],
                            (const float*)d_in[9], (const float*)d_in[10]};
    const float* defw[3] = {(const float*)d_in[11], (const float*)d_in[12],
                            (const float*)d_in[13]};
    const float* w0a = (const float*)d_in[14];
    const float* w0b = (const float*)d_in[15];
    const float* w0c = (const float*)d_in[16];
    const float* w1a = (const float*)d_in[17];
    const float* w1b = (const float*)d_in[18];
    const float* w1c = (const float*)d_in[19];
    const float* wx_w  = (const float*)d_in[20];
    const float* wx_b  = (const float*)d_in[21];
    const float* wxf_w = (const float*)d_in[22];
    const float* wxf_b = (const float*)d_in[23];
    const float* s1w = (const float*)d_in[24];
    const float* s2w = (const float*)d_in[25];
    const float* s3w = (const float*)d_in[26];
    float* out = (float*)d_out;

    float *xenc, *yenc, *f512a, *f512b, *cols, *off, *cpart, *f177, *f177b;
    float *wb1, *wb2, *wb3, *fw, *adw, *def0, *def1, *s1o, *s2o, *swa, *swb;
    cudaGetSymbolAddress((void**)&xenc,  g_xenc);
    cudaGetSymbolAddress((void**)&yenc,  g_yenc);
    cudaGetSymbolAddress((void**)&f512a, g_f512a);
    cudaGetSymbolAddress((void**)&f512b, g_f512b);
    cudaGetSymbolAddress((void**)&cols,  g_cols);
    cudaGetSymbolAddress((void**)&off,   g_offb);
    cudaGetSymbolAddress((void**)&cpart, g_cpart);
    cudaGetSymbolAddress((void**)&f177,  g_f177);
    cudaGetSymbolAddress((void**)&f177b, g_f177b);
    cudaGetSymbolAddress((void**)&wb1,   g_wb1);
    cudaGetSymbolAddress((void**)&wb2,   g_wb2);
    cudaGetSymbolAddress((void**)&wb3,   g_wb3);
    cudaGetSymbolAddress((void**)&fw,    g_fwb);
    cudaGetSymbolAddress((void**)&adw,   g_adw);
    cudaGetSymbolAddress((void**)&def0,  g_def0);
    cudaGetSymbolAddress((void**)&def1,  g_def1);
    cudaGetSymbolAddress((void**)&s1o,   g_s1o);
    cudaGetSymbolAddress((void**)&s2o,   g_s2o);
    cudaGetSymbolAddress((void**)&swa,   g_swa);
    cudaGetSymbolAddress((void**)&swb,   g_swb);

    const long long imgStride = 2LL * 256 * HW2;

    // fast aligned GEMM (M%64==0, K%16==0, N%TN==0); wide=1 -> TN=128
    auto GEMMA = [&](const float* A, const float* Bm, float* C, int M, int N, int K,
                     long long sA, long long sB, long long sC,
                     const float* bias, int relu, int wide) {
        if (wide)
            gemm_al<8><<<dim3(N / 128, M / 64, 2), 256>>>(A, Bm, C, M, N, K, sA, sB, sC, bias, relu);
        else
            gemm_al<4><<<dim3(N / 64, M / 64, 2), 256>>>(A, Bm, C, M, N, K, sA, sB, sC, bias, relu);
    };
    // fallback for odd shapes
    auto GEMMF = [&](const float* A, const float* Bm, float* C, int M, int N, int K,
                     long long sA, long long sB, long long sC,
                     const float* bias, int relu) {
        dim3 g((N + 63) / 64, (M + 63) / 64, 2);
        gemm64<<<g, dim3(16, 16)>>>(A, Bm, C, M, N, K, sA, sB, sC, bias, relu);
    };
    auto DIM2COL = [&](const float* src, long long sB, const float* offp, int C) {
        dim3 g((HW2 + 255) / 256, 18, (C + 63) / 64);
        deform_im2col_k<<<g, 256>>>(src, sB, offp, cols, C);
    };
    auto IM2COL = [&](const float* src, long long sB, int C, int H, int W,
                      int KH, int KW, int st, int pad, int OH, int OW) {
        dim3 g((OH * OW + 255) / 256, C * KH * KW, 2);
        im2col_g<<<g, 256>>>(src, sB, cols, C, H, W, KH, KW, st, pad, OH, OW);
    };
    auto CONV18 = [&](const float* in, long long inB, const float* w, float* o) {
        conv18_k<<<dim3(9, 8, 2), 256>>>(in, inB, w, cpart, 512);
        reduce18_k<<<(2 * 18 * HW2 + 255) / 256, 256>>>(cpart, o);
    };
    auto WBRANCH = [&](const float* feat, const float* wa, const float* wb,
                       const float* wc, int Mc) {
        IM2COL(feat, 177LL * HW2, 177, 48, 48, 5, 5, 2, 2, 24, 24);
        GEMMF(wa, cols, wb1, 64, 576, 4425, 0, 4425LL * 576, 64LL * 576, nullptr, 1);
        IM2COL(wb1, 64LL * 576, 64, 24, 24, 5, 5, 2, 2, 12, 12);
        GEMMF(wb, cols, wb2, 64, 144, 1600, 0, 1600LL * 144, 64LL * 144, nullptr, 1);
        IM2COL(wb2, 64LL * 144, 64, 12, 12, 3, 3, 2, 1, 6, 6);
        GEMMF(wc, cols, wb3, Mc, 36, 576, 0, 576LL * 36, (long long)Mc * 36, nullptr, 0);
        int tot = 2 * Mc;
        mean36_k<<<(tot + 255) / 256, 256>>>(wb3, fw, tot);
    };

    // ---- encoders (1x1 conv == GEMM on NCHW directly) ----
    GEMMA(enc0_w, inp,             xenc, 64, HW2, 256, 0, imgStride, 64LL * HW2, enc0_b, 0, 0);
    GEMMA(enc1_w, inp + 256 * HW2, yenc, 64, HW2, 256, 0, imgStride, 64LL * HW2, enc1_b, 0, 0);

    auto BRANCH = [&](int br, float* gdef, float* gsw) {
        const float* imgA = (br == 0) ? inp : inp + 256 * HW2;
        const float* imgB = inp + 256 * HW2;   // y for both branches

        // ---- stsn_offset ----
        {
            int tot = 2 * 512 * HW2;
            concat_k<<<(tot + 255) / 256, 256>>>(imgA, imgB, f512a, imgStride);
        }
        float* cur = f512a; float* oth = f512b;
        for (int i = 0; i < 3; i++) {
            CONV18(cur, 512LL * HW2, offw[i], off);
            DIM2COL(cur, 512LL * HW2, off, 512);
            GEMMA(defw[i], cols, oth, 512, HW2, 4608, 0, 4608LL * HW2, 512LL * HW2,
                  nullptr, 0, 1);
            float* t = cur; cur = oth; oth = t;
        }
        CONV18(cur, 512LL * HW2, offw[3], off);  // final offsets -> g_offb

        // ---- astsn_weight ----
        const float* Ra = R0 + (br == 0 ? 0 : 64 * HW2);   // R_pre / R_cur
        const float* Tb = T0 + 64 * HW2;                    // T_cur
        const float* eA = (br == 0) ? xenc : yenc;
        const float* eB = yenc;
        {
            int tot = 2 * 49 * HW2;
            corr_k<<<(tot + 255) / 256, 256>>>(Ra, Tb, f177);
        }
        {
            int tot = 2 * 64 * HW2;
            pack_k<<<(tot + 255) / 256, 256>>>(eA, eB, f177);
        }
        WBRANCH(f177, w0a, w0b, w0c, 177);
        {
            int tot = 2 * 177 * 1593;
            mkw_k<<<(tot + 255) / 256, 256>>>(fw, wx_w, wx_b, adw, 177, 1593, tot);
        }
        DIM2COL(f177, 177LL * HW2, nullptr, 177);
        GEMMF(adw, cols, f177b, 177, HW2, 1593, 177LL * 1593, 1593LL * HW2, 177LL * HW2,
              nullptr, 1);
        WBRANCH(f177b, w1a, w1b, w1c, 256);
        {
            int tot = 2 * 256 * 2304;
            mkw_k<<<(tot + 255) / 256, 256>>>(fw, wxf_w, wxf_b, adw, 256, 2304, tot);
        }

        // ---- adaptive deform conv ----
        DIM2COL(imgA, imgStride, off, 256);
        GEMMA(adw, cols, gdef, 256, HW2, 2304, 256LL * 2304, 2304LL * HW2, 256LL * HW2,
              nullptr, 0, 0);

        // ---- s_net ----
        DIM2COL(gdef, 256LL * HW2, nullptr, 256);
        GEMMA(s1w, cols, s1o, 128, HW2, 2304, 0, 2304LL * HW2, 128LL * HW2, nullptr, 1, 0);
        DIM2COL(s1o, 128LL * HW2, nullptr, 128);
        GEMMA(s2w, cols, s2o, 64, HW2, 1152, 0, 1152LL * HW2, 64LL * HW2, nullptr, 1, 0);
        conv3x3_direct<<<dim3(9, 1, 2), 256>>>(s2o, 64LL * HW2, s3w, gsw,
                                               (long long)HW2, 64, 1);
    };

    BRANCH(0, def0, swa);
    BRANCH(1, def1, swb);

    {
        int tot = 2 * 256 * HW2;
        final_k<<<(tot + 255) / 256, 256>>>(def0, def1, swa, swb, out, tot);
    }
}

// round 4
// speedup vs baseline: 1.9803x; 1.1624x over previous
#include <cuda_runtime.h>
#include <cuda_bf16.h>
#include <math.h>

#define HW2 2304
#define HH 48
#define WW 48

typedef unsigned int u32;

// ---------------- device scratch (no allocations allowed) ----------------
__device__ float g_xenc  [2*64 *HW2];
__device__ float g_yenc  [2*64 *HW2];
__device__ float g_f512a [2*512*HW2];
__device__ float g_f512b [2*512*HW2];
__device__ float g_cols  [2*4608*HW2];   // reused for every im2col
__device__ float g_offb  [2*18 *HW2];
__device__ float g_cpart [8*2*18*HW2];   // conv18 channel-split partials
__device__ float g_f177  [2*177*HW2];
__device__ float g_f177b [2*177*HW2];
__device__ float g_wb1   [2*64*576];
__device__ float g_wb2   [2*64*144];
__device__ float g_wb3   [2*256*36];
__device__ float g_fwb   [2*256];
__device__ float g_adw   [2*256*HW2];
__device__ float g_def0  [2*256*HW2];
__device__ float g_def1  [2*256*HW2];
__device__ float g_s1o   [2*128*HW2];
__device__ float g_s2o   [2*64*HW2];
__device__ float g_swa   [2*HW2];
__device__ float g_swb   [2*HW2];

// ---------------- bf16x3 split tensor-core GEMM ----------------
// C[M,N] = A[M,K]*B[K,N], fp32 in/out, 3-term bf16 split (hi*hi + hi*lo + lo*hi),
// fp32 MMA accumulators. Requires M%128==0, N%64==0, K%16==0.
// Tile 128x64, KT=16, 8 warps (4m x 2n), warp tile 32x32.

__device__ __forceinline__ u32 split_pack(float x, float y, u32& lo)
{
    __nv_bfloat16 xh = __float2bfloat16(x);
    __nv_bfloat16 yh = __float2bfloat16(y);
    __nv_bfloat16 xl = __float2bfloat16(x - __bfloat162float(xh));
    __nv_bfloat16 yl = __float2bfloat16(y - __bfloat162float(yh));
    lo = ((u32)__bfloat16_as_ushort(yl) << 16) | (u32)__bfloat16_as_ushort(xl);
    return ((u32)__bfloat16_as_ushort(yh) << 16) | (u32)__bfloat16_as_ushort(xh);
}

#define MMA16816(c, a, b0v, b1v) \
    asm volatile("mma.sync.aligned.m16n8k16.row.col.f32.bf16.bf16.f32 " \
        "{%0,%1,%2,%3},{%4,%5,%6,%7},{%8,%9},{%0,%1,%2,%3};" \
        : "+f"((c)[0]), "+f"((c)[1]), "+f"((c)[2]), "+f"((c)[3]) \
        : "r"((a)[0]), "r"((a)[1]), "r"((a)[2]), "r"((a)[3]), \
          "r"(b0v), "r"(b1v))

__global__ __launch_bounds__(256)
void gemm_bf3(const float* __restrict__ A, const float* __restrict__ B,
              float* __restrict__ C, int M, int N, int K,
              long long sA, long long sB, long long sC, int relu)
{
    A += (long long)blockIdx.z * sA;
    B += (long long)blockIdx.z * sB;
    C += (long long)blockIdx.z * sC;

    // packed bf16x2 along k; 8 used cols, pad to 12 -> conflict-free frag reads
    __shared__ u32 sAh[2][128][12];
    __shared__ u32 sAl[2][128][12];
    __shared__ u32 sBh[2][64][12];
    __shared__ u32 sBl[2][64][12];

    const int tid = threadIdx.x;
    const int lane = tid & 31, warp = tid >> 5;
    const int wm = warp >> 1, wn = warp & 1;
    const int m0 = blockIdx.y * 128, n0 = blockIdx.x * 64;

    // A staging: row = tid>>1 (0..127), half = tid&1 -> floats [half*8, half*8+8)
    const int arow = tid >> 1, ahalf = tid & 1;
    const float* Ap = A + (long long)(m0 + arow) * K + ahalf * 8;

    // B staging: 2 k-pairs per thread
    int bn[2], bkp[2];
#pragma unroll
    for (int p = 0; p < 2; p++) {
        int pi = tid + p * 256;
        bn[p] = pi & 63;
        bkp[p] = pi >> 6;          // 0..7
    }

    float acc[2][4][4];
#pragma unroll
    for (int mt = 0; mt < 2; mt++)
#pragma unroll
        for (int nt = 0; nt < 4; nt++)
#pragma unroll
            for (int i = 0; i < 4; i++) acc[mt][nt][i] = 0.f;

    float4 la0, la1;
    float lb[2][2];

    // prologue loads (k0 = 0)
    la0 = *(const float4*)(Ap);
    la1 = *(const float4*)(Ap + 4);
#pragma unroll
    for (int p = 0; p < 2; p++) {
        lb[p][0] = B[(long long)(2 * bkp[p]) * N + n0 + bn[p]];
        lb[p][1] = B[(long long)(2 * bkp[p] + 1) * N + n0 + bn[p]];
    }
    // convert + store buf 0
    {
        u32 lo, hi;
        hi = split_pack(la0.x, la0.y, lo); sAh[0][arow][ahalf*4+0] = hi; sAl[0][arow][ahalf*4+0] = lo;
        hi = split_pack(la0.z, la0.w, lo); sAh[0][arow][ahalf*4+1] = hi; sAl[0][arow][ahalf*4+1] = lo;
        hi = split_pack(la1.x, la1.y, lo); sAh[0][arow][ahalf*4+2] = hi; sAl[0][arow][ahalf*4+2] = lo;
        hi = split_pack(la1.z, la1.w, lo); sAh[0][arow][ahalf*4+3] = hi; sAl[0][arow][ahalf*4+3] = lo;
#pragma unroll
        for (int p = 0; p < 2; p++) {
            hi = split_pack(lb[p][0], lb[p][1], lo);
            sBh[0][bn[p]][bkp[p]] = hi; sBl[0][bn[p]][bkp[p]] = lo;
        }
    }
    __syncthreads();

    const int ar = lane >> 2, ac = lane & 3;
    int buf = 0;
    for (int k0 = 0; k0 < K; k0 += 16) {
        const bool has = (k0 + 16) < K;
        if (has) {
            la0 = *(const float4*)(Ap + k0 + 16);
            la1 = *(const float4*)(Ap + k0 + 20);
#pragma unroll
            for (int p = 0; p < 2; p++) {
                lb[p][0] = B[(long long)(k0 + 16 + 2 * bkp[p]) * N + n0 + bn[p]];
                lb[p][1] = B[(long long)(k0 + 17 + 2 * bkp[p]) * N + n0 + bn[p]];
            }
        }

        // fragment loads
        u32 ah[2][4], al[2][4];
#pragma unroll
        for (int mt = 0; mt < 2; mt++) {
            int r = wm * 32 + mt * 16 + ar;
            ah[mt][0] = sAh[buf][r][ac];       al[mt][0] = sAl[buf][r][ac];
            ah[mt][1] = sAh[buf][r + 8][ac];   al[mt][1] = sAl[buf][r + 8][ac];
            ah[mt][2] = sAh[buf][r][ac + 4];   al[mt][2] = sAl[buf][r][ac + 4];
            ah[mt][3] = sAh[buf][r + 8][ac + 4]; al[mt][3] = sAl[buf][r + 8][ac + 4];
        }
#pragma unroll
        for (int nt = 0; nt < 4; nt++) {
            int nr = wn * 32 + nt * 8 + ar;
            u32 bh0 = sBh[buf][nr][ac], bh1 = sBh[buf][nr][ac + 4];
            u32 bl0 = sBl[buf][nr][ac], bl1 = sBl[buf][nr][ac + 4];
#pragma unroll
            for (int mt = 0; mt < 2; mt++) {
                MMA16816(acc[mt][nt], ah[mt], bh0, bh1);   // hi*hi
                MMA16816(acc[mt][nt], ah[mt], bl0, bl1);   // hi*lo
                MMA16816(acc[mt][nt], al[mt], bh0, bh1);   // lo*hi
            }
        }

        if (has) {
            int nb = buf ^ 1;
            u32 lo, hi;
            hi = split_pack(la0.x, la0.y, lo); sAh[nb][arow][ahalf*4+0] = hi; sAl[nb][arow][ahalf*4+0] = lo;
            hi = split_pack(la0.z, la0.w, lo); sAh[nb][arow][ahalf*4+1] = hi; sAl[nb][arow][ahalf*4+1] = lo;
            hi = split_pack(la1.x, la1.y, lo); sAh[nb][arow][ahalf*4+2] = hi; sAl[nb][arow][ahalf*4+2] = lo;
            hi = split_pack(la1.z, la1.w, lo); sAh[nb][arow][ahalf*4+3] = hi; sAl[nb][arow][ahalf*4+3] = lo;
#pragma unroll
            for (int p = 0; p < 2; p++) {
                hi = split_pack(lb[p][0], lb[p][1], lo);
                sBh[nb][bn[p]][bkp[p]] = hi; sBl[nb][bn[p]][bkp[p]] = lo;
            }
        }
        __syncthreads();
        buf ^= 1;
    }

    // epilogue
#pragma unroll
    for (int mt = 0; mt < 2; mt++) {
        int r = m0 + wm * 32 + mt * 16 + ar;
#pragma unroll
        for (int nt = 0; nt < 4; nt++) {
            int c = n0 + wn * 32 + nt * 8 + ac * 2;
            float2 v0 = make_float2(acc[mt][nt][0], acc[mt][nt][1]);
            float2 v1 = make_float2(acc[mt][nt][2], acc[mt][nt][3]);
            if (relu) {
                v0.x = fmaxf(v0.x, 0.f); v0.y = fmaxf(v0.y, 0.f);
                v1.x = fmaxf(v1.x, 0.f); v1.y = fmaxf(v1.y, 0.f);
            }
            *(float2*)&C[(long long)r * N + c] = v0;
            *(float2*)&C[(long long)(r + 8) * N + c] = v1;
        }
    }
}

// ---------------- aligned fast fp32 GEMM: 64 x 64 tile, KT=16, double buffered ----------------
template<int RN>   // TN = 16*RN
__global__ __launch_bounds__(256)
void gemm_al(const float* __restrict__ A, const float* __restrict__ B,
             float* __restrict__ C, int M, int N, int K,
             long long sA, long long sB, long long sC,
             const float* __restrict__ bias, int relu)
{
    constexpr int TN = 16 * RN;
    A += (long long)blockIdx.z * sA;
    B += (long long)blockIdx.z * sB;
    C += (long long)blockIdx.z * sC;

    __shared__ float As[2][16][68];
    __shared__ float Bs[2][16][TN];

    const int tid = threadIdx.x;
    const int tx = tid & 15, ty = tid >> 4;
    const int m0 = blockIdx.y * 64, n0 = blockIdx.x * TN;

    const int ar = tid >> 2;
    const int ak = (tid & 3) * 4;
    const int bk = tid >> 4;
    const int bn = (tid & 15) * RN;

    const float* Ap = A + (long long)(m0 + ar) * K + ak;
    const float* Bp = B + (long long)bk * N + n0 + bn;

    float acc[4][RN];
#pragma unroll
    for (int i = 0; i < 4; i++)
#pragma unroll
        for (int j = 0; j < RN; j++) acc[i][j] = 0.f;

    {
        float4 av = *(const float4*)Ap;
        As[0][ak + 0][ar] = av.x; As[0][ak + 1][ar] = av.y;
        As[0][ak + 2][ar] = av.z; As[0][ak + 3][ar] = av.w;
#pragma unroll
        for (int h = 0; h < RN / 4; h++)
            *(float4*)&Bs[0][bk][bn + h * 4] = *(const float4*)(Bp + h * 4);
    }
    __syncthreads();

    int buf = 0;
    for (int k0 = 0; k0 < K; k0 += 16) {
        const bool has = (k0 + 16) < K;
        float4 la;
        float4 lbv[RN / 4];
        if (has) {
            la = *(const float4*)(Ap + k0 + 16);
#pragma unroll
            for (int h = 0; h < RN / 4; h++)
                lbv[h] = *(const float4*)(Bp + (long long)(k0 + 16) * N + h * 4);
        }

#pragma unroll
        for (int kk = 0; kk < 16; kk++) {
            float4 a4 = *(const float4*)&As[buf][kk][ty * 4];
            float a[4] = {a4.x, a4.y, a4.z, a4.w};
            float b[RN];
#pragma unroll
            for (int h = 0; h < RN / 4; h++) {
                float4 b4 = *(const float4*)&Bs[buf][kk][h * 64 + tx * 4];
                b[h * 4 + 0] = b4.x; b[h * 4 + 1] = b4.y;
                b[h * 4 + 2] = b4.z; b[h * 4 + 3] = b4.w;
            }
#pragma unroll
            for (int i = 0; i < 4; i++)
#pragma unroll
                for (int j = 0; j < RN; j++) acc[i][j] += a[i] * b[j];
        }

        if (has) {
            int nb = buf ^ 1;
            As[nb][ak + 0][ar] = la.x; As[nb][ak + 1][ar] = la.y;
            As[nb][ak + 2][ar] = la.z; As[nb][ak + 3][ar] = la.w;
#pragma unroll
            for (int h = 0; h < RN / 4; h++)
                *(float4*)&Bs[nb][bk][bn + h * 4] = lbv[h];
        }
        __syncthreads();
        buf ^= 1;
    }

#pragma unroll
    for (int i = 0; i < 4; i++) {
        int m = m0 + ty * 4 + i;
        float bv = bias ? bias[m] : 0.f;
#pragma unroll
        for (int h = 0; h < RN / 4; h++) {
            float4 v;
            v.x = acc[i][h * 4 + 0] + bv;
            v.y = acc[i][h * 4 + 1] + bv;
            v.z = acc[i][h * 4 + 2] + bv;
            v.w = acc[i][h * 4 + 3] + bv;
            if (relu) {
                v.x = fmaxf(v.x, 0.f); v.y = fmaxf(v.y, 0.f);
                v.z = fmaxf(v.z, 0.f); v.w = fmaxf(v.w, 0.f);
            }
            *(float4*)&C[(long long)m * N + n0 + h * 64 + tx * 4] = v;
        }
    }
}

// ---------------- fallback 64x64 GEMM (any shape; known-good) ----------------
__global__ void gemm64(const float* __restrict__ A, const float* __restrict__ B,
                       float* __restrict__ C, int M, int N, int K,
                       long long sA, long long sB, long long sC,
                       const float* __restrict__ bias, int relu)
{
    A += (long long)blockIdx.z * sA;
    B += (long long)blockIdx.z * sB;
    C += (long long)blockIdx.z * sC;
    __shared__ float As[16][64];
    __shared__ float Bs[16][68];
    int tx = threadIdx.x, ty = threadIdx.y;
    int tid = ty * 16 + tx;
    int m0 = blockIdx.y * 64, n0 = blockIdx.x * 64;
    int mA = tid >> 2, kA = (tid & 3) * 4;
    int kB = tid >> 4, nB = (tid & 15) * 4;
    float acc[4][4];
#pragma unroll
    for (int i = 0; i < 4; i++)
#pragma unroll
        for (int j = 0; j < 4; j++) acc[i][j] = 0.f;

    for (int k0 = 0; k0 < K; k0 += 16) {
#pragma unroll
        for (int i = 0; i < 4; i++) {
            int k = k0 + kA + i;
            As[kA + i][mA] = (m0 + mA < M && k < K) ? A[(long long)(m0 + mA) * K + k] : 0.f;
        }
#pragma unroll
        for (int i = 0; i < 4; i++) {
            int n = n0 + nB + i;
            Bs[kB][nB + i] = (k0 + kB < K && n < N) ? B[(long long)(k0 + kB) * N + n] : 0.f;
        }
        __syncthreads();
#pragma unroll
        for (int kk = 0; kk < 16; kk++) {
            float a[4], b[4];
#pragma unroll
            for (int i = 0; i < 4; i++) a[i] = As[kk][ty * 4 + i];
#pragma unroll
            for (int j = 0; j < 4; j++) b[j] = Bs[kk][tx * 4 + j];
#pragma unroll
            for (int i = 0; i < 4; i++)
#pragma unroll
                for (int j = 0; j < 4; j++) acc[i][j] += a[i] * b[j];
        }
        __syncthreads();
    }
#pragma unroll
    for (int i = 0; i < 4; i++) {
        int m = m0 + ty * 4 + i;
        if (m >= M) continue;
        float bv = bias ? bias[m] : 0.f;
#pragma unroll
        for (int j = 0; j < 4; j++) {
            int n = n0 + tx * 4 + j;
            if (n >= N) continue;
            float v = acc[i][j] + bv;
            if (relu) v = fmaxf(v, 0.f);
            C[(long long)m * N + n] = v;
        }
    }
}

// ---------------- 512->18 offset-head 3x3 conv, channel-split partials ----------------
__global__ void conv18_k(const float* __restrict__ in, long long inB,
                         const float* __restrict__ w, float* __restrict__ part, int C)
{
    const int t = blockIdx.x, cc = blockIdx.y, b = blockIdx.z;
    const int tid = threadIdx.x;
    const int hw = t * 256 + tid;
    const int h = hw / WW, x = hw % WW;
    const int hf = (t * 256) / WW;

    __shared__ float sIn[4][9 * WW];
    __shared__ float sW[4][18 * 9];

    float acc[18];
#pragma unroll
    for (int o = 0; o < 18; o++) acc[o] = 0.f;

    const float* ib = in + (long long)b * inB + (long long)(cc * 64) * HW2;
    const int lr = h - (hf - 1);

    for (int cs = 0; cs < 64; cs += 4) {
        for (int i = tid; i < 4 * 9 * WW; i += 256) {
            int c = i / (9 * WW), r = i % (9 * WW);
            int row = hf - 1 + r / WW, col = r % WW;
            float v = 0.f;
            if (row >= 0 && row < HH) v = ib[(long long)(cs + c) * HW2 + row * WW + col];
            sIn[c][r] = v;
        }
        for (int i = tid; i < 4 * 162; i += 256) {
            int c = i / 162, r = i % 162;
            int o = r / 9, q = r % 9;
            sW[c][r] = w[((long long)o * C + (cc * 64 + cs + c)) * 9 + q];
        }
        __syncthreads();

#pragma unroll
        for (int c = 0; c < 4; c++) {
            float tap[9];
#pragma unroll
            for (int ki = 0; ki < 3; ki++)
#pragma unroll
                for (int kj = 0; kj < 3; kj++) {
                    int xx = x - 1 + kj;
                    float v = 0.f;
                    if (xx >= 0 && xx < WW) v = sIn[c][(lr - 1 + ki) * WW + xx];
                    tap[ki * 3 + kj] = v;
                }
#pragma unroll
            for (int o = 0; o < 18; o++) {
                float s = acc[o];
#pragma unroll
                for (int q = 0; q < 9; q++) s += sW[c][o * 9 + q] * tap[q];
                acc[o] = s;
            }
        }
        __syncthreads();
    }

    float* pp = part + ((long long)cc * 2 + b) * 18 * HW2;
#pragma unroll
    for (int o = 0; o < 18; o++) pp[(long long)o * HW2 + hw] = acc[o];
}

__global__ void reduce18_k(const float* __restrict__ part, float* __restrict__ out)
{
    int idx = blockIdx.x * 256 + threadIdx.x;
    if (idx >= 2 * 18 * HW2) return;
    int b = idx / (18 * HW2);
    int r = idx % (18 * HW2);
    float s = 0.f;
#pragma unroll
    for (int c = 0; c < 8; c++) s += part[((long long)c * 2 + b) * 18 * HW2 + r];
    out[(long long)b * 18 * HW2 + r] = s;
}

// ---------------- deformable (or plain) 3x3 s1 p1 im2col over 48x48 ----------------
__global__ void deform_im2col_k(const float* __restrict__ src, long long srcB,
                                const float* __restrict__ off,
                                float* __restrict__ cols, int C)
{
    int hw = blockIdx.x * 256 + threadIdx.x;
    if (hw >= HW2) return;
    int bq = blockIdx.y;
    int b = bq / 9, q = bq % 9;
    int ki = q / 3, kj = q % 3;
    int h = hw / WW, w = hw % WW;
    const float* sb = src + (long long)b * srcB;
    float* cb = cols + (long long)b * C * 9 * HW2;
    int c0 = blockIdx.z * 64;
    int c1 = c0 + 64; if (c1 > C) c1 = C;

    if (off == nullptr) {
        int y = h - 1 + ki, x = w - 1 + kj;
        bool vin = (y >= 0 && y < HH && x >= 0 && x < WW);
        int idx = vin ? (y * WW + x) : 0;
        for (int c = c0; c < c1; c++) {
            float v = vin ? sb[(long long)c * HW2 + idx] : 0.f;
            cb[((long long)c * 9 + q) * HW2 + hw] = v;
        }
    } else {
        float py = (float)(h - 1 + ki) + off[((long long)b * 18 + 2 * q) * HW2 + hw];
        float px = (float)(w - 1 + kj) + off[((long long)b * 18 + 2 * q + 1) * HW2 + hw];
        float fy = floorf(py), fx = floorf(px);
        float ay = py - fy, ax = px - fx;
        int y0 = (int)fy, x0 = (int)fx;
        int y1 = y0 + 1, x1 = x0 + 1;
        bool by0 = (y0 >= 0 && y0 < HH), by1 = (y1 >= 0 && y1 < HH);
        bool bx0 = (x0 >= 0 && x0 < WW), bx1 = (x1 >= 0 && x1 < WW);
        int yc0 = min(max(y0, 0), HH - 1), yc1 = min(max(y1, 0), HH - 1);
        int xc0 = min(max(x0, 0), WW - 1), xc1 = min(max(x1, 0), WW - 1);
        float w00 = (by0 && bx0) ? (1.f - ay) * (1.f - ax) : 0.f;
        float w01 = (by0 && bx1) ? (1.f - ay) * ax : 0.f;
        float w10 = (by1 && bx0) ? ay * (1.f - ax) : 0.f;
        float w11 = (by1 && bx1) ? ay * ax : 0.f;
        int i00 = yc0 * WW + xc0, i01 = yc0 * WW + xc1;
        int i10 = yc1 * WW + xc0, i11 = yc1 * WW + xc1;
        for (int c = c0; c < c1; c++) {
            const float* s = sb + (long long)c * HW2;
            float v = w00 * s[i00] + w01 * s[i01] + w10 * s[i10] + w11 * s[i11];
            cb[((long long)c * 9 + q) * HW2 + hw] = v;
        }
    }
}

// ---------------- generic strided im2col (5x5 s2 p2 and 3x3 s2 p1) ----------------
__global__ void im2col_g(const float* __restrict__ src, long long srcB,
                         float* __restrict__ cols,
                         int C, int H, int W, int KH, int KW,
                         int stride, int pad, int OH, int OW)
{
    int ohw = blockIdx.x * 256 + threadIdx.x;
    int OHW = OH * OW;
    if (ohw >= OHW) return;
    int row = blockIdx.y;
    int b = blockIdx.z;
    int kk = row % (KH * KW);
    int c = row / (KH * KW);
    int kh = kk / KW, kw = kk % KW;
    int oh = ohw / OW, ow = ohw % OW;
    int ih = oh * stride - pad + kh;
    int iw = ow * stride - pad + kw;
    float v = 0.f;
    if (ih >= 0 && ih < H && iw >= 0 && iw < W)
        v = src[(long long)b * srcB + ((long long)c * H + ih) * W + iw];
    cols[((long long)b * C * KH * KW + row) * OHW + ohw] = v;
}

// ---------------- direct 3x3 s1 p1 conv (tiny s3: 64->1) ----------------
__global__ void conv3x3_direct(const float* __restrict__ in, long long inB,
                               const float* __restrict__ w, float* __restrict__ out,
                               long long outB, int C, int relu)
{
    int hw = blockIdx.x * 256 + threadIdx.x;
    if (hw >= HW2) return;
    int o = blockIdx.y, b = blockIdx.z;
    int h = hw / WW, x = hw % WW;
    const float* ib = in + (long long)b * inB;
    const float* wo = w + (long long)o * C * 9;
    float acc = 0.f;
    for (int c = 0; c < C; c++) {
        const float* ic = ib + (long long)c * HW2;
        const float* wc = wo + c * 9;
#pragma unroll
        for (int kh = 0; kh < 3; kh++) {
            int ih = h + kh - 1;
            if (ih < 0 || ih >= HH) continue;
#pragma unroll
            for (int kw = 0; kw < 3; kw++) {
                int iw = x + kw - 1;
                if (iw < 0 || iw >= WW) continue;
                acc += ic[ih * WW + iw] * wc[kh * 3 + kw];
            }
        }
    }
    if (relu) acc = fmaxf(acc, 0.f);
    out[(long long)b * outB + (long long)o * HW2 + hw] = acc;
}

// ---------------- elementwise kernels ----------------
__global__ void concat_k(const float* __restrict__ a, const float* __restrict__ b_,
                         float* __restrict__ o, long long imgStride)
{
    int idx = blockIdx.x * 256 + threadIdx.x;
    if (idx >= 2 * 512 * HW2) return;
    int bb = idx / (512 * HW2);
    int c = (idx / HW2) % 512;
    int hw = idx % HW2;
    float v = (c < 256) ? a[bb * imgStride + (long long)c * HW2 + hw]
                        : b_[bb * imgStride + (long long)(c - 256) * HW2 + hw];
    o[idx] = v;
}

__global__ void corr_k(const float* __restrict__ Ra, const float* __restrict__ Tb,
                       float* __restrict__ f177)
{
    int idx = blockIdx.x * 256 + threadIdx.x;
    if (idx >= 2 * 49 * HW2) return;
    int b = idx / (49 * HW2);
    int q = (idx / HW2) % 49;
    int hw = idx % HW2;
    int h = hw / WW, w = hw % WW;
    int dy = 2 * ((q / 7) - 3), dx = 2 * ((q % 7) - 3);
    int hh = h + dy, ww = w + dx;
    float s = 0.f;
    if (hh >= 0 && hh < HH && ww >= 0 && ww < WW) {
        const float* a = Ra + (long long)b * (2 * 64 * HW2) + hw;
        const float* bp = Tb + (long long)b * (2 * 64 * HW2) + hh * WW + ww;
        for (int c = 0; c < 64; c++) s += a[c * HW2] * bp[c * HW2];
    }
    f177[((long long)b * 177 + q) * HW2 + hw] = s * (1.f / 64.f);
}

__global__ void pack_k(const float* __restrict__ eA, const float* __restrict__ eB,
                       float* __restrict__ f177)
{
    int idx = blockIdx.x * 256 + threadIdx.x;
    if (idx >= 2 * 64 * HW2) return;
    int b = idx / (64 * HW2);
    int c = (idx / HW2) % 64;
    int hw = idx % HW2;
    f177[((long long)b * 177 + 49 + c) * HW2 + hw] = eA[idx];
    f177[((long long)b * 177 + 113 + c) * HW2 + hw] = eB[idx];
}

__global__ void mean36_k(const float* __restrict__ in, float* __restrict__ fw, int total)
{
    int i = blockIdx.x * 256 + threadIdx.x;
    if (i >= total) return;
    float s = 0.f;
#pragma unroll
    for (int j = 0; j < 36; j++) s += in[i * 36 + j];
    fw[i] = s * (1.f / 36.f);
}

__global__ void mkw_k(const float* __restrict__ fw, const float* __restrict__ Wt,
                      const float* __restrict__ Bi, float* __restrict__ adw,
                      int M, int Kc, int total)
{
    int idx = blockIdx.x * 256 + threadIdx.x;
    if (idx >= total) return;
    int b = idx / (M * Kc);
    int r = idx - b * M * Kc;
    int o = r / Kc;
    adw[idx] = fw[b * M + o] * Wt[r] + Bi[r];
}

__global__ void final_k(const float* __restrict__ d0, const float* __restrict__ d1,
                        const float* __restrict__ s0p, const float* __restrict__ s1p,
                        float* __restrict__ out, int total)
{
    int idx = blockIdx.x * 256 + threadIdx.x;
    if (idx >= total) return;
    int b = idx / (256 * HW2);
    int hw = idx % HW2;
    float s0 = s0p[b * HW2 + hw];
    float s1 = s1p[b * HW2 + hw];
    const float eps = 1e-8f;
    float wx = (s0 * s1) / (fmaxf(fabsf(s0), eps) * fmaxf(fabsf(s1), eps));
    float wy = (s1 * s1) / (fmaxf(fabsf(s1), eps) * fmaxf(fabsf(s1), eps));
    float mx = fmaxf(wx, wy);
    float e0 = expf(wx - mx), e1 = expf(wy - mx);
    float inv = 1.f / (e0 + e1);
    out[idx] = d0[idx] * (e0 * inv) + d1[idx] * (e1 * inv);
}

// ---------------- host orchestration ----------------
extern "C" void kernel_launch(void* const* d_in, const int* in_sizes, int n_in,
                              void* d_out, int out_size)
{
    (void)in_sizes; (void)n_in; (void)out_size;
    const float* R0     = (const float*)d_in[0];
    const float* T0     = (const float*)d_in[1];
    const float* inp    = (const float*)d_in[2];
    const float* enc0_w = (const float*)d_in[3];
    const float* enc0_b = (const float*)d_in[4];
    const float* enc1_w = (const float*)d_in[5];
    const float* enc1_b = (const float*)d_in[6];
    const float* offw[4] = {(const float*)d_in[7], (const float*)d_in[8],
                            (const float*)d_in[9], (const float*)d_in[10]};
    const float* defw[3] = {(const float*)d_in[11], (const float*)d_in[12],
                            (const float*)d_in[13]};
    const float* w0a = (const float*)d_in[14];
    const float* w0b = (const float*)d_in[15];
    const float* w0c = (const float*)d_in[16];
    const float* w1a = (const float*)d_in[17];
    const float* w1b = (const float*)d_in[18];
    const float* w1c = (const float*)d_in[19];
    const float* wx_w  = (const float*)d_in[20];
    const float* wx_b  = (const float*)d_in[21];
    const float* wxf_w = (const float*)d_in[22];
    const float* wxf_b = (const float*)d_in[23];
    const float* s1w = (const float*)d_in[24];
    const float* s2w = (const float*)d_in[25];
    const float* s3w = (const float*)d_in[26];
    float* out = (float*)d_out;

    float *xenc, *yenc, *f512a, *f512b, *cols, *off, *cpart, *f177, *f177b;
    float *wb1, *wb2, *wb3, *fw, *adw, *def0, *def1, *s1o, *s2o, *swa, *swb;
    cudaGetSymbolAddress((void**)&xenc,  g_xenc);
    cudaGetSymbolAddress((void**)&yenc,  g_yenc);
    cudaGetSymbolAddress((void**)&f512a, g_f512a);
    cudaGetSymbolAddress((void**)&f512b, g_f512b);
    cudaGetSymbolAddress((void**)&cols,  g_cols);
    cudaGetSymbolAddress((void**)&off,   g_offb);
    cudaGetSymbolAddress((void**)&cpart, g_cpart);
    cudaGetSymbolAddress((void**)&f177,  g_f177);
    cudaGetSymbolAddress((void**)&f177b, g_f177b);
    cudaGetSymbolAddress((void**)&wb1,   g_wb1);
    cudaGetSymbolAddress((void**)&wb2,   g_wb2);
    cudaGetSymbolAddress((void**)&wb3,   g_wb3);
    cudaGetSymbolAddress((void**)&fw,    g_fwb);
    cudaGetSymbolAddress((void**)&adw,   g_adw);
    cudaGetSymbolAddress((void**)&def0,  g_def0);
    cudaGetSymbolAddress((void**)&def1,  g_def1);
    cudaGetSymbolAddress((void**)&s1o,   g_s1o);
    cudaGetSymbolAddress((void**)&s2o,   g_s2o);
    cudaGetSymbolAddress((void**)&swa,   g_swa);
    cudaGetSymbolAddress((void**)&swb,   g_swb);

    const long long imgStride = 2LL * 256 * HW2;

    // tensor-core bf16x3 GEMM (M%128==0, N%64==0, K%16==0)
    auto GEMMT = [&](const float* A, const float* Bm, float* C, int M, int N, int K,
                     long long sA, long long sB, long long sC, int relu) {
        gemm_bf3<<<dim3(N / 64, M / 128, 2), 256>>>(A, Bm, C, M, N, K, sA, sB, sC, relu);
    };
    // fp32 aligned GEMM (M%64==0, K%16==0, N%64==0)
    auto GEMMA = [&](const float* A, const float* Bm, float* C, int M, int N, int K,
                     long long sA, long long sB, long long sC,
                     const float* bias, int relu) {
        gemm_al<4><<<dim3(N / 64, M / 64, 2), 256>>>(A, Bm, C, M, N, K, sA, sB, sC, bias, relu);
    };
    // fallback for odd shapes
    auto GEMMF = [&](const float* A, const float* Bm, float* C, int M, int N, int K,
                     long long sA, long long sB, long long sC,
                     const float* bias, int relu) {
        dim3 g((N + 63) / 64, (M + 63) / 64, 2);
        gemm64<<<g, dim3(16, 16)>>>(A, Bm, C, M, N, K, sA, sB, sC, bias, relu);
    };
    auto DIM2COL = [&](const float* src, long long sB, const float* offp, int C) {
        dim3 g((HW2 + 255) / 256, 18, (C + 63) / 64);
        deform_im2col_k<<<g, 256>>>(src, sB, offp, cols, C);
    };
    auto IM2COL = [&](const float* src, long long sB, int C, int H, int W,
                      int KH, int KW, int st, int pad, int OH, int OW) {
        dim3 g((OH * OW + 255) / 256, C * KH * KW, 2);
        im2col_g<<<g, 256>>>(src, sB, cols, C, H, W, KH, KW, st, pad, OH, OW);
    };
    auto CONV18 = [&](const float* in, long long inB, const float* w, float* o) {
        conv18_k<<<dim3(9, 8, 2), 256>>>(in, inB, w, cpart, 512);
        reduce18_k<<<(2 * 18 * HW2 + 255) / 256, 256>>>(cpart, o);
    };
    auto WBRANCH = [&](const float* feat, const float* wa, const float* wb,
                       const float* wc, int Mc) {
        IM2COL(feat, 177LL * HW2, 177, 48, 48, 5, 5, 2, 2, 24, 24);
        GEMMF(wa, cols, wb1, 64, 576, 4425, 0, 4425LL * 576, 64LL * 576, nullptr, 1);
        IM2COL(wb1, 64LL * 576, 64, 24, 24, 5, 5, 2, 2, 12, 12);
        GEMMF(wb, cols, wb2, 64, 144, 1600, 0, 1600LL * 144, 64LL * 144, nullptr, 1);
        IM2COL(wb2, 64LL * 144, 64, 12, 12, 3, 3, 2, 1, 6, 6);
        GEMMF(wc, cols, wb3, Mc, 36, 576, 0, 576LL * 36, (long long)Mc * 36, nullptr, 0);
        int tot = 2 * Mc;
        mean36_k<<<(tot + 255) / 256, 256>>>(wb3, fw, tot);
    };

    // ---- encoders (1x1 conv == GEMM on NCHW directly) ----
    GEMMA(enc0_w, inp,             xenc, 64, HW2, 256, 0, imgStride, 64LL * HW2, enc0_b, 0);
    GEMMA(enc1_w, inp + 256 * HW2, yenc, 64, HW2, 256, 0, imgStride, 64LL * HW2, enc1_b, 0);

    auto BRANCH = [&](int br, float* gdef, float* gsw) {
        const float* imgA = (br == 0) ? inp : inp + 256 * HW2;
        const float* imgB = inp + 256 * HW2;   // y for both branches

        // ---- stsn_offset ----
        {
            int tot = 2 * 512 * HW2;
            concat_k<<<(tot + 255) / 256, 256>>>(imgA, imgB, f512a, imgStride);
        }
        float* cur = f512a; float* oth = f512b;
        for (int i = 0; i < 3; i++) {
            CONV18(cur, 512LL * HW2, offw[i], off);
            DIM2COL(cur, 512LL * HW2, off, 512);
            GEMMT(defw[i], cols, oth, 512, HW2, 4608, 0, 4608LL * HW2, 512LL * HW2, 0);
            float* t = cur; cur = oth; oth = t;
        }
        CONV18(cur, 512LL * HW2, offw[3], off);  // final offsets -> g_offb

        // ---- astsn_weight ----
        const float* Ra = R0 + (br == 0 ? 0 : 64 * HW2);   // R_pre / R_cur
        const float* Tb = T0 + 64 * HW2;                    // T_cur
        const float* eA = (br == 0) ? xenc : yenc;
        const float* eB = yenc;
        {
            int tot = 2 * 49 * HW2;
            corr_k<<<(tot + 255) / 256, 256>>>(Ra, Tb, f177);
        }
        {
            int tot = 2 * 64 * HW2;
            pack_k<<<(tot + 255) / 256, 256>>>(eA, eB, f177);
        }
        WBRANCH(f177, w0a, w0b, w0c, 177);
        {
            int tot = 2 * 177 * 1593;
            mkw_k<<<(tot + 255) / 256, 256>>>(fw, wx_w, wx_b, adw, 177, 1593, tot);
        }
        DIM2COL(f177, 177LL * HW2, nullptr, 177);
        GEMMF(adw, cols, f177b, 177, HW2, 1593, 177LL * 1593, 1593LL * HW2, 177LL * HW2,
              nullptr, 1);
        WBRANCH(f177b, w1a, w1b, w1c, 256);
        {
            int tot = 2 * 256 * 2304;
            mkw_k<<<(tot + 255) / 256, 256>>>(fw, wxf_w, wxf_b, adw, 256, 2304, tot);
        }

        // ---- adaptive deform conv ----
        DIM2COL(imgA, imgStride, off, 256);
        GEMMT(adw, cols, gdef, 256, HW2, 2304, 256LL * 2304, 2304LL * HW2, 256LL * HW2, 0);

        // ---- s_net ----
        DIM2COL(gdef, 256LL * HW2, nullptr, 256);
        GEMMT(s1w, cols, s1o, 128, HW2, 2304, 0, 2304LL * HW2, 128LL * HW2, 1);
        DIM2COL(s1o, 128LL * HW2, nullptr, 128);
        GEMMA(s2w, cols, s2o, 64, HW2, 1152, 0, 1152LL * HW2, 64LL * HW2, nullptr, 1);
        conv3x3_direct<<<dim3(9, 1, 2), 256>>>(s2o, 64LL * HW2, s3w, gsw,
                                               (long long)HW2, 64, 1);
    };

    BRANCH(0, def0, swa);
    BRANCH(1, def1, swb);

    {
        int tot = 2 * 256 * HW2;
        final_k<<<(tot + 255) / 256, 256>>>(def0, def1, swa, swb, out, tot);
    }
}

// round 6
// speedup vs baseline: 2.0042x; 1.0121x over previous
#include <cuda_runtime.h>
#include <cuda_bf16.h>
#include <math.h>

#define HW2 2304
#define HH 48
#define WW 48

typedef unsigned int u32;
typedef unsigned short u16;

// ---------------- device scratch (no allocations allowed) ----------------
__device__ float g_xenc  [2*64 *HW2];
__device__ float g_yenc  [2*64 *HW2];
__device__ float g_f512a [2*512*HW2];
__device__ float g_f512b [2*512*HW2];
__device__ float g_cols  [2*1600*HW2];   // fp32 cols (only small GEMM paths)
__device__ u16   g_colsh [2*4608*HW2];   // bf16-hi cols for tensor GEMMs
__device__ u16   g_colsl [2*4608*HW2];   // bf16-lo cols
__device__ u16   g_awh   [2*512*4608];   // pre-split A (weights) hi
__device__ u16   g_awl   [2*512*4608];   // pre-split A lo
__device__ float g_offb  [2*18 *HW2];
__device__ float g_cpart [16*2*18*HW2];  // conv18 channel-split partials
__device__ float g_f177  [2*177*HW2];
__device__ float g_f177b [2*177*HW2];
__device__ float g_wb1   [2*64*576];
__device__ float g_wb2   [2*64*144];
__device__ float g_wb3   [2*256*36];
__device__ float g_fwb   [2*256];
__device__ float g_adw   [2*256*HW2];
__device__ float g_def0  [2*256*HW2];
__device__ float g_def1  [2*256*HW2];
__device__ float g_s1o   [2*128*HW2];
__device__ float g_s2o   [2*64*HW2];
__device__ float g_swa   [2*HW2];
__device__ float g_swb   [2*HW2];

// ---------------- helpers ----------------
__device__ __forceinline__ void split16(float x, u16& h, u16& l)
{
    __nv_bfloat16 xh = __float2bfloat16(x);
    h = __bfloat16_as_ushort(xh);
    l = __bfloat16_as_ushort(__float2bfloat16(x - __bfloat162float(xh)));
}

// weight pre-split: fp32[n] -> bf16 hi/lo
__global__ void convw_k(const float* __restrict__ src, u16* __restrict__ h,
                        u16* __restrict__ l, int n)
{
    int i = blockIdx.x * 256 + threadIdx.x;
    if (i >= n) return;
    u16 hh, ll;
    split16(src[i], hh, ll);
    h[i] = hh; l[i] = ll;
}

#define MMA16816(c, a, b0v, b1v) \
    asm volatile("mma.sync.aligned.m16n8k16.row.col.f32.bf16.bf16.f32 " \
        "{%0,%1,%2,%3},{%4,%5,%6,%7},{%8,%9},{%0,%1,%2,%3};" \
        : "+f"((c)[0]), "+f"((c)[1]), "+f"((c)[2]), "+f"((c)[3]) \
        : "r"((a)[0]), "r"((a)[1]), "r"((a)[2]), "r"((a)[3]), \
          "r"(b0v), "r"(b1v))

// ---------------- bf16x3 split tensor-core GEMM, pre-split inputs ----------------
// C[M,N] = A[M,K]*B[K,N]; A,B given as separate bf16 hi/lo arrays.
// Requires M%128==0, N%64==0, K%16==0. Tile 128x64, KT=16, 8 warps (4m x 2n).
__global__ __launch_bounds__(256)
void gemm_bf3b(const u16* __restrict__ Ah, const u16* __restrict__ Al,
               const u16* __restrict__ Bh, const u16* __restrict__ Bl,
               float* __restrict__ C, int M, int N, int K,
               long long sA, long long sB, long long sC, int relu)
{
    Ah += (long long)blockIdx.z * sA;
    Al += (long long)blockIdx.z * sA;
    Bh += (long long)blockIdx.z * sB;
    Bl += (long long)blockIdx.z * sB;
    C  += (long long)blockIdx.z * sC;

    __shared__ u32 sAh[2][128][12];
    __shared__ u32 sAl[2][128][12];
    __shared__ u32 sBh[2][64][12];
    __shared__ u32 sBl[2][64][12];

    const int tid = threadIdx.x;
    const int lane = tid & 31, warp = tid >> 5;
    const int wm = warp >> 1, wn = warp & 1;
    const int m0 = blockIdx.y * 128, n0 = blockIdx.x * 64;

    // A staging: row = tid>>1 (0..127), half = tid&1 -> k [half*8, half*8+8)
    const int arow = tid >> 1, ahalf = tid & 1;
    const u16* ApH = Ah + (long long)(m0 + arow) * K + ahalf * 8;
    const u16* ApL = Al + (long long)(m0 + arow) * K + ahalf * 8;

    // B staging: one (2n x 1kp) slot per thread
    const int bkp = tid & 7;              // k-pair 0..7
    const int bn  = (tid >> 3) * 2;       // n offset 0..62 (even)

    float acc[2][4][4];
#pragma unroll
    for (int mt = 0; mt < 2; mt++)
#pragma unroll
        for (int nt = 0; nt < 4; nt++)
#pragma unroll
            for (int i = 0; i < 4; i++) acc[mt][nt][i] = 0.f;

    uint4 lah, lal;
    u32 lbh0, lbh1, lbl0, lbl1;

    // prologue loads (k0 = 0)
    lah = *(const uint4*)ApH;
    lal = *(const uint4*)ApL;
    {
        const long long r0 = (long long)(2 * bkp) * N + n0 + bn;
        lbh0 = *(const u32*)(Bh + r0);
        lbh1 = *(const u32*)(Bh + r0 + N);
        lbl0 = *(const u32*)(Bl + r0);
        lbl1 = *(const u32*)(Bl + r0 + N);
    }
    // store buf 0
    {
        sAh[0][arow][ahalf*4+0] = lah.x; sAh[0][arow][ahalf*4+1] = lah.y;
        sAh[0][arow][ahalf*4+2] = lah.z; sAh[0][arow][ahalf*4+3] = lah.w;
        sAl[0][arow][ahalf*4+0] = lal.x; sAl[0][arow][ahalf*4+1] = lal.y;
        sAl[0][arow][ahalf*4+2] = lal.z; sAl[0][arow][ahalf*4+3] = lal.w;
        sBh[0][bn  ][bkp] = __byte_perm(lbh0, lbh1, 0x5410);
        sBh[0][bn+1][bkp] = __byte_perm(lbh0, lbh1, 0x7632);
        sBl[0][bn  ][bkp] = __byte_perm(lbl0, lbl1, 0x5410);
        sBl[0][bn+1][bkp] = __byte_perm(lbl0, lbl1, 0x7632);
    }
    __syncthreads();

    const int ar = lane >> 2, ac = lane & 3;
    int buf = 0;
    for (int k0 = 0; k0 < K; k0 += 16) {
        const bool has = (k0 + 16) < K;
        if (has) {
            lah = *(const uint4*)(ApH + k0 + 16);
            lal = *(const uint4*)(ApL + k0 + 16);
            const long long r0 = (long long)(k0 + 16 + 2 * bkp) * N + n0 + bn;
            lbh0 = *(const u32*)(Bh + r0);
            lbh1 = *(const u32*)(Bh + r0 + N);
            lbl0 = *(const u32*)(Bl + r0);
            lbl1 = *(const u32*)(Bl + r0 + N);
        }

        // fragment loads
        u32 ah[2][4], al[2][4];
#pragma unroll
        for (int mt = 0; mt < 2; mt++) {
            int r = wm * 32 + mt * 16 + ar;
            ah[mt][0] = sAh[buf][r][ac];         al[mt][0] = sAl[buf][r][ac];
            ah[mt][1] = sAh[buf][r + 8][ac];     al[mt][1] = sAl[buf][r + 8][ac];
            ah[mt][2] = sAh[buf][r][ac + 4];     al[mt][2] = sAl[buf][r][ac + 4];
            ah[mt][3] = sAh[buf][r + 8][ac + 4]; al[mt][3] = sAl[buf][r + 8][ac + 4];
        }
#pragma unroll
        for (int nt = 0; nt < 4; nt++) {
            int nr = wn * 32 + nt * 8 + ar;
            u32 bh0 = sBh[buf][nr][ac], bh1 = sBh[buf][nr][ac + 4];
            u32 bl0 = sBl[buf][nr][ac], bl1 = sBl[buf][nr][ac + 4];
#pragma unroll
            for (int mt = 0; mt < 2; mt++) {
                MMA16816(acc[mt][nt], ah[mt], bh0, bh1);   // hi*hi
                MMA16816(acc[mt][nt], ah[mt], bl0, bl1);   // hi*lo
                MMA16816(acc[mt][nt], al[mt], bh0, bh1);   // lo*hi
            }
        }

        if (has) {
            int nb = buf ^ 1;
            sAh[nb][arow][ahalf*4+0] = lah.x; sAh[nb][arow][ahalf*4+1] = lah.y;
            sAh[nb][arow][ahalf*4+2] = lah.z; sAh[nb][arow][ahalf*4+3] = lah.w;
            sAl[nb][arow][ahalf*4+0] = lal.x; sAl[nb][arow][ahalf*4+1] = lal.y;
            sAl[nb][arow][ahalf*4+2] = lal.z; sAl[nb][arow][ahalf*4+3] = lal.w;
            sBh[nb][bn  ][bkp] = __byte_perm(lbh0, lbh1, 0x5410);
            sBh[nb][bn+1][bkp] = __byte_perm(lbh0, lbh1, 0x7632);
            sBl[nb][bn  ][bkp] = __byte_perm(lbl0, lbl1, 0x5410);
            sBl[nb][bn+1][bkp] = __byte_perm(lbl0, lbl1, 0x7632);
        }
        __syncthreads();
        buf ^= 1;
    }

    // epilogue
#pragma unroll
    for (int mt = 0; mt < 2; mt++) {
        int r = m0 + wm * 32 + mt * 16 + ar;
#pragma unroll
        for (int nt = 0; nt < 4; nt++) {
            int c = n0 + wn * 32 + nt * 8 + ac * 2;
            float2 v0 = make_float2(acc[mt][nt][0], acc[mt][nt][1]);
            float2 v1 = make_float2(acc[mt][nt][2], acc[mt][nt][3]);
            if (relu) {
                v0.x = fmaxf(v0.x, 0.f); v0.y = fmaxf(v0.y, 0.f);
                v1.x = fmaxf(v1.x, 0.f); v1.y = fmaxf(v1.y, 0.f);
            }
            *(float2*)&C[(long long)r * N + c] = v0;
            *(float2*)&C[(long long)(r + 8) * N + c] = v1;
        }
    }
}

// ---------------- aligned fast fp32 GEMM: 64x64 tile, KT=16, double buffered ----------------
template<int RN>
__global__ __launch_bounds__(256)
void gemm_al(const float* __restrict__ A, const float* __restrict__ B,
             float* __restrict__ C, int M, int N, int K,
             long long sA, long long sB, long long sC,
             const float* __restrict__ bias, int relu)
{
    constexpr int TN = 16 * RN;
    A += (long long)blockIdx.z * sA;
    B += (long long)blockIdx.z * sB;
    C += (long long)blockIdx.z * sC;

    __shared__ float As[2][16][68];
    __shared__ float Bs[2][16][TN];

    const int tid = threadIdx.x;
    const int tx = tid & 15, ty = tid >> 4;
    const int m0 = blockIdx.y * 64, n0 = blockIdx.x * TN;

    const int ar = tid >> 2;
    const int ak = (tid & 3) * 4;
    const int bk = tid >> 4;
    const int bn = (tid & 15) * RN;

    const float* Ap = A + (long long)(m0 + ar) * K + ak;
    const float* Bp = B + (long long)bk * N + n0 + bn;

    float acc[4][RN];
#pragma unroll
    for (int i = 0; i < 4; i++)
#pragma unroll
        for (int j = 0; j < RN; j++) acc[i][j] = 0.f;

    {
        float4 av = *(const float4*)Ap;
        As[0][ak + 0][ar] = av.x; As[0][ak + 1][ar] = av.y;
        As[0][ak + 2][ar] = av.z; As[0][ak + 3][ar] = av.w;
#pragma unroll
        for (int h = 0; h < RN / 4; h++)
            *(float4*)&Bs[0][bk][bn + h * 4] = *(const float4*)(Bp + h * 4);
    }
    __syncthreads();

    int buf = 0;
    for (int k0 = 0; k0 < K; k0 += 16) {
        const bool has = (k0 + 16) < K;
        float4 la;
        float4 lbv[RN / 4];
        if (has) {
            la = *(const float4*)(Ap + k0 + 16);
#pragma unroll
            for (int h = 0; h < RN / 4; h++)
                lbv[h] = *(const float4*)(Bp + (long long)(k0 + 16) * N + h * 4);
        }

#pragma unroll
        for (int kk = 0; kk < 16; kk++) {
            float4 a4 = *(const float4*)&As[buf][kk][ty * 4];
            float a[4] = {a4.x, a4.y, a4.z, a4.w};
            float b[RN];
#pragma unroll
            for (int h = 0; h < RN / 4; h++) {
                float4 b4 = *(const float4*)&Bs[buf][kk][h * 64 + tx * 4];
                b[h * 4 + 0] = b4.x; b[h * 4 + 1] = b4.y;
                b[h * 4 + 2] = b4.z; b[h * 4 + 3] = b4.w;
            }
#pragma unroll
            for (int i = 0; i < 4; i++)
#pragma unroll
                for (int j = 0; j < RN; j++) acc[i][j] += a[i] * b[j];
        }

        if (has) {
            int nb = buf ^ 1;
            As[nb][ak + 0][ar] = la.x; As[nb][ak + 1][ar] = la.y;
            As[nb][ak + 2][ar] = la.z; As[nb][ak + 3][ar] = la.w;
#pragma unroll
            for (int h = 0; h < RN / 4; h++)
                *(float4*)&Bs[nb][bk][bn + h * 4] = lbv[h];
        }
        __syncthreads();
        buf ^= 1;
    }

#pragma unroll
    for (int i = 0; i < 4; i++) {
        int m = m0 + ty * 4 + i;
        float bv = bias ? bias[m] : 0.f;
#pragma unroll
        for (int h = 0; h < RN / 4; h++) {
            float4 v;
            v.x = acc[i][h * 4 + 0] + bv;
            v.y = acc[i][h * 4 + 1] + bv;
            v.z = acc[i][h * 4 + 2] + bv;
            v.w = acc[i][h * 4 + 3] + bv;
            if (relu) {
                v.x = fmaxf(v.x, 0.f); v.y = fmaxf(v.y, 0.f);
                v.z = fmaxf(v.z, 0.f); v.w = fmaxf(v.w, 0.f);
            }
            *(float4*)&C[(long long)m * N + n0 + h * 64 + tx * 4] = v;
        }
    }
}

// ---------------- fallback 64x64 GEMM (any shape; known-good) ----------------
__global__ void gemm64(const float* __restrict__ A, const float* __restrict__ B,
                       float* __restrict__ C, int M, int N, int K,
                       long long sA, long long sB, long long sC,
                       const float* __restrict__ bias, int relu)
{
    A += (long long)blockIdx.z * sA;
    B += (long long)blockIdx.z * sB;
    C += (long long)blockIdx.z * sC;
    __shared__ float As[16][64];
    __shared__ float Bs[16][68];
    int tx = threadIdx.x, ty = threadIdx.y;
    int tid = ty * 16 + tx;
    int m0 = blockIdx.y * 64, n0 = blockIdx.x * 64;
    int mA = tid >> 2, kA = (tid & 3) * 4;
    int kB = tid >> 4, nB = (tid & 15) * 4;
    float acc[4][4];
#pragma unroll
    for (int i = 0; i < 4; i++)
#pragma unroll
        for (int j = 0; j < 4; j++) acc[i][j] = 0.f;

    for (int k0 = 0; k0 < K; k0 += 16) {
#pragma unroll
        for (int i = 0; i < 4; i++) {
            int k = k0 + kA + i;
            As[kA + i][mA] = (m0 + mA < M && k < K) ? A[(long long)(m0 + mA) * K + k] : 0.f;
        }
#pragma unroll
        for (int i = 0; i < 4; i++) {
            int n = n0 + nB + i;
            Bs[kB][nB + i] = (k0 + kB < K && n < N) ? B[(long long)(k0 + kB) * N + n] : 0.f;
        }
        __syncthreads();
#pragma unroll
        for (int kk = 0; kk < 16; kk++) {
            float a[4], b[4];
#pragma unroll
            for (int i = 0; i < 4; i++) a[i] = As[kk][ty * 4 + i];
#pragma unroll
            for (int j = 0; j < 4; j++) b[j] = Bs[kk][tx * 4 + j];
#pragma unroll
            for (int i = 0; i < 4; i++)
#pragma unroll
                for (int j = 0; j < 4; j++) acc[i][j] += a[i] * b[j];
        }
        __syncthreads();
    }
#pragma unroll
    for (int i = 0; i < 4; i++) {
        int m = m0 + ty * 4 + i;
        if (m >= M) continue;
        float bv = bias ? bias[m] : 0.f;
#pragma unroll
        for (int j = 0; j < 4; j++) {
            int n = n0 + tx * 4 + j;
            if (n >= N) continue;
            float v = acc[i][j] + bv;
            if (relu) v = fmaxf(v, 0.f);
            C[(long long)m * N + n] = v;
        }
    }
}

// ---------------- 512->18 offset-head 3x3 conv, channel-split partials ----------------
// grid: (9 hw-tiles, 16 channel chunks of 32, batch 2), block 256.
__global__ void conv18_k(const float* __restrict__ in, long long inB,
                         const float* __restrict__ w, float* __restrict__ part, int C)
{
    const int t = blockIdx.x, cc = blockIdx.y, b = blockIdx.z;
    const int tid = threadIdx.x;
    const int hw = t * 256 + tid;
    const int h = hw / WW, x = hw % WW;
    const int hf = (t * 256) / WW;

    __shared__ float sIn[4][9 * WW];
    __shared__ float sW[4][18 * 9];

    float acc[18];
#pragma unroll
    for (int o = 0; o < 18; o++) acc[o] = 0.f;

    const float* ib = in + (long long)b * inB + (long long)(cc * 32) * HW2;
    const int lr = h - (hf - 1);

    for (int cs = 0; cs < 32; cs += 4) {
        for (int i = tid; i < 4 * 9 * WW; i += 256) {
            int c = i / (9 * WW), r = i % (9 * WW);
            int row = hf - 1 + r / WW, col = r % WW;
            float v = 0.f;
            if (row >= 0 && row < HH) v = ib[(long long)(cs + c) * HW2 + row * WW + col];
            sIn[c][r] = v;
        }
        for (int i = tid; i < 4 * 162; i += 256) {
            int c = i / 162, r = i % 162;
            int o = r / 9, q = r % 9;
            sW[c][r] = w[((long long)o * C + (cc * 32 + cs + c)) * 9 + q];
        }
        __syncthreads();

#pragma unroll
        for (int c = 0; c < 4; c++) {
            float tap[9];
#pragma unroll
            for (int ki = 0; ki < 3; ki++)
#pragma unroll
                for (int kj = 0; kj < 3; kj++) {
                    int xx = x - 1 + kj;
                    float v = 0.f;
                    if (xx >= 0 && xx < WW) v = sIn[c][(lr - 1 + ki) * WW + xx];
                    tap[ki * 3 + kj] = v;
                }
#pragma unroll
            for (int o = 0; o < 18; o++) {
                float s = acc[o];
#pragma unroll
                for (int q = 0; q < 9; q++) s += sW[c][o * 9 + q] * tap[q];
                acc[o] = s;
            }
        }
        __syncthreads();
    }

    float* pp = part + ((long long)cc * 2 + b) * 18 * HW2;
#pragma unroll
    for (int o = 0; o < 18; o++) pp[(long long)o * HW2 + hw] = acc[o];
}

__global__ void reduce18_k(const float* __restrict__ part, float* __restrict__ out)
{
    int idx = blockIdx.x * 256 + threadIdx.x;
    if (idx >= 2 * 18 * HW2) return;
    int b = idx / (18 * HW2);
    int r = idx % (18 * HW2);
    float s = 0.f;
#pragma unroll
    for (int c = 0; c < 16; c++) s += part[((long long)c * 2 + b) * 18 * HW2 + r];
    out[(long long)b * 18 * HW2 + r] = s;
}

// ---------------- deformable (or plain) 3x3 s1 p1 im2col over 48x48 ----------------
// mode 0: write fp32 to colsF; mode 1: write bf16 hi/lo split to colsH/colsL.
__global__ void deform_im2col_k(const float* __restrict__ src, long long srcB,
                                const float* __restrict__ off,
                                float* __restrict__ colsF,
                                u16* __restrict__ colsH, u16* __restrict__ colsL,
                                int C, int mode)
{
    int hw = blockIdx.x * 256 + threadIdx.x;
    if (hw >= HW2) return;
    int bq = blockIdx.y;
    int b = bq / 9, q = bq % 9;
    int ki = q / 3, kj = q % 3;
    int h = hw / WW, w = hw % WW;
    const float* sb = src + (long long)b * srcB;
    long long cbase = (long long)b * C * 9 * HW2;
    int c0 = blockIdx.z * 64;
    int c1 = c0 + 64; if (c1 > C) c1 = C;

    float w00, w01, w10, w11;
    int i00, i01, i10, i11;
    if (off == nullptr) {
        int y = h - 1 + ki, x = w - 1 + kj;
        bool vin = (y >= 0 && y < HH && x >= 0 && x < WW);
        w00 = vin ? 1.f : 0.f; w01 = w10 = w11 = 0.f;
        i00 = vin ? (y * WW + x) : 0; i01 = i10 = i11 = 0;
    } else {
        float py = (float)(h - 1 + ki) + off[((long long)b * 18 + 2 * q) * HW2 + hw];
        float px = (float)(w - 1 + kj) + off[((long long)b * 18 + 2 * q + 1) * HW2 + hw];
        float fy = floorf(py), fx = floorf(px);
        float ay = py - fy, ax = px - fx;
        int y0 = (int)fy, x0 = (int)fx;
        int y1 = y0 + 1, x1 = x0 + 1;
        bool by0 = (y0 >= 0 && y0 < HH), by1 = (y1 >= 0 && y1 < HH);
        bool bx0 = (x0 >= 0 && x0 < WW), bx1 = (x1 >= 0 && x1 < WW);
        int yc0 = min(max(y0, 0), HH - 1), yc1 = min(max(y1, 0), HH - 1);
        int xc0 = min(max(x0, 0), WW - 1), xc1 = min(max(x1, 0), WW - 1);
        w00 = (by0 && bx0) ? (1.f - ay) * (1.f - ax) : 0.f;
        w01 = (by0 && bx1) ? (1.f - ay) * ax : 0.f;
        w10 = (by1 && bx0) ? ay * (1.f - ax) : 0.f;
        w11 = (by1 && bx1) ? ay * ax : 0.f;
        i00 = yc0 * WW + xc0; i01 = yc0 * WW + xc1;
        i10 = yc1 * WW + xc0; i11 = yc1 * WW + xc1;
    }

    for (int c = c0; c < c1; c++) {
        const float* s = sb + (long long)c * HW2;
        float v = w00 * s[i00] + w01 * s[i01] + w10 * s[i10] + w11 * s[i11];
        long long idx = cbase + ((long long)c * 9 + q) * HW2 + hw;
        if (mode == 0) {
            colsF[idx] = v;
        } else {
            u16 hh, ll;
            split16(v, hh, ll);
            colsH[idx] = hh; colsL[idx] = ll;
        }
    }
}

// ---------------- generic strided im2col (5x5 s2 p2 and 3x3 s2 p1) ----------------
__global__ void im2col_g(const float* __restrict__ src, long long srcB,
                         float* __restrict__ cols,
                         int C, int H, int W, int KH, int KW,
                         int stride, int pad, int OH, int OW)
{
    int ohw = blockIdx.x * 256 + threadIdx.x;
    int OHW = OH * OW;
    if (ohw >= OHW) return;
    int row = blockIdx.y;
    int b = blockIdx.z;
    int kk = row % (KH * KW);
    int c = row / (KH * KW);
    int kh = kk / KW, kw = kk % KW;
    int oh = ohw / OW, ow = ohw % OW;
    int ih = oh * stride - pad + kh;
    int iw = ow * stride - pad + kw;
    float v = 0.f;
    if (ih >= 0 && ih < H && iw >= 0 && iw < W)
        v = src[(long long)b * srcB + ((long long)c * H + ih) * W + iw];
    cols[((long long)b * C * KH * KW + row) * OHW + ohw] = v;
}

// ---------------- direct 3x3 s1 p1 conv (tiny s3: 64->1) ----------------
__global__ void conv3x3_direct(const float* __restrict__ in, long long inB,
                               const float* __restrict__ w, float* __restrict__ out,
                               long long outB, int C, int relu)
{
    int hw = blockIdx.x * 256 + threadIdx.x;
    if (hw >= HW2) return;
    int o = blockIdx.y, b = blockIdx.z;
    int h = hw / WW, x = hw % WW;
    const float* ib = in + (long long)b * inB;
    const float* wo = w + (long long)o * C * 9;
    float acc = 0.f;
    for (int c = 0; c < C; c++) {
        const float* ic = ib + (long long)c * HW2;
        const float* wc = wo + c * 9;
#pragma unroll
        for (int kh = 0; kh < 3; kh++) {
            int ih = h + kh - 1;
            if (ih < 0 || ih >= HH) continue;
#pragma unroll
            for (int kw = 0; kw < 3; kw++) {
                int iw = x + kw - 1;
                if (iw < 0 || iw >= WW) continue;
                acc += ic[ih * WW + iw] * wc[kh * 3 + kw];
            }
        }
    }
    if (relu) acc = fmaxf(acc, 0.f);
    out[(long long)b * outB + (long long)o * HW2 + hw] = acc;
}

// ---------------- elementwise kernels ----------------
__global__ void concat_k(const float* __restrict__ a, const float* __restrict__ b_,
                         float* __restrict__ o, long long imgStride)
{
    int idx = blockIdx.x * 256 + threadIdx.x;
    if (idx >= 2 * 512 * HW2) return;
    int bb = idx / (512 * HW2);
    int c = (idx / HW2) % 512;
    int hw = idx % HW2;
    float v = (c < 256) ? a[bb * imgStride + (long long)c * HW2 + hw]
                        : b_[bb * imgStride + (long long)(c - 256) * HW2 + hw];
    o[idx] = v;
}

__global__ void corr_k(const float* __restrict__ Ra, const float* __restrict__ Tb,
                       float* __restrict__ f177)
{
    int idx = blockIdx.x * 256 + threadIdx.x;
    if (idx >= 2 * 49 * HW2) return;
    int b = idx / (49 * HW2);
    int q = (idx / HW2) % 49;
    int hw = idx % HW2;
    int h = hw / WW, w = hw % WW;
    int dy = 2 * ((q / 7) - 3), dx = 2 * ((q % 7) - 3);
    int hh = h + dy, ww = w + dx;
    float s = 0.f;
    if (hh >= 0 && hh < HH && ww >= 0 && ww < WW) {
        const float* a = Ra + (long long)b * (2 * 64 * HW2) + hw;
        const float* bp = Tb + (long long)b * (2 * 64 * HW2) + hh * WW + ww;
        for (int c = 0; c < 64; c++) s += a[c * HW2] * bp[c * HW2];
    }
    f177[((long long)b * 177 + q) * HW2 + hw] = s * (1.f / 64.f);
}

__global__ void pack_k(const float* __restrict__ eA, const float* __restrict__ eB,
                       float* __restrict__ f177)
{
    int idx = blockIdx.x * 256 + threadIdx.x;
    if (idx >= 2 * 64 * HW2) return;
    int b = idx / (64 * HW2);
    int c = (idx / HW2) % 64;
    int hw = idx % HW2;
    f177[((long long)b * 177 + 49 + c) * HW2 + hw] = eA[idx];
    f177[((long long)b * 177 + 113 + c) * HW2 + hw] = eB[idx];
}

__global__ void mean36_k(const float* __restrict__ in, float* __restrict__ fw, int total)
{
    int i = blockIdx.x * 256 + threadIdx.x;
    if (i >= total) return;
    float s = 0.f;
#pragma unroll
    for (int j = 0; j < 36; j++) s += in[i * 36 + j];
    fw[i] = s * (1.f / 36.f);
}

__global__ void mkw_k(const float* __restrict__ fw, const float* __restrict__ Wt,
                      const float* __restrict__ Bi, float* __restrict__ adw,
                      int M, int Kc, int total)
{
    int idx = blockIdx.x * 256 + threadIdx.x;
    if (idx >= total) return;
    int b = idx / (M * Kc);
    int r = idx - b * M * Kc;
    int o = r / Kc;
    adw[idx] = fw[b * M + o] * Wt[r] + Bi[r];
}

__global__ void final_k(const float* __restrict__ d0, const float* __restrict__ d1,
                        const float* __restrict__ s0p, const float* __restrict__ s1p,
                        float* __restrict__ out, int total)
{
    int idx = blockIdx.x * 256 + threadIdx.x;
    if (idx >= total) return;
    int b = idx / (256 * HW2);
    int hw = idx % HW2;
    float s0 = s0p[b * HW2 + hw];
    float s1 = s1p[b * HW2 + hw];
    const float eps = 1e-8f;
    float wx = (s0 * s1) / (fmaxf(fabsf(s0), eps) * fmaxf(fabsf(s1), eps));
    float wy = (s1 * s1) / (fmaxf(fabsf(s1), eps) * fmaxf(fabsf(s1), eps));
    float mx = fmaxf(wx, wy);
    float e0 = expf(wx - mx), e1 = expf(wy - mx);
    float inv = 1.f / (e0 + e1);
    out[idx] = d0[idx] * (e0 * inv) + d1[idx] * (e1 * inv);
}

// ---------------- host orchestration ----------------
extern "C" void kernel_launch(void* const* d_in, const int* in_sizes, int n_in,
                              void* d_out, int out_size)
{
    (void)in_sizes; (void)n_in; (void)out_size;
    const float* R0     = (const float*)d_in[0];
    const float* T0     = (const float*)d_in[1];
    const float* inp    = (const float*)d_in[2];
    const float* enc0_w = (const float*)d_in[3];
    const float* enc0_b = (const float*)d_in[4];
    const float* enc1_w = (const float*)d_in[5];
    const float* enc1_b = (const float*)d_in[6];
    const float* offw[4] = {(const float*)d_in[7], (const float*)d_in[8],
                            (const float*)d_in[9], (const float*)d_in[10]};
    const float* defw[3] = {(const float*)d_in[11], (const float*)d_in[12],
                            (const float*)d_in[13]};
    const float* w0a = (const float*)d_in[14];
    const float* w0b = (const float*)d_in[15];
    const float* w0c = (const float*)d_in[16];
    const float* w1a = (const float*)d_in[17];
    const float* w1b = (const float*)d_in[18];
    const float* w1c = (const float*)d_in[19];
    const float* wx_w  = (const float*)d_in[20];
    const float* wx_b  = (const float*)d_in[21];
    const float* wxf_w = (const float*)d_in[22];
    const float* wxf_b = (const float*)d_in[23];
    const float* s1w = (const float*)d_in[24];
    const float* s2w = (const float*)d_in[25];
    const float* s3w = (const float*)d_in[26];
    float* out = (float*)d_out;

    float *xenc, *yenc, *f512a, *f512b, *cols, *off, *cpart, *f177, *f177b;
    float *wb1, *wb2, *wb3, *fw, *adw, *def0, *def1, *s1o, *s2o, *swa, *swb;
    u16 *colsh, *colsl, *awh, *awl;
    cudaGetSymbolAddress((void**)&xenc,  g_xenc);
    cudaGetSymbolAddress((void**)&yenc,  g_yenc);
    cudaGetSymbolAddress((void**)&f512a, g_f512a);
    cudaGetSymbolAddress((void**)&f512b, g_f512b);
    cudaGetSymbolAddress((void**)&cols,  g_cols);
    cudaGetSymbolAddress((void**)&colsh, g_colsh);
    cudaGetSymbolAddress((void**)&colsl, g_colsl);
    cudaGetSymbolAddress((void**)&awh,   g_awh);
    cudaGetSymbolAddress((void**)&awl,   g_awl);
    cudaGetSymbolAddress((void**)&off,   g_offb);
    cudaGetSymbolAddress((void**)&cpart, g_cpart);
    cudaGetSymbolAddress((void**)&f177,  g_f177);
    cudaGetSymbolAddress((void**)&f177b, g_f177b);
    cudaGetSymbolAddress((void**)&wb1,   g_wb1);
    cudaGetSymbolAddress((void**)&wb2,   g_wb2);
    cudaGetSymbolAddress((void**)&wb3,   g_wb3);
    cudaGetSymbolAddress((void**)&fw,    g_fwb);
    cudaGetSymbolAddress((void**)&adw,   g_adw);
    cudaGetSymbolAddress((void**)&def0,  g_def0);
    cudaGetSymbolAddress((void**)&def1,  g_def1);
    cudaGetSymbolAddress((void**)&s1o,   g_s1o);
    cudaGetSymbolAddress((void**)&s2o,   g_s2o);
    cudaGetSymbolAddress((void**)&swa,   g_swa);
    cudaGetSymbolAddress((void**)&swb,   g_swb);

    const long long imgStride = 2LL * 256 * HW2;

    // tensor GEMM: pre-split A, bf16 cols as B
    auto GEMMT = [&](const float* A, int Aelems, float* C, int M, int N, int K,
                     long long sA, long long sB, long long sC, int relu) {
        convw_k<<<(Aelems + 255) / 256, 256>>>(A, awh, awl, Aelems);
        gemm_bf3b<<<dim3(N / 64, M / 128, 2), 256>>>(awh, awl, colsh, colsl,
                                                     C, M, N, K, sA, sB, sC, relu);
    };
    // fp32 aligned GEMM (M%64==0, K%16==0, N%64==0)
    auto GEMMA = [&](const float* A, const float* Bm, float* C, int M, int N, int K,
                     long long sA, long long sB, long long sC,
                     const float* bias, int relu) {
        gemm_al<4><<<dim3(N / 64, M / 64, 2), 256>>>(A, Bm, C, M, N, K, sA, sB, sC, bias, relu);
    };
    // fallback for odd shapes
    auto GEMMF = [&](const float* A, const float* Bm, float* C, int M, int N, int K,
                     long long sA, long long sB, long long sC,
                     const float* bias, int relu) {
        dim3 g((N + 63) / 64, (M + 63) / 64, 2);
        gemm64<<<g, dim3(16, 16)>>>(A, Bm, C, M, N, K, sA, sB, sC, bias, relu);
    };
    auto DIM2COL = [&](const float* src, long long sB, const float* offp, int C, int mode) {
        dim3 g((HW2 + 255) / 256, 18, (C + 63) / 64);
        deform_im2col_k<<<g, 256>>>(src, sB, offp, cols, colsh, colsl, C, mode);
    };
    auto IM2COL = [&](const float* src, long long sB, int C, int H, int W,
                      int KH, int KW, int st, int pad, int OH, int OW) {
        dim3 g((OH * OW + 255) / 256, C * KH * KW, 2);
        im2col_g<<<g, 256>>>(src, sB, cols, C, H, W, KH, KW, st, pad, OH, OW);
    };
    auto CONV18 = [&](const float* in, long long inB, const float* w, float* o) {
        conv18_k<<<dim3(9, 16, 2), 256>>>(in, inB, w, cpart, 512);
        reduce18_k<<<(2 * 18 * HW2 + 255) / 256, 256>>>(cpart, o);
    };
    auto WBRANCH = [&](const float* feat, const float* wa, const float* wb,
                       const float* wc, int Mc) {
        IM2COL(feat, 177LL * HW2, 177, 48, 48, 5, 5, 2, 2, 24, 24);
        GEMMF(wa, cols, wb1, 64, 576, 4425, 0, 4425LL * 576, 64LL * 576, nullptr, 1);
        IM2COL(wb1, 64LL * 576, 64, 24, 24, 5, 5, 2, 2, 12, 12);
        GEMMF(wb, cols, wb2, 64, 144, 1600, 0, 1600LL * 144, 64LL * 144, nullptr, 1);
        IM2COL(wb2, 64LL * 144, 64, 12, 12, 3, 3, 2, 1, 6, 6);
        GEMMF(wc, cols, wb3, Mc, 36, 576, 0, 576LL * 36, (long long)Mc * 36, nullptr, 0);
        int tot = 2 * Mc;
        mean36_k<<<(tot + 255) / 256, 256>>>(wb3, fw, tot);
    };

    // ---- encoders (1x1 conv == GEMM on NCHW directly) ----
    GEMMA(enc0_w, inp,             xenc, 64, HW2, 256, 0, imgStride, 64LL * HW2, enc0_b, 0);
    GEMMA(enc1_w, inp + 256 * HW2, yenc, 64, HW2, 256, 0, imgStride, 64LL * HW2, enc1_b, 0);

    auto BRANCH = [&](int br, float* gdef, float* gsw) {
        const float* imgA = (br == 0) ? inp : inp + 256 * HW2;
        const float* imgB = inp + 256 * HW2;   // y for both branches

        // ---- stsn_offset ----
        {
            int tot = 2 * 512 * HW2;
            concat_k<<<(tot + 255) / 256, 256>>>(imgA, imgB, f512a, imgStride);
        }
        float* cur = f512a; float* oth = f512b;
        for (int i = 0; i < 3; i++) {
            CONV18(cur, 512LL * HW2, offw[i], off);
            DIM2COL(cur, 512LL * HW2, off, 512, 1);
            GEMMT(defw[i], 512 * 4608, oth, 512, HW2, 4608,
                  0, 4608LL * HW2, 512LL * HW2, 0);
            float* t = cur; cur = oth; oth = t;
        }
        CONV18(cur, 512LL * HW2, offw[3], off);  // final offsets -> g_offb

        // ---- astsn_weight ----
        const float* Ra = R0 + (br == 0 ? 0 : 64 * HW2);   // R_pre / R_cur
        const float* Tb = T0 + 64 * HW2;                    // T_cur
        const float* eA = (br == 0) ? xenc : yenc;
        const float* eB = yenc;
        {
            int tot = 2 * 49 * HW2;
            corr_k<<<(tot + 255) / 256, 256>>>(Ra, Tb, f177);
        }
        {
            int tot = 2 * 64 * HW2;
            pack_k<<<(tot + 255) / 256, 256>>>(eA, eB, f177);
        }
        WBRANCH(f177, w0a, w0b, w0c, 177);
        {
            int tot = 2 * 177 * 1593;
            mkw_k<<<(tot + 255) / 256, 256>>>(fw, wx_w, wx_b, adw, 177, 1593, tot);
        }
        DIM2COL(f177, 177LL * HW2, nullptr, 177, 0);
        GEMMF(adw, cols, f177b, 177, HW2, 1593, 177LL * 1593, 1593LL * HW2, 177LL * HW2,
              nullptr, 1);
        WBRANCH(f177b, w1a, w1b, w1c, 256);
        {
            int tot = 2 * 256 * 2304;
            mkw_k<<<(tot + 255) / 256, 256>>>(fw, wxf_w, wxf_b, adw, 256, 2304, tot);
        }

        // ---- adaptive deform conv (A per-batch) ----
        DIM2COL(imgA, imgStride, off, 256, 1);
        GEMMT(adw, 2 * 256 * 2304, gdef, 256, HW2, 2304,
              256LL * 2304, 2304LL * HW2, 256LL * HW2, 0);

        // ---- s_net ----
        DIM2COL(gdef, 256LL * HW2, nullptr, 256, 1);
        GEMMT(s1w, 128 * 2304, s1o, 128, HW2, 2304,
              0, 2304LL * HW2, 128LL * HW2, 1);
        DIM2COL(s1o, 128LL * HW2, nullptr, 128, 0);
        GEMMA(s2w, cols, s2o, 64, HW2, 1152, 0, 1152LL * HW2, 64LL * HW2, nullptr, 1);
        conv3x3_direct<<<dim3(9, 1, 2), 256>>>(s2o, 64LL * HW2, s3w, gsw,
                                               (long long)HW2, 64, 1);
    };

    BRANCH(0, def0, swa);
    BRANCH(1, def1, swb);

    {
        int tot = 2 * 256 * HW2;
        final_k<<<(tot + 255) / 256, 256>>>(def0, def1, swa, swb, out, tot);
    }
}

// round 7
// speedup vs baseline: 2.0376x; 1.0167x over previous
#include <cuda_runtime.h>
#include <cuda_bf16.h>
#include <math.h>

#define HW2 2304
#define HH 48
#define WW 48

typedef unsigned int u32;
typedef unsigned short u16;

// ---------------- device scratch (no allocations allowed) ----------------
__device__ float g_xenc  [2*64 *HW2];
__device__ float g_yenc  [2*64 *HW2];
__device__ float g_f512a [2*512*HW2];
__device__ float g_f512b [2*512*HW2];
__device__ float g_cols  [2*1600*HW2];   // fp32 cols (small GEMM paths)
__device__ u16   g_colsh [2*4608*HW2];   // bf16-hi cols for tensor GEMMs
__device__ u16   g_colsl [2*4608*HW2];   // bf16-lo cols
__device__ u16   g_awh   [2*256*2304];   // per-branch split A (adw)
__device__ u16   g_awl   [2*256*2304];
__device__ u16   g_dwh   [3*512*4608];   // pre-split deform weights (hoisted)
__device__ u16   g_dwl   [3*512*4608];
__device__ u16   g_s1h   [128*2304];     // pre-split s1 weights (hoisted)
__device__ u16   g_s1l   [128*2304];
__device__ float g_offb  [2*18 *HW2];
__device__ float g_cpart [16*2*18*HW2];  // conv18 channel-split partials
__device__ float g_f177  [2*177*HW2];
__device__ float g_f177b [2*177*HW2];
__device__ float g_wb1   [2*64*576];
__device__ float g_wb2   [2*64*144];
__device__ float g_wb3   [2*256*36];
__device__ float g_fwb   [2*256];
__device__ float g_adw   [2*256*HW2];
__device__ float g_def0  [2*256*HW2];
__device__ float g_def1  [2*256*HW2];
__device__ float g_s1o   [2*128*HW2];
__device__ float g_s2o   [2*64*HW2];
__device__ float g_swa   [2*HW2];
__device__ float g_swb   [2*HW2];

// ---------------- helpers ----------------
__device__ __forceinline__ void split16(float x, u16& h, u16& l)
{
    __nv_bfloat16 xh = __float2bfloat16(x);
    h = __bfloat16_as_ushort(xh);
    l = __bfloat16_as_ushort(__float2bfloat16(x - __bfloat162float(xh)));
}

// weight pre-split: fp32[n] -> bf16 hi/lo
__global__ void convw_k(const float* __restrict__ src, u16* __restrict__ h,
                        u16* __restrict__ l, int n)
{
    int i = blockIdx.x * 256 + threadIdx.x;
    if (i >= n) return;
    u16 hh, ll;
    split16(src[i], hh, ll);
    h[i] = hh; l[i] = ll;
}

#define MMA16816(c, a, b0v, b1v) \
    asm volatile("mma.sync.aligned.m16n8k16.row.col.f32.bf16.bf16.f32 " \
        "{%0,%1,%2,%3},{%4,%5,%6,%7},{%8,%9},{%0,%1,%2,%3};" \
        : "+f"((c)[0]), "+f"((c)[1]), "+f"((c)[2]), "+f"((c)[3]) \
        : "r"((a)[0]), "r"((a)[1]), "r"((a)[2]), "r"((a)[3]), \
          "r"(b0v), "r"(b1v))

// ---------------- bf16x3 split tensor-core GEMM, pre-split inputs ----------------
// C[M,N] = A[M,K]*B[K,N]; A,B given as separate bf16 hi/lo arrays.
// Requires M%128==0, N%64==0, K%16==0. Tile 128x64, KT=16, 8 warps (4m x 2n).
__global__ __launch_bounds__(256)
void gemm_bf3b(const u16* __restrict__ Ah, const u16* __restrict__ Al,
               const u16* __restrict__ Bh, const u16* __restrict__ Bl,
               float* __restrict__ C, int M, int N, int K,
               long long sA, long long sB, long long sC, int relu)
{
    Ah += (long long)blockIdx.z * sA;
    Al += (long long)blockIdx.z * sA;
    Bh += (long long)blockIdx.z * sB;
    Bl += (long long)blockIdx.z * sB;
    C  += (long long)blockIdx.z * sC;

    __shared__ u32 sAh[2][128][13];
    __shared__ u32 sAl[2][128][13];
    __shared__ u32 sBh[2][64][13];
    __shared__ u32 sBl[2][64][13];

    const int tid = threadIdx.x;
    const int lane = tid & 31, warp = tid >> 5;
    const int wm = warp >> 1, wn = warp & 1;
    const int m0 = blockIdx.y * 128, n0 = blockIdx.x * 64;

    // A staging: row = tid>>1 (0..127), half = tid&1 -> k [half*8, half*8+8)
    const int arow = tid >> 1, ahalf = tid & 1;
    const u16* ApH = Ah + (long long)(m0 + arow) * K + ahalf * 8;
    const u16* ApL = Al + (long long)(m0 + arow) * K + ahalf * 8;

    // B staging: warp = k-pair (rows 2w,2w+1), lane = n-pair (coalesced 128B/warp/row)
    const int bw = warp;                 // k-pair 0..7
    const int bn = lane * 2;             // n offset 0..62
    const u16* BpH = Bh + n0 + bn;
    const u16* BpL = Bl + n0 + bn;

    float acc[2][4][4];
#pragma unroll
    for (int mt = 0; mt < 2; mt++)
#pragma unroll
        for (int nt = 0; nt < 4; nt++)
#pragma unroll
            for (int i = 0; i < 4; i++) acc[mt][nt][i] = 0.f;

    uint4 lah, lal;
    u32 lbh0, lbh1, lbl0, lbl1;

    // prologue loads (k0 = 0)
    lah = *(const uint4*)ApH;
    lal = *(const uint4*)ApL;
    lbh0 = *(const u32*)(BpH + (long long)(2 * bw) * N);
    lbh1 = *(const u32*)(BpH + (long long)(2 * bw + 1) * N);
    lbl0 = *(const u32*)(BpL + (long long)(2 * bw) * N);
    lbl1 = *(const u32*)(BpL + (long long)(2 * bw + 1) * N);
    // store buf 0
    {
        sAh[0][arow][ahalf*4+0] = lah.x; sAh[0][arow][ahalf*4+1] = lah.y;
        sAh[0][arow][ahalf*4+2] = lah.z; sAh[0][arow][ahalf*4+3] = lah.w;
        sAl[0][arow][ahalf*4+0] = lal.x; sAl[0][arow][ahalf*4+1] = lal.y;
        sAl[0][arow][ahalf*4+2] = lal.z; sAl[0][arow][ahalf*4+3] = lal.w;
        sBh[0][bn  ][bw] = __byte_perm(lbh0, lbh1, 0x5410);
        sBh[0][bn+1][bw] = __byte_perm(lbh0, lbh1, 0x7632);
        sBl[0][bn  ][bw] = __byte_perm(lbl0, lbl1, 0x5410);
        sBl[0][bn+1][bw] = __byte_perm(lbl0, lbl1, 0x7632);
    }
    __syncthreads();

    const int ar = lane >> 2, ac = lane & 3;
    int buf = 0;
    for (int k0 = 0; k0 < K; k0 += 16) {
        const bool has = (k0 + 16) < K;
        if (has) {
            lah = *(const uint4*)(ApH + k0 + 16);
            lal = *(const uint4*)(ApL + k0 + 16);
            const long long r0 = (long long)(k0 + 16 + 2 * bw) * N;
            lbh0 = *(const u32*)(BpH + r0);
            lbh1 = *(const u32*)(BpH + r0 + N);
            lbl0 = *(const u32*)(BpL + r0);
            lbl1 = *(const u32*)(BpL + r0 + N);
        }

        // fragment loads
        u32 ah[2][4], al[2][4];
#pragma unroll
        for (int mt = 0; mt < 2; mt++) {
            int r = wm * 32 + mt * 16 + ar;
            ah[mt][0] = sAh[buf][r][ac];         al[mt][0] = sAl[buf][r][ac];
            ah[mt][1] = sAh[buf][r + 8][ac];     al[mt][1] = sAl[buf][r + 8][ac];
            ah[mt][2] = sAh[buf][r][ac + 4];     al[mt][2] = sAl[buf][r][ac + 4];
            ah[mt][3] = sAh[buf][r + 8][ac + 4]; al[mt][3] = sAl[buf][r + 8][ac + 4];
        }
#pragma unroll
        for (int nt = 0; nt < 4; nt++) {
            int nr = wn * 32 + nt * 8 + ar;
            u32 bh0 = sBh[buf][nr][ac], bh1 = sBh[buf][nr][ac + 4];
            u32 bl0 = sBl[buf][nr][ac], bl1 = sBl[buf][nr][ac + 4];
#pragma unroll
            for (int mt = 0; mt < 2; mt++) {
                MMA16816(acc[mt][nt], ah[mt], bh0, bh1);   // hi*hi
                MMA16816(acc[mt][nt], ah[mt], bl0, bl1);   // hi*lo
                MMA16816(acc[mt][nt], al[mt], bh0, bh1);   // lo*hi
            }
        }

        if (has) {
            int nb = buf ^ 1;
            sAh[nb][arow][ahalf*4+0] = lah.x; sAh[nb][arow][ahalf*4+1] = lah.y;
            sAh[nb][arow][ahalf*4+2] = lah.z; sAh[nb][arow][ahalf*4+3] = lah.w;
            sAl[nb][arow][ahalf*4+0] = lal.x; sAl[nb][arow][ahalf*4+1] = lal.y;
            sAl[nb][arow][ahalf*4+2] = lal.z; sAl[nb][arow][ahalf*4+3] = lal.w;
            sBh[nb][bn  ][bw] = __byte_perm(lbh0, lbh1, 0x5410);
            sBh[nb][bn+1][bw] = __byte_perm(lbh0, lbh1, 0x7632);
            sBl[nb][bn  ][bw] = __byte_perm(lbl0, lbl1, 0x5410);
            sBl[nb][bn+1][bw] = __byte_perm(lbl0, lbl1, 0x7632);
        }
        __syncthreads();
        buf ^= 1;
    }

    // epilogue
#pragma unroll
    for (int mt = 0; mt < 2; mt++) {
        int r = m0 + wm * 32 + mt * 16 + ar;
#pragma unroll
        for (int nt = 0; nt < 4; nt++) {
            int c = n0 + wn * 32 + nt * 8 + ac * 2;
            float2 v0 = make_float2(acc[mt][nt][0], acc[mt][nt][1]);
            float2 v1 = make_float2(acc[mt][nt][2], acc[mt][nt][3]);
            if (relu) {
                v0.x = fmaxf(v0.x, 0.f); v0.y = fmaxf(v0.y, 0.f);
                v1.x = fmaxf(v1.x, 0.f); v1.y = fmaxf(v1.y, 0.f);
            }
            *(float2*)&C[(long long)r * N + c] = v0;
            *(float2*)&C[(long long)(r + 8) * N + c] = v1;
        }
    }
}

// ---------------- aligned fast fp32 GEMM: 64x64 tile, KT=16, double buffered ----------------
template<int RN>
__global__ __launch_bounds__(256)
void gemm_al(const float* __restrict__ A, const float* __restrict__ B,
             float* __restrict__ C, int M, int N, int K,
             long long sA, long long sB, long long sC,
             const float* __restrict__ bias, int relu)
{
    constexpr int TN = 16 * RN;
    A += (long long)blockIdx.z * sA;
    B += (long long)blockIdx.z * sB;
    C += (long long)blockIdx.z * sC;

    __shared__ float As[2][16][68];
    __shared__ float Bs[2][16][TN];

    const int tid = threadIdx.x;
    const int tx = tid & 15, ty = tid >> 4;
    const int m0 = blockIdx.y * 64, n0 = blockIdx.x * TN;

    const int ar = tid >> 2;
    const int ak = (tid & 3) * 4;
    const int bk = tid >> 4;
    const int bn = (tid & 15) * RN;

    const float* Ap = A + (long long)(m0 + ar) * K + ak;
    const float* Bp = B + (long long)bk * N + n0 + bn;

    float acc[4][RN];
#pragma unroll
    for (int i = 0; i < 4; i++)
#pragma unroll
        for (int j = 0; j < RN; j++) acc[i][j] = 0.f;

    {
        float4 av = *(const float4*)Ap;
        As[0][ak + 0][ar] = av.x; As[0][ak + 1][ar] = av.y;
        As[0][ak + 2][ar] = av.z; As[0][ak + 3][ar] = av.w;
#pragma unroll
        for (int h = 0; h < RN / 4; h++)
            *(float4*)&Bs[0][bk][bn + h * 4] = *(const float4*)(Bp + h * 4);
    }
    __syncthreads();

    int buf = 0;
    for (int k0 = 0; k0 < K; k0 += 16) {
        const bool has = (k0 + 16) < K;
        float4 la;
        float4 lbv[RN / 4];
        if (has) {
            la = *(const float4*)(Ap + k0 + 16);
#pragma unroll
            for (int h = 0; h < RN / 4; h++)
                lbv[h] = *(const float4*)(Bp + (long long)(k0 + 16) * N + h * 4);
        }

#pragma unroll
        for (int kk = 0; kk < 16; kk++) {
            float4 a4 = *(const float4*)&As[buf][kk][ty * 4];
            float a[4] = {a4.x, a4.y, a4.z, a4.w};
            float b[RN];
#pragma unroll
            for (int h = 0; h < RN / 4; h++) {
                float4 b4 = *(const float4*)&Bs[buf][kk][h * 64 + tx * 4];
                b[h * 4 + 0] = b4.x; b[h * 4 + 1] = b4.y;
                b[h * 4 + 2] = b4.z; b[h * 4 + 3] = b4.w;
            }
#pragma unroll
            for (int i = 0; i < 4; i++)
#pragma unroll
                for (int j = 0; j < RN; j++) acc[i][j] += a[i] * b[j];
        }

        if (has) {
            int nb = buf ^ 1;
            As[nb][ak + 0][ar] = la.x; As[nb][ak + 1][ar] = la.y;
            As[nb][ak + 2][ar] = la.z; As[nb][ak + 3][ar] = la.w;
#pragma unroll
            for (int h = 0; h < RN / 4; h++)
                *(float4*)&Bs[nb][bk][bn + h * 4] = lbv[h];
        }
        __syncthreads();
        buf ^= 1;
    }

#pragma unroll
    for (int i = 0; i < 4; i++) {
        int m = m0 + ty * 4 + i;
        float bv = bias ? bias[m] : 0.f;
#pragma unroll
        for (int h = 0; h < RN / 4; h++) {
            float4 v;
            v.x = acc[i][h * 4 + 0] + bv;
            v.y = acc[i][h * 4 + 1] + bv;
            v.z = acc[i][h * 4 + 2] + bv;
            v.w = acc[i][h * 4 + 3] + bv;
            if (relu) {
                v.x = fmaxf(v.x, 0.f); v.y = fmaxf(v.y, 0.f);
                v.z = fmaxf(v.z, 0.f); v.w = fmaxf(v.w, 0.f);
            }
            *(float4*)&C[(long long)m * N + n0 + h * 64 + tx * 4] = v;
        }
    }
}

// ---------------- fallback 64x64 GEMM (any shape; known-good) ----------------
__global__ void gemm64(const float* __restrict__ A, const float* __restrict__ B,
                       float* __restrict__ C, int M, int N, int K,
                       long long sA, long long sB, long long sC,
                       const float* __restrict__ bias, int relu)
{
    A += (long long)blockIdx.z * sA;
    B += (long long)blockIdx.z * sB;
    C += (long long)blockIdx.z * sC;
    __shared__ float As[16][64];
    __shared__ float Bs[16][68];
    int tx = threadIdx.x, ty = threadIdx.y;
    int tid = ty * 16 + tx;
    int m0 = blockIdx.y * 64, n0 = blockIdx.x * 64;
    int mA = tid >> 2, kA = (tid & 3) * 4;
    int kB = tid >> 4, nB = (tid & 15) * 4;
    float acc[4][4];
#pragma unroll
    for (int i = 0; i < 4; i++)
#pragma unroll
        for (int j = 0; j < 4; j++) acc[i][j] = 0.f;

    for (int k0 = 0; k0 < K; k0 += 16) {
#pragma unroll
        for (int i = 0; i < 4; i++) {
            int k = k0 + kA + i;
            As[kA + i][mA] = (m0 + mA < M && k < K) ? A[(long long)(m0 + mA) * K + k] : 0.f;
        }
#pragma unroll
        for (int i = 0; i < 4; i++) {
            int n = n0 + nB + i;
            Bs[kB][nB + i] = (k0 + kB < K && n < N) ? B[(long long)(k0 + kB) * N + n] : 0.f;
        }
        __syncthreads();
#pragma unroll
        for (int kk = 0; kk < 16; kk++) {
            float a[4], b[4];
#pragma unroll
            for (int i = 0; i < 4; i++) a[i] = As[kk][ty * 4 + i];
#pragma unroll
            for (int j = 0; j < 4; j++) b[j] = Bs[kk][tx * 4 + j];
#pragma unroll
            for (int i = 0; i < 4; i++)
#pragma unroll
                for (int j = 0; j < 4; j++) acc[i][j] += a[i] * b[j];
        }
        __syncthreads();
    }
#pragma unroll
    for (int i = 0; i < 4; i++) {
        int m = m0 + ty * 4 + i;
        if (m >= M) continue;
        float bv = bias ? bias[m] : 0.f;
#pragma unroll
        for (int j = 0; j < 4; j++) {
            int n = n0 + tx * 4 + j;
            if (n >= N) continue;
            float v = acc[i][j] + bv;
            if (relu) v = fmaxf(v, 0.f);
            C[(long long)m * N + n] = v;
        }
    }
}

// ---------------- 512->18 offset-head 3x3 conv, channel-split partials ----------------
// grid: (9 hw-tiles, 16 channel chunks of 32, batch 2), block 256.
__global__ void conv18_k(const float* __restrict__ in, long long inB,
                         const float* __restrict__ w, float* __restrict__ part, int C)
{
    const int t = blockIdx.x, cc = blockIdx.y, b = blockIdx.z;
    const int tid = threadIdx.x;
    const int hw = t * 256 + tid;
    const int h = hw / WW, x = hw % WW;
    const int hf = (t * 256) / WW;

    __shared__ float sIn[4][9 * WW];
    __shared__ float sW[4][18 * 9];

    float acc[18];
#pragma unroll
    for (int o = 0; o < 18; o++) acc[o] = 0.f;

    const float* ib = in + (long long)b * inB + (long long)(cc * 32) * HW2;
    const int lr = h - (hf - 1);

    for (int cs = 0; cs < 32; cs += 4) {
        for (int i = tid; i < 4 * 9 * WW; i += 256) {
            int c = i / (9 * WW), r = i % (9 * WW);
            int row = hf - 1 + r / WW, col = r % WW;
            float v = 0.f;
            if (row >= 0 && row < HH) v = ib[(long long)(cs + c) * HW2 + row * WW + col];
            sIn[c][r] = v;
        }
        for (int i = tid; i < 4 * 162; i += 256) {
            int c = i / 162, r = i % 162;
            int o = r / 9, q = r % 9;
            sW[c][r] = w[((long long)o * C + (cc * 32 + cs + c)) * 9 + q];
        }
        __syncthreads();

#pragma unroll
        for (int c = 0; c < 4; c++) {
            float tap[9];
#pragma unroll
            for (int ki = 0; ki < 3; ki++)
#pragma unroll
                for (int kj = 0; kj < 3; kj++) {
                    int xx = x - 1 + kj;
                    float v = 0.f;
                    if (xx >= 0 && xx < WW) v = sIn[c][(lr - 1 + ki) * WW + xx];
                    tap[ki * 3 + kj] = v;
                }
#pragma unroll
            for (int o = 0; o < 18; o++) {
                float s = acc[o];
#pragma unroll
                for (int q = 0; q < 9; q++) s += sW[c][o * 9 + q] * tap[q];
                acc[o] = s;
            }
        }
        __syncthreads();
    }

    float* pp = part + ((long long)cc * 2 + b) * 18 * HW2;
#pragma unroll
    for (int o = 0; o < 18; o++) pp[(long long)o * HW2 + hw] = acc[o];
}

__global__ void reduce18_k(const float* __restrict__ part, float* __restrict__ out)
{
    int idx = blockIdx.x * 256 + threadIdx.x;
    if (idx >= 2 * 18 * HW2) return;
    int b = idx / (18 * HW2);
    int r = idx % (18 * HW2);
    float s = 0.f;
#pragma unroll
    for (int c = 0; c < 16; c++) s += part[((long long)c * 2 + b) * 18 * HW2 + r];
    out[(long long)b * 18 * HW2 + r] = s;
}

// ---------------- deformable (or plain) 3x3 s1 p1 im2col over 48x48 ----------------
// mode 0: write fp32 to colsF; mode 1: write bf16 hi/lo split to colsH/colsL.
__global__ void deform_im2col_k(const float* __restrict__ src, long long srcB,
                                const float* __restrict__ off,
                                float* __restrict__ colsF,
                                u16* __restrict__ colsH, u16* __restrict__ colsL,
                                int C, int mode)
{
    int hw = blockIdx.x * 256 + threadIdx.x;
    if (hw >= HW2) return;
    int bq = blockIdx.y;
    int b = bq / 9, q = bq % 9;
    int ki = q / 3, kj = q % 3;
    int h = hw / WW, w = hw % WW;
    const float* sb = src + (long long)b * srcB;
    long long cbase = (long long)b * C * 9 * HW2;
    int c0 = blockIdx.z * 64;
    int c1 = c0 + 64; if (c1 > C) c1 = C;

    float w00, w01, w10, w11;
    int i00, i01, i10, i11;
    if (off == nullptr) {
        int y = h - 1 + ki, x = w - 1 + kj;
        bool vin = (y >= 0 && y < HH && x >= 0 && x < WW);
        w00 = vin ? 1.f : 0.f; w01 = w10 = w11 = 0.f;
        i00 = vin ? (y * WW + x) : 0; i01 = i10 = i11 = 0;
    } else {
        float py = (float)(h - 1 + ki) + off[((long long)b * 18 + 2 * q) * HW2 + hw];
        float px = (float)(w - 1 + kj) + off[((long long)b * 18 + 2 * q + 1) * HW2 + hw];
        float fy = floorf(py), fx = floorf(px);
        float ay = py - fy, ax = px - fx;
        int y0 = (int)fy, x0 = (int)fx;
        int y1 = y0 + 1, x1 = x0 + 1;
        bool by0 = (y0 >= 0 && y0 < HH), by1 = (y1 >= 0 && y1 < HH);
        bool bx0 = (x0 >= 0 && x0 < WW), bx1 = (x1 >= 0 && x1 < WW);
        int yc0 = min(max(y0, 0), HH - 1), yc1 = min(max(y1, 0), HH - 1);
        int xc0 = min(max(x0, 0), WW - 1), xc1 = min(max(x1, 0), WW - 1);
        w00 = (by0 && bx0) ? (1.f - ay) * (1.f - ax) : 0.f;
        w01 = (by0 && bx1) ? (1.f - ay) * ax : 0.f;
        w10 = (by1 && bx0) ? ay * (1.f - ax) : 0.f;
        w11 = (by1 && bx1) ? ay * ax : 0.f;
        i00 = yc0 * WW + xc0; i01 = yc0 * WW + xc1;
        i10 = yc1 * WW + xc0; i11 = yc1 * WW + xc1;
    }

    for (int c = c0; c < c1; c++) {
        const float* s = sb + (long long)c * HW2;
        float v = w00 * s[i00] + w01 * s[i01] + w10 * s[i10] + w11 * s[i11];
        long long idx = cbase + ((long long)c * 9 + q) * HW2 + hw;
        if (mode == 0) {
            colsF[idx] = v;
        } else {
            u16 hh, ll;
            split16(v, hh, ll);
            colsH[idx] = hh; colsL[idx] = ll;
        }
    }
}

// ---------------- generic strided im2col (5x5 s2 p2 and 3x3 s2 p1) ----------------
__global__ void im2col_g(const float* __restrict__ src, long long srcB,
                         float* __restrict__ cols,
                         int C, int H, int W, int KH, int KW,
                         int stride, int pad, int OH, int OW)
{
    int ohw = blockIdx.x * 256 + threadIdx.x;
    int OHW = OH * OW;
    if (ohw >= OHW) return;
    int row = blockIdx.y;
    int b = blockIdx.z;
    int kk = row % (KH * KW);
    int c = row / (KH * KW);
    int kh = kk / KW, kw = kk % KW;
    int oh = ohw / OW, ow = ohw % OW;
    int ih = oh * stride - pad + kh;
    int iw = ow * stride - pad + kw;
    float v = 0.f;
    if (ih >= 0 && ih < H && iw >= 0 && iw < W)
        v = src[(long long)b * srcB + ((long long)c * H + ih) * W + iw];
    cols[((long long)b * C * KH * KW + row) * OHW + ohw] = v;
}

// ---------------- direct 3x3 s1 p1 conv (tiny s3: 64->1) ----------------
__global__ void conv3x3_direct(const float* __restrict__ in, long long inB,
                               const float* __restrict__ w, float* __restrict__ out,
                               long long outB, int C, int relu)
{
    int hw = blockIdx.x * 256 + threadIdx.x;
    if (hw >= HW2) return;
    int o = blockIdx.y, b = blockIdx.z;
    int h = hw / WW, x = hw % WW;
    const float* ib = in + (long long)b * inB;
    const float* wo = w + (long long)o * C * 9;
    float acc = 0.f;
    for (int c = 0; c < C; c++) {
        const float* ic = ib + (long long)c * HW2;
        const float* wc = wo + c * 9;
#pragma unroll
        for (int kh = 0; kh < 3; kh++) {
            int ih = h + kh - 1;
            if (ih < 0 || ih >= HH) continue;
#pragma unroll
            for (int kw = 0; kw < 3; kw++) {
                int iw = x + kw - 1;
                if (iw < 0 || iw >= WW) continue;
                acc += ic[ih * WW + iw] * wc[kh * 3 + kw];
            }
        }
    }
    if (relu) acc = fmaxf(acc, 0.f);
    out[(long long)b * outB + (long long)o * HW2 + hw] = acc;
}

// ---------------- elementwise kernels ----------------
__global__ void concat_k(const float* __restrict__ a, const float* __restrict__ b_,
                         float* __restrict__ o, long long imgStride)
{
    int idx = blockIdx.x * 256 + threadIdx.x;
    if (idx >= 2 * 512 * HW2) return;
    int bb = idx / (512 * HW2);
    int c = (idx / HW2) % 512;
    int hw = idx % HW2;
    float v = (c < 256) ? a[bb * imgStride + (long long)c * HW2 + hw]
                        : b_[bb * imgStride + (long long)(c - 256) * HW2 + hw];
    o[idx] = v;
}

__global__ void corr_k(const float* __restrict__ Ra, const float* __restrict__ Tb,
                       float* __restrict__ f177)
{
    int idx = blockIdx.x * 256 + threadIdx.x;
    if (idx >= 2 * 49 * HW2) return;
    int b = idx / (49 * HW2);
    int q = (idx / HW2) % 49;
    int hw = idx % HW2;
    int h = hw / WW, w = hw % WW;
    int dy = 2 * ((q / 7) - 3), dx = 2 * ((q % 7) - 3);
    int hh = h + dy, ww = w + dx;
    float s = 0.f;
    if (hh >= 0 && hh < HH && ww >= 0 && ww < WW) {
        const float* a = Ra + (long long)b * (2 * 64 * HW2) + hw;
        const float* bp = Tb + (long long)b * (2 * 64 * HW2) + hh * WW + ww;
        for (int c = 0; c < 64; c++) s += a[c * HW2] * bp[c * HW2];
    }
    f177[((long long)b * 177 + q) * HW2 + hw] = s * (1.f / 64.f);
}

__global__ void pack_k(const float* __restrict__ eA, const float* __restrict__ eB,
                       float* __restrict__ f177)
{
    int idx = blockIdx.x * 256 + threadIdx.x;
    if (idx >= 2 * 64 * HW2) return;
    int b = idx / (64 * HW2);
    int c = (idx / HW2) % 64;
    int hw = idx % HW2;
    f177[((long long)b * 177 + 49 + c) * HW2 + hw] = eA[idx];
    f177[((long long)b * 177 + 113 + c) * HW2 + hw] = eB[idx];
}

__global__ void mean36_k(const float* __restrict__ in, float* __restrict__ fw, int total)
{
    int i = blockIdx.x * 256 + threadIdx.x;
    if (i >= total) return;
    float s = 0.f;
#pragma unroll
    for (int j = 0; j < 36; j++) s += in[i * 36 + j];
    fw[i] = s * (1.f / 36.f);
}

__global__ void mkw_k(const float* __restrict__ fw, const float* __restrict__ Wt,
                      const float* __restrict__ Bi, float* __restrict__ adw,
                      int M, int Kc, int total)
{
    int idx = blockIdx.x * 256 + threadIdx.x;
    if (idx >= total) return;
    int b = idx / (M * Kc);
    int r = idx - b * M * Kc;
    int o = r / Kc;
    adw[idx] = fw[b * M + o] * Wt[r] + Bi[r];
}

__global__ void final_k(const float* __restrict__ d0, const float* __restrict__ d1,
                        const float* __restrict__ s0p, const float* __restrict__ s1p,
                        float* __restrict__ out, int total)
{
    int idx = blockIdx.x * 256 + threadIdx.x;
    if (idx >= total) return;
    int b = idx / (256 * HW2);
    int hw = idx % HW2;
    float s0 = s0p[b * HW2 + hw];
    float s1 = s1p[b * HW2 + hw];
    const float eps = 1e-8f;
    float wx = (s0 * s1) / (fmaxf(fabsf(s0), eps) * fmaxf(fabsf(s1), eps));
    float wy = (s1 * s1) / (fmaxf(fabsf(s1), eps) * fmaxf(fabsf(s1), eps));
    float mx = fmaxf(wx, wy);
    float e0 = expf(wx - mx), e1 = expf(wy - mx);
    float inv = 1.f / (e0 + e1);
    out[idx] = d0[idx] * (e0 * inv) + d1[idx] * (e1 * inv);
}

// ---------------- host orchestration ----------------
extern "C" void kernel_launch(void* const* d_in, const int* in_sizes, int n_in,
                              void* d_out, int out_size)
{
    (void)in_sizes; (void)n_in; (void)out_size;
    const float* R0     = (const float*)d_in[0];
    const float* T0     = (const float*)d_in[1];
    const float* inp    = (const float*)d_in[2];
    const float* enc0_w = (const float*)d_in[3];
    const float* enc0_b = (const float*)d_in[4];
    const float* enc1_w = (const float*)d_in[5];
    const float* enc1_b = (const float*)d_in[6];
    const float* offw[4] = {(const float*)d_in[7], (const float*)d_in[8],
                            (const float*)d_in[9], (const float*)d_in[10]};
    const float* defw[3] = {(const float*)d_in[11], (const float*)d_in[12],
                            (const float*)d_in[13]};
    const float* w0a = (const float*)d_in[14];
    const float* w0b = (const float*)d_in[15];
    const float* w0c = (const float*)d_in[16];
    const float* w1a = (const float*)d_in[17];
    const float* w1b = (const float*)d_in[18];
    const float* w1c = (const float*)d_in[19];
    const float* wx_w  = (const float*)d_in[20];
    const float* wx_b  = (const float*)d_in[21];
    const float* wxf_w = (const float*)d_in[22];
    const float* wxf_b = (const float*)d_in[23];
    const float* s1w = (const float*)d_in[24];
    const float* s2w = (const float*)d_in[25];
    const float* s3w = (const float*)d_in[26];
    float* out = (float*)d_out;

    float *xenc, *yenc, *f512a, *f512b, *cols, *off, *cpart, *f177, *f177b;
    float *wb1, *wb2, *wb3, *fw, *adw, *def0, *def1, *s1o, *s2o, *swa, *swb;
    u16 *colsh, *colsl, *awh, *awl, *dwh, *dwl, *s1h, *s1l;
    cudaGetSymbolAddress((void**)&xenc,  g_xenc);
    cudaGetSymbolAddress((void**)&yenc,  g_yenc);
    cudaGetSymbolAddress((void**)&f512a, g_f512a);
    cudaGetSymbolAddress((void**)&f512b, g_f512b);
    cudaGetSymbolAddress((void**)&cols,  g_cols);
    cudaGetSymbolAddress((void**)&colsh, g_colsh);
    cudaGetSymbolAddress((void**)&colsl, g_colsl);
    cudaGetSymbolAddress((void**)&awh,   g_awh);
    cudaGetSymbolAddress((void**)&awl,   g_awl);
    cudaGetSymbolAddress((void**)&dwh,   g_dwh);
    cudaGetSymbolAddress((void**)&dwl,   g_dwl);
    cudaGetSymbolAddress((void**)&s1h,   g_s1h);
    cudaGetSymbolAddress((void**)&s1l,   g_s1l);
    cudaGetSymbolAddress((void**)&off,   g_offb);
    cudaGetSymbolAddress((void**)&cpart, g_cpart);
    cudaGetSymbolAddress((void**)&f177,  g_f177);
    cudaGetSymbolAddress((void**)&f177b, g_f177b);
    cudaGetSymbolAddress((void**)&wb1,   g_wb1);
    cudaGetSymbolAddress((void**)&wb2,   g_wb2);
    cudaGetSymbolAddress((void**)&wb3,   g_wb3);
    cudaGetSymbolAddress((void**)&fw,    g_fwb);
    cudaGetSymbolAddress((void**)&adw,   g_adw);
    cudaGetSymbolAddress((void**)&def0,  g_def0);
    cudaGetSymbolAddress((void**)&def1,  g_def1);
    cudaGetSymbolAddress((void**)&s1o,   g_s1o);
    cudaGetSymbolAddress((void**)&s2o,   g_s2o);
    cudaGetSymbolAddress((void**)&swa,   g_swa);
    cudaGetSymbolAddress((void**)&swb,   g_swb);

    const long long imgStride = 2LL * 256 * HW2;
    const int DW = 512 * 4608;

    // hoisted weight pre-splits (branch-invariant)
    for (int i = 0; i < 3; i++)
        convw_k<<<(DW + 255) / 256, 256>>>(defw[i], dwh + (long long)i * DW,
                                           dwl + (long long)i * DW, DW);
    convw_k<<<(128 * 2304 + 255) / 256, 256>>>(s1w, s1h, s1l, 128 * 2304);

    auto GEMMTB = [&](const u16* Ah, const u16* Al, float* C, int M, int N, int K,
                      long long sA, long long sB, long long sC, int relu) {
        gemm_bf3b<<<dim3(N / 64, M / 128, 2), 256>>>(Ah, Al, colsh, colsl,
                                                     C, M, N, K, sA, sB, sC, relu);
    };
    auto GEMMA = [&](const float* A, const float* Bm, float* C, int M, int N, int K,
                     long long sA, long long sB, long long sC,
                     const float* bias, int relu) {
        gemm_al<4><<<dim3(N / 64, M / 64, 2), 256>>>(A, Bm, C, M, N, K, sA, sB, sC, bias, relu);
    };
    auto GEMMF = [&](const float* A, const float* Bm, float* C, int M, int N, int K,
                     long long sA, long long sB, long long sC,
                     const float* bias, int relu) {
        dim3 g((N + 63) / 64, (M + 63) / 64, 2);
        gemm64<<<g, dim3(16, 16)>>>(A, Bm, C, M, N, K, sA, sB, sC, bias, relu);
    };
    auto DIM2COL = [&](const float* src, long long sB, const float* offp, int C, int mode) {
        dim3 g((HW2 + 255) / 256, 18, (C + 63) / 64);
        deform_im2col_k<<<g, 256>>>(src, sB, offp, cols, colsh, colsl, C, mode);
    };
    auto IM2COL = [&](const float* src, long long sB, int C, int H, int W,
                      int KH, int KW, int st, int pad, int OH, int OW) {
        dim3 g((OH * OW + 255) / 256, C * KH * KW, 2);
        im2col_g<<<g, 256>>>(src, sB, cols, C, H, W, KH, KW, st, pad, OH, OW);
    };
    auto CONV18 = [&](const float* in, long long inB, const float* w, float* o) {
        conv18_k<<<dim3(9, 16, 2), 256>>>(in, inB, w, cpart, 512);
        reduce18_k<<<(2 * 18 * HW2 + 255) / 256, 256>>>(cpart, o);
    };
    auto WBRANCH = [&](const float* feat, const float* wa, const float* wb,
                       const float* wc, int Mc) {
        IM2COL(feat, 177LL * HW2, 177, 48, 48, 5, 5, 2, 2, 24, 24);
        GEMMF(wa, cols, wb1, 64, 576, 4425, 0, 4425LL * 576, 64LL * 576, nullptr, 1);
        IM2COL(wb1, 64LL * 576, 64, 24, 24, 5, 5, 2, 2, 12, 12);
        GEMMF(wb, cols, wb2, 64, 144, 1600, 0, 1600LL * 144, 64LL * 144, nullptr, 1);
        IM2COL(wb2, 64LL * 144, 64, 12, 12, 3, 3, 2, 1, 6, 6);
        GEMMF(wc, cols, wb3, Mc, 36, 576, 0, 576LL * 36, (long long)Mc * 36, nullptr, 0);
        int tot = 2 * Mc;
        mean36_k<<<(tot + 255) / 256, 256>>>(wb3, fw, tot);
    };

    // ---- encoders (1x1 conv == GEMM on NCHW directly) ----
    GEMMA(enc0_w, inp,             xenc, 64, HW2, 256, 0, imgStride, 64LL * HW2, enc0_b, 0);
    GEMMA(enc1_w, inp + 256 * HW2, yenc, 64, HW2, 256, 0, imgStride, 64LL * HW2, enc1_b, 0);

    auto BRANCH = [&](int br, float* gdef, float* gsw) {
        const float* imgA = (br == 0) ? inp : inp + 256 * HW2;
        const float* imgB = inp + 256 * HW2;   // y for both branches

        // ---- stsn_offset ----
        {
            int tot = 2 * 512 * HW2;
            concat_k<<<(tot + 255) / 256, 256>>>(imgA, imgB, f512a, imgStride);
        }
        float* cur = f512a; float* oth = f512b;
        for (int i = 0; i < 3; i++) {
            CONV18(cur, 512LL * HW2, offw[i], off);
            DIM2COL(cur, 512LL * HW2, off, 512, 1);
            GEMMTB(dwh + (long long)i * DW, dwl + (long long)i * DW,
                   oth, 512, HW2, 4608, 0, 4608LL * HW2, 512LL * HW2, 0);
            float* t = cur; cur = oth; oth = t;
        }
        CONV18(cur, 512LL * HW2, offw[3], off);  // final offsets -> g_offb

        // ---- astsn_weight ----
        const float* Ra = R0 + (br == 0 ? 0 : 64 * HW2);   // R_pre / R_cur
        const float* Tb = T0 + 64 * HW2;                    // T_cur
        const float* eA = (br == 0) ? xenc : yenc;
        const float* eB = yenc;
        {
            int tot = 2 * 49 * HW2;
            corr_k<<<(tot + 255) / 256, 256>>>(Ra, Tb, f177);
        }
        {
            int tot = 2 * 64 * HW2;
            pack_k<<<(tot + 255) / 256, 256>>>(eA, eB, f177);
        }
        WBRANCH(f177, w0a, w0b, w0c, 177);
        {
            int tot = 2 * 177 * 1593;
            mkw_k<<<(tot + 255) / 256, 256>>>(fw, wx_w, wx_b, adw, 177, 1593, tot);
        }
        DIM2COL(f177, 177LL * HW2, nullptr, 177, 0);
        GEMMF(adw, cols, f177b, 177, HW2, 1593, 177LL * 1593, 1593LL * HW2, 177LL * HW2,
              nullptr, 1);
        WBRANCH(f177b, w1a, w1b, w1c, 256);
        {
            int tot = 2 * 256 * 2304;
            mkw_k<<<(tot + 255) / 256, 256>>>(fw, wxf_w, wxf_b, adw, 256, 2304, tot);
        }

        // ---- adaptive deform conv (A per-batch) ----
        convw_k<<<(2 * 256 * 2304 + 255) / 256, 256>>>(adw, awh, awl, 2 * 256 * 2304);
        DIM2COL(imgA, imgStride, off, 256, 1);
        GEMMTB(awh, awl, gdef, 256, HW2, 2304,
               256LL * 2304, 2304LL * HW2, 256LL * HW2, 0);

        // ---- s_net ----
        DIM2COL(gdef, 256LL * HW2, nullptr, 256, 1);
        GEMMTB(s1h, s1l, s1o, 128, HW2, 2304, 0, 2304LL * HW2, 128LL * HW2, 1);
        DIM2COL(s1o, 128LL * HW2, nullptr, 128, 0);
        GEMMA(s2w, cols, s2o, 64, HW2, 1152, 0, 1152LL * HW2, 64LL * HW2, nullptr, 1);
        conv3x3_direct<<<dim3(9, 1, 2), 256>>>(s2o, 64LL * HW2, s3w, gsw,
                                               (long long)HW2, 64, 1);
    };

    BRANCH(0, def0, swa);
    BRANCH(1, def1, swb);

    {
        int tot = 2 * 256 * HW2;
        final_k<<<(tot + 255) / 256, 256>>>(def0, def1, swa, swb, out, tot);
    }
}

// round 8
// speedup vs baseline: 3.3334x; 1.6359x over previous
#include <cuda_runtime.h>
#include <cuda_bf16.h>
#include <math.h>

#define HW2 2304
#define HH 48
#define WW 48

typedef unsigned int u32;
typedef unsigned short u16;

// ---------------- device scratch (no allocations allowed; [2] = per-branch) ----------------
__device__ float g_xenc  [2*64 *HW2];
__device__ float g_yenc  [2*64 *HW2];
__device__ float g_f512a [2][2*512*HW2];
__device__ float g_f512b [2][2*512*HW2];
__device__ float g_cols  [2][2*1600*HW2];
__device__ u16   g_colsh [2][2*4608*HW2];
__device__ u16   g_colsl [2][2*4608*HW2];
__device__ u16   g_awh   [2][2*256*2304];
__device__ u16   g_awl   [2][2*256*2304];
__device__ u16   g_dwh   [3*512*4608];
__device__ u16   g_dwl   [3*512*4608];
__device__ u16   g_s1h   [128*2304];
__device__ u16   g_s1l   [128*2304];
__device__ float g_offb  [2][2*18 *HW2];
__device__ float g_cpart [2][16*2*18*HW2];
__device__ float g_f177  [2][2*177*HW2];
__device__ float g_f177b [2][2*177*HW2];
__device__ float g_wb1   [2][2*64*576];
__device__ float g_wb2   [2][2*64*144];
__device__ float g_wb3   [2][2*256*36];
__device__ float g_fwb   [2][2*256];
__device__ float g_adw   [2][2*256*HW2];
__device__ float g_def0  [2*256*HW2];
__device__ float g_def1  [2*256*HW2];
__device__ float g_s1o   [2][2*128*HW2];
__device__ float g_s2o   [2][2*64*HW2];
__device__ float g_swa   [2*HW2];
__device__ float g_swb   [2*HW2];

// ---------------- helpers ----------------
__device__ __forceinline__ void split16(float x, u16& h, u16& l)
{
    __nv_bfloat16 xh = __float2bfloat16(x);
    h = __bfloat16_as_ushort(xh);
    l = __bfloat16_as_ushort(__float2bfloat16(x - __bfloat162float(xh)));
}

__global__ void convw_k(const float* __restrict__ src, u16* __restrict__ h,
                        u16* __restrict__ l, int n)
{
    int i = blockIdx.x * 256 + threadIdx.x;
    if (i >= n) return;
    u16 hh, ll;
    split16(src[i], hh, ll);
    h[i] = hh; l[i] = ll;
}

#define MMA16816(c, a, b0v, b1v) \
    asm volatile("mma.sync.aligned.m16n8k16.row.col.f32.bf16.bf16.f32 " \
        "{%0,%1,%2,%3},{%4,%5,%6,%7},{%8,%9},{%0,%1,%2,%3};" \
        : "+f"((c)[0]), "+f"((c)[1]), "+f"((c)[2]), "+f"((c)[3]) \
        : "r"((a)[0]), "r"((a)[1]), "r"((a)[2]), "r"((a)[3]), \
          "r"(b0v), "r"(b1v))

// ---------------- bf16x3 split tensor-core GEMM, pre-split inputs ----------------
__global__ __launch_bounds__(256)
void gemm_bf3b(const u16* __restrict__ Ah, const u16* __restrict__ Al,
               const u16* __restrict__ Bh, const u16* __restrict__ Bl,
               float* __restrict__ C, int M, int N, int K,
               long long sA, long long sB, long long sC, int relu)
{
    Ah += (long long)blockIdx.z * sA;
    Al += (long long)blockIdx.z * sA;
    Bh += (long long)blockIdx.z * sB;
    Bl += (long long)blockIdx.z * sB;
    C  += (long long)blockIdx.z * sC;

    __shared__ u32 sAh[2][128][13];
    __shared__ u32 sAl[2][128][13];
    __shared__ u32 sBh[2][64][13];
    __shared__ u32 sBl[2][64][13];

    const int tid = threadIdx.x;
    const int lane = tid & 31, warp = tid >> 5;
    const int wm = warp >> 1, wn = warp & 1;
    const int m0 = blockIdx.y * 128, n0 = blockIdx.x * 64;

    const int arow = tid >> 1, ahalf = tid & 1;
    const u16* ApH = Ah + (long long)(m0 + arow) * K + ahalf * 8;
    const u16* ApL = Al + (long long)(m0 + arow) * K + ahalf * 8;

    const int bw = warp;
    const int bn = lane * 2;
    const u16* BpH = Bh + n0 + bn;
    const u16* BpL = Bl + n0 + bn;

    float acc[2][4][4];
#pragma unroll
    for (int mt = 0; mt < 2; mt++)
#pragma unroll
        for (int nt = 0; nt < 4; nt++)
#pragma unroll
            for (int i = 0; i < 4; i++) acc[mt][nt][i] = 0.f;

    uint4 lah, lal;
    u32 lbh0, lbh1, lbl0, lbl1;

    lah = *(const uint4*)ApH;
    lal = *(const uint4*)ApL;
    lbh0 = *(const u32*)(BpH + (long long)(2 * bw) * N);
    lbh1 = *(const u32*)(BpH + (long long)(2 * bw + 1) * N);
    lbl0 = *(const u32*)(BpL + (long long)(2 * bw) * N);
    lbl1 = *(const u32*)(BpL + (long long)(2 * bw + 1) * N);
    {
        sAh[0][arow][ahalf*4+0] = lah.x; sAh[0][arow][ahalf*4+1] = lah.y;
        sAh[0][arow][ahalf*4+2] = lah.z; sAh[0][arow][ahalf*4+3] = lah.w;
        sAl[0][arow][ahalf*4+0] = lal.x; sAl[0][arow][ahalf*4+1] = lal.y;
        sAl[0][arow][ahalf*4+2] = lal.z; sAl[0][arow][ahalf*4+3] = lal.w;
        sBh[0][bn  ][bw] = __byte_perm(lbh0, lbh1, 0x5410);
        sBh[0][bn+1][bw] = __byte_perm(lbh0, lbh1, 0x7632);
        sBl[0][bn  ][bw] = __byte_perm(lbl0, lbl1, 0x5410);
        sBl[0][bn+1][bw] = __byte_perm(lbl0, lbl1, 0x7632);
    }
    __syncthreads();

    const int ar = lane >> 2, ac = lane & 3;
    int buf = 0;
    for (int k0 = 0; k0 < K; k0 += 16) {
        const bool has = (k0 + 16) < K;
        if (has) {
            lah = *(const uint4*)(ApH + k0 + 16);
            lal = *(const uint4*)(ApL + k0 + 16);
            const long long r0 = (long long)(k0 + 16 + 2 * bw) * N;
            lbh0 = *(const u32*)(BpH + r0);
            lbh1 = *(const u32*)(BpH + r0 + N);
            lbl0 = *(const u32*)(BpL + r0);
            lbl1 = *(const u32*)(BpL + r0 + N);
        }

        u32 ah[2][4], al[2][4];
#pragma unroll
        for (int mt = 0; mt < 2; mt++) {
            int r = wm * 32 + mt * 16 + ar;
            ah[mt][0] = sAh[buf][r][ac];         al[mt][0] = sAl[buf][r][ac];
            ah[mt][1] = sAh[buf][r + 8][ac];     al[mt][1] = sAl[buf][r + 8][ac];
            ah[mt][2] = sAh[buf][r][ac + 4];     al[mt][2] = sAl[buf][r][ac + 4];
            ah[mt][3] = sAh[buf][r + 8][ac + 4]; al[mt][3] = sAl[buf][r + 8][ac + 4];
        }
#pragma unroll
        for (int nt = 0; nt < 4; nt++) {
            int nr = wn * 32 + nt * 8 + ar;
            u32 bh0 = sBh[buf][nr][ac], bh1 = sBh[buf][nr][ac + 4];
            u32 bl0 = sBl[buf][nr][ac], bl1 = sBl[buf][nr][ac + 4];
#pragma unroll
            for (int mt = 0; mt < 2; mt++) {
                MMA16816(acc[mt][nt], ah[mt], bh0, bh1);
                MMA16816(acc[mt][nt], ah[mt], bl0, bl1);
                MMA16816(acc[mt][nt], al[mt], bh0, bh1);
            }
        }

        if (has) {
            int nb = buf ^ 1;
            sAh[nb][arow][ahalf*4+0] = lah.x; sAh[nb][arow][ahalf*4+1] = lah.y;
            sAh[nb][arow][ahalf*4+2] = lah.z; sAh[nb][arow][ahalf*4+3] = lah.w;
            sAl[nb][arow][ahalf*4+0] = lal.x; sAl[nb][arow][ahalf*4+1] = lal.y;
            sAl[nb][arow][ahalf*4+2] = lal.z; sAl[nb][arow][ahalf*4+3] = lal.w;
            sBh[nb][bn  ][bw] = __byte_perm(lbh0, lbh1, 0x5410);
            sBh[nb][bn+1][bw] = __byte_perm(lbh0, lbh1, 0x7632);
            sBl[nb][bn  ][bw] = __byte_perm(lbl0, lbl1, 0x5410);
            sBl[nb][bn+1][bw] = __byte_perm(lbl0, lbl1, 0x7632);
        }
        __syncthreads();
        buf ^= 1;
    }

#pragma unroll
    for (int mt = 0; mt < 2; mt++) {
        int r = m0 + wm * 32 + mt * 16 + ar;
#pragma unroll
        for (int nt = 0; nt < 4; nt++) {
            int c = n0 + wn * 32 + nt * 8 + ac * 2;
            float2 v0 = make_float2(acc[mt][nt][0], acc[mt][nt][1]);
            float2 v1 = make_float2(acc[mt][nt][2], acc[mt][nt][3]);
            if (relu) {
                v0.x = fmaxf(v0.x, 0.f); v0.y = fmaxf(v0.y, 0.f);
                v1.x = fmaxf(v1.x, 0.f); v1.y = fmaxf(v1.y, 0.f);
            }
            *(float2*)&C[(long long)r * N + c] = v0;
            *(float2*)&C[(long long)(r + 8) * N + c] = v1;
        }
    }
}

// ---------------- aligned fast fp32 GEMM ----------------
template<int RN>
__global__ __launch_bounds__(256)
void gemm_al(const float* __restrict__ A, const float* __restrict__ B,
             float* __restrict__ C, int M, int N, int K,
             long long sA, long long sB, long long sC,
             const float* __restrict__ bias, int relu)
{
    constexpr int TN = 16 * RN;
    A += (long long)blockIdx.z * sA;
    B += (long long)blockIdx.z * sB;
    C += (long long)blockIdx.z * sC;

    __shared__ float As[2][16][68];
    __shared__ float Bs[2][16][TN];

    const int tid = threadIdx.x;
    const int tx = tid & 15, ty = tid >> 4;
    const int m0 = blockIdx.y * 64, n0 = blockIdx.x * TN;

    const int ar = tid >> 2;
    const int ak = (tid & 3) * 4;
    const int bk = tid >> 4;
    const int bn = (tid & 15) * RN;

    const float* Ap = A + (long long)(m0 + ar) * K + ak;
    const float* Bp = B + (long long)bk * N + n0 + bn;

    float acc[4][RN];
#pragma unroll
    for (int i = 0; i < 4; i++)
#pragma unroll
        for (int j = 0; j < RN; j++) acc[i][j] = 0.f;

    {
        float4 av = *(const float4*)Ap;
        As[0][ak + 0][ar] = av.x; As[0][ak + 1][ar] = av.y;
        As[0][ak + 2][ar] = av.z; As[0][ak + 3][ar] = av.w;
#pragma unroll
        for (int h = 0; h < RN / 4; h++)
            *(float4*)&Bs[0][bk][bn + h * 4] = *(const float4*)(Bp + h * 4);
    }
    __syncthreads();

    int buf = 0;
    for (int k0 = 0; k0 < K; k0 += 16) {
        const bool has = (k0 + 16) < K;
        float4 la;
        float4 lbv[RN / 4];
        if (has) {
            la = *(const float4*)(Ap + k0 + 16);
#pragma unroll
            for (int h = 0; h < RN / 4; h++)
                lbv[h] = *(const float4*)(Bp + (long long)(k0 + 16) * N + h * 4);
        }

#pragma unroll
        for (int kk = 0; kk < 16; kk++) {
            float4 a4 = *(const float4*)&As[buf][kk][ty * 4];
            float a[4] = {a4.x, a4.y, a4.z, a4.w};
            float b[RN];
#pragma unroll
            for (int h = 0; h < RN / 4; h++) {
                float4 b4 = *(const float4*)&Bs[buf][kk][h * 64 + tx * 4];
                b[h * 4 + 0] = b4.x; b[h * 4 + 1] = b4.y;
                b[h * 4 + 2] = b4.z; b[h * 4 + 3] = b4.w;
            }
#pragma unroll
            for (int i = 0; i < 4; i++)
#pragma unroll
                for (int j = 0; j < RN; j++) acc[i][j] += a[i] * b[j];
        }

        if (has) {
            int nb = buf ^ 1;
            As[nb][ak + 0][ar] = la.x; As[nb][ak + 1][ar] = la.y;
            As[nb][ak + 2][ar] = la.z; As[nb][ak + 3][ar] = la.w;
#pragma unroll
            for (int h = 0; h < RN / 4; h++)
                *(float4*)&Bs[nb][bk][bn + h * 4] = lbv[h];
        }
        __syncthreads();
        buf ^= 1;
    }

#pragma unroll
    for (int i = 0; i < 4; i++) {
        int m = m0 + ty * 4 + i;
        float bv = bias ? bias[m] : 0.f;
#pragma unroll
        for (int h = 0; h < RN / 4; h++) {
            float4 v;
            v.x = acc[i][h * 4 + 0] + bv;
            v.y = acc[i][h * 4 + 1] + bv;
            v.z = acc[i][h * 4 + 2] + bv;
            v.w = acc[i][h * 4 + 3] + bv;
            if (relu) {
                v.x = fmaxf(v.x, 0.f); v.y = fmaxf(v.y, 0.f);
                v.z = fmaxf(v.z, 0.f); v.w = fmaxf(v.w, 0.f);
            }
            *(float4*)&C[(long long)m * N + n0 + h * 64 + tx * 4] = v;
        }
    }
}

// ---------------- fallback 64x64 GEMM (any shape) ----------------
__global__ void gemm64(const float* __restrict__ A, const float* __restrict__ B,
                       float* __restrict__ C, int M, int N, int K,
                       long long sA, long long sB, long long sC,
                       const float* __restrict__ bias, int relu)
{
    A += (long long)blockIdx.z * sA;
    B += (long long)blockIdx.z * sB;
    C += (long long)blockIdx.z * sC;
    __shared__ float As[16][64];
    __shared__ float Bs[16][68];
    int tx = threadIdx.x, ty = threadIdx.y;
    int tid = ty * 16 + tx;
    int m0 = blockIdx.y * 64, n0 = blockIdx.x * 64;
    int mA = tid >> 2, kA = (tid & 3) * 4;
    int kB = tid >> 4, nB = (tid & 15) * 4;
    float acc[4][4];
#pragma unroll
    for (int i = 0; i < 4; i++)
#pragma unroll
        for (int j = 0; j < 4; j++) acc[i][j] = 0.f;

    for (int k0 = 0; k0 < K; k0 += 16) {
#pragma unroll
        for (int i = 0; i < 4; i++) {
            int k = k0 + kA + i;
            As[kA + i][mA] = (m0 + mA < M && k < K) ? A[(long long)(m0 + mA) * K + k] : 0.f;
        }
#pragma unroll
        for (int i = 0; i < 4; i++) {
            int n = n0 + nB + i;
            Bs[kB][nB + i] = (k0 + kB < K && n < N) ? B[(long long)(k0 + kB) * N + n] : 0.f;
        }
        __syncthreads();
#pragma unroll
        for (int kk = 0; kk < 16; kk++) {
            float a[4], b[4];
#pragma unroll
            for (int i = 0; i < 4; i++) a[i] = As[kk][ty * 4 + i];
#pragma unroll
            for (int j = 0; j < 4; j++) b[j] = Bs[kk][tx * 4 + j];
#pragma unroll
            for (int i = 0; i < 4; i++)
#pragma unroll
                for (int j = 0; j < 4; j++) acc[i][j] += a[i] * b[j];
        }
        __syncthreads();
    }
#pragma unroll
    for (int i = 0; i < 4; i++) {
        int m = m0 + ty * 4 + i;
        if (m >= M) continue;
        float bv = bias ? bias[m] : 0.f;
#pragma unroll
        for (int j = 0; j < 4; j++) {
            int n = n0 + tx * 4 + j;
            if (n >= N) continue;
            float v = acc[i][j] + bv;
            if (relu) v = fmaxf(v, 0.f);
            C[(long long)m * N + n] = v;
        }
    }
}

// ---------------- 512->18 offset-head 3x3 conv ----------------
__global__ void conv18_k(const float* __restrict__ in, long long inB,
                         const float* __restrict__ w, float* __restrict__ part, int C)
{
    const int t = blockIdx.x, cc = blockIdx.y, b = blockIdx.z;
    const int tid = threadIdx.x;
    const int hw = t * 256 + tid;
    const int h = hw / WW, x = hw % WW;
    const int hf = (t * 256) / WW;

    __shared__ float sIn[4][9 * WW];
    __shared__ float sW[4][18 * 9];

    float acc[18];
#pragma unroll
    for (int o = 0; o < 18; o++) acc[o] = 0.f;

    const float* ib = in + (long long)b * inB + (long long)(cc * 32) * HW2;
    const int lr = h - (hf - 1);

    for (int cs = 0; cs < 32; cs += 4) {
        for (int i = tid; i < 4 * 9 * WW; i += 256) {
            int c = i / (9 * WW), r = i % (9 * WW);
            int row = hf - 1 + r / WW, col = r % WW;
            float v = 0.f;
            if (row >= 0 && row < HH) v = ib[(long long)(cs + c) * HW2 + row * WW + col];
            sIn[c][r] = v;
        }
        for (int i = tid; i < 4 * 162; i += 256) {
            int c = i / 162, r = i % 162;
            int o = r / 9, q = r % 9;
            sW[c][r] = w[((long long)o * C + (cc * 32 + cs + c)) * 9 + q];
        }
        __syncthreads();

#pragma unroll
        for (int c = 0; c < 4; c++) {
            float tap[9];
#pragma unroll
            for (int ki = 0; ki < 3; ki++)
#pragma unroll
                for (int kj = 0; kj < 3; kj++) {
                    int xx = x - 1 + kj;
                    float v = 0.f;
                    if (xx >= 0 && xx < WW) v = sIn[c][(lr - 1 + ki) * WW + xx];
                    tap[ki * 3 + kj] = v;
                }
#pragma unroll
            for (int o = 0; o < 18; o++) {
                float s = acc[o];
#pragma unroll
                for (int q = 0; q < 9; q++) s += sW[c][o * 9 + q] * tap[q];
                acc[o] = s;
            }
        }
        __syncthreads();
    }

    float* pp = part + ((long long)cc * 2 + b) * 18 * HW2;
#pragma unroll
    for (int o = 0; o < 18; o++) pp[(long long)o * HW2 + hw] = acc[o];
}

__global__ void reduce18_k(const float* __restrict__ part, float* __restrict__ out)
{
    int idx = blockIdx.x * 256 + threadIdx.x;
    if (idx >= 2 * 18 * HW2) return;
    int b = idx / (18 * HW2);
    int r = idx % (18 * HW2);
    float s = 0.f;
#pragma unroll
    for (int c = 0; c < 16; c++) s += part[((long long)c * 2 + b) * 18 * HW2 + r];
    out[(long long)b * 18 * HW2 + r] = s;
}

// ---------------- deformable (or plain) 3x3 s1 p1 im2col ----------------
__global__ void deform_im2col_k(const float* __restrict__ src, long long srcB,
                                const float* __restrict__ off,
                                float* __restrict__ colsF,
                                u16* __restrict__ colsH, u16* __restrict__ colsL,
                                int C, int mode)
{
    int hw = blockIdx.x * 256 + threadIdx.x;
    if (hw >= HW2) return;
    int bq = blockIdx.y;
    int b = bq / 9, q = bq % 9;
    int ki = q / 3, kj = q % 3;
    int h = hw / WW, w = hw % WW;
    const float* sb = src + (long long)b * srcB;
    long long cbase = (long long)b * C * 9 * HW2;
    int c0 = blockIdx.z * 64;
    int c1 = c0 + 64; if (c1 > C) c1 = C;

    float w00, w01, w10, w11;
    int i00, i01, i10, i11;
    if (off == nullptr) {
        int y = h - 1 + ki, x = w - 1 + kj;
        bool vin = (y >= 0 && y < HH && x >= 0 && x < WW);
        w00 = vin ? 1.f : 0.f; w01 = w10 = w11 = 0.f;
        i00 = vin ? (y * WW + x) : 0; i01 = i10 = i11 = 0;
    } else {
        float py = (float)(h - 1 + ki) + off[((long long)b * 18 + 2 * q) * HW2 + hw];
        float px = (float)(w - 1 + kj) + off[((long long)b * 18 + 2 * q + 1) * HW2 + hw];
        float fy = floorf(py), fx = floorf(px);
        float ay = py - fy, ax = px - fx;
        int y0 = (int)fy, x0 = (int)fx;
        int y1 = y0 + 1, x1 = x0 + 1;
        bool by0 = (y0 >= 0 && y0 < HH), by1 = (y1 >= 0 && y1 < HH);
        bool bx0 = (x0 >= 0 && x0 < WW), bx1 = (x1 >= 0 && x1 < WW);
        int yc0 = min(max(y0, 0), HH - 1), yc1 = min(max(y1, 0), HH - 1);
        int xc0 = min(max(x0, 0), WW - 1), xc1 = min(max(x1, 0), WW - 1);
        w00 = (by0 && bx0) ? (1.f - ay) * (1.f - ax) : 0.f;
        w01 = (by0 && bx1) ? (1.f - ay) * ax : 0.f;
        w10 = (by1 && bx0) ? ay * (1.f - ax) : 0.f;
        w11 = (by1 && bx1) ? ay * ax : 0.f;
        i00 = yc0 * WW + xc0; i01 = yc0 * WW + xc1;
        i10 = yc1 * WW + xc0; i11 = yc1 * WW + xc1;
    }

    for (int c = c0; c < c1; c++) {
        const float* s = sb + (long long)c * HW2;
        float v = w00 * s[i00] + w01 * s[i01] + w10 * s[i10] + w11 * s[i11];
        long long idx = cbase + ((long long)c * 9 + q) * HW2 + hw;
        if (mode == 0) {
            colsF[idx] = v;
        } else {
            u16 hh, ll;
            split16(v, hh, ll);
            colsH[idx] = hh; colsL[idx] = ll;
        }
    }
}

// ---------------- generic strided im2col ----------------
__global__ void im2col_g(const float* __restrict__ src, long long srcB,
                         float* __restrict__ cols,
                         int C, int H, int W, int KH, int KW,
                         int stride, int pad, int OH, int OW)
{
    int ohw = blockIdx.x * 256 + threadIdx.x;
    int OHW = OH * OW;
    if (ohw >= OHW) return;
    int row = blockIdx.y;
    int b = blockIdx.z;
    int kk = row % (KH * KW);
    int c = row / (KH * KW);
    int kh = kk / KW, kw = kk % KW;
    int oh = ohw / OW, ow = ohw % OW;
    int ih = oh * stride - pad + kh;
    int iw = ow * stride - pad + kw;
    float v = 0.f;
    if (ih >= 0 && ih < H && iw >= 0 && iw < W)
        v = src[(long long)b * srcB + ((long long)c * H + ih) * W + iw];
    cols[((long long)b * C * KH * KW + row) * OHW + ohw] = v;
}

// ---------------- direct 3x3 conv (tiny s3: 64->1) ----------------
__global__ void conv3x3_direct(const float* __restrict__ in, long long inB,
                               const float* __restrict__ w, float* __restrict__ out,
                               long long outB, int C, int relu)
{
    int hw = blockIdx.x * 256 + threadIdx.x;
    if (hw >= HW2) return;
    int o = blockIdx.y, b = blockIdx.z;
    int h = hw / WW, x = hw % WW;
    const float* ib = in + (long long)b * inB;
    const float* wo = w + (long long)o * C * 9;
    float acc = 0.f;
    for (int c = 0; c < C; c++) {
        const float* ic = ib + (long long)c * HW2;
        const float* wc = wo + c * 9;
#pragma unroll
        for (int kh = 0; kh < 3; kh++) {
            int ih = h + kh - 1;
            if (ih < 0 || ih >= HH) continue;
#pragma unroll
            for (int kw = 0; kw < 3; kw++) {
                int iw = x + kw - 1;
                if (iw < 0 || iw >= WW) continue;
                acc += ic[ih * WW + iw] * wc[kh * 3 + kw];
            }
        }
    }
    if (relu) acc = fmaxf(acc, 0.f);
    out[(long long)b * outB + (long long)o * HW2 + hw] = acc;
}

// ---------------- elementwise kernels ----------------
__global__ void concat_k(const float* __restrict__ a, const float* __restrict__ b_,
                         float* __restrict__ o, long long imgStride)
{
    int idx = blockIdx.x * 256 + threadIdx.x;
    if (idx >= 2 * 512 * HW2) return;
    int bb = idx / (512 * HW2);
    int c = (idx / HW2) % 512;
    int hw = idx % HW2;
    float v = (c < 256) ? a[bb * imgStride + (long long)c * HW2 + hw]
                        : b_[bb * imgStride + (long long)(c - 256) * HW2 + hw];
    o[idx] = v;
}

__global__ void corr_k(const float* __restrict__ Ra, const float* __restrict__ Tb,
                       float* __restrict__ f177)
{
    int idx = blockIdx.x * 256 + threadIdx.x;
    if (idx >= 2 * 49 * HW2) return;
    int b = idx / (49 * HW2);
    int q = (idx / HW2) % 49;
    int hw = idx % HW2;
    int h = hw / WW, w = hw % WW;
    int dy = 2 * ((q / 7) - 3), dx = 2 * ((q % 7) - 3);
    int hh = h + dy, ww = w + dx;
    float s = 0.f;
    if (hh >= 0 && hh < HH && ww >= 0 && ww < WW) {
        const float* a = Ra + (long long)b * (2 * 64 * HW2) + hw;
        const float* bp = Tb + (long long)b * (2 * 64 * HW2) + hh * WW + ww;
        for (int c = 0; c < 64; c++) s += a[c * HW2] * bp[c * HW2];
    }
    f177[((long long)b * 177 + q) * HW2 + hw] = s * (1.f / 64.f);
}

__global__ void pack_k(const float* __restrict__ eA, const float* __restrict__ eB,
                       float* __restrict__ f177)
{
    int idx = blockIdx.x * 256 + threadIdx.x;
    if (idx >= 2 * 64 * HW2) return;
    int b = idx / (64 * HW2);
    int c = (idx / HW2) % 64;
    int hw = idx % HW2;
    f177[((long long)b * 177 + 49 + c) * HW2 + hw] = eA[idx];
    f177[((long long)b * 177 + 113 + c) * HW2 + hw] = eB[idx];
}

__global__ void mean36_k(const float* __restrict__ in, float* __restrict__ fw, int total)
{
    int i = blockIdx.x * 256 + threadIdx.x;
    if (i >= total) return;
    float s = 0.f;
#pragma unroll
    for (int j = 0; j < 36; j++) s += in[i * 36 + j];
    fw[i] = s * (1.f / 36.f);
}

__global__ void mkw_k(const float* __restrict__ fw, const float* __restrict__ Wt,
                      const float* __restrict__ Bi, float* __restrict__ adw,
                      int M, int Kc, int total)
{
    int idx = blockIdx.x * 256 + threadIdx.x;
    if (idx >= total) return;
    int b = idx / (M * Kc);
    int r = idx - b * M * Kc;
    int o = r / Kc;
    adw[idx] = fw[b * M + o] * Wt[r] + Bi[r];
}

__global__ void final_k(const float* __restrict__ d0, const float* __restrict__ d1,
                        const float* __restrict__ s0p, const float* __restrict__ s1p,
                        float* __restrict__ out, int total)
{
    int idx = blockIdx.x * 256 + threadIdx.x;
    if (idx >= total) return;
    int b = idx / (256 * HW2);
    int hw = idx % HW2;
    float s0 = s0p[b * HW2 + hw];
    float s1 = s1p[b * HW2 + hw];
    const float eps = 1e-8f;
    float wx = (s0 * s1) / (fmaxf(fabsf(s0), eps) * fmaxf(fabsf(s1), eps));
    float wy = (s1 * s1) / (fmaxf(fabsf(s1), eps) * fmaxf(fabsf(s1), eps));
    float mx = fmaxf(wx, wy);
    float e0 = expf(wx - mx), e1 = expf(wy - mx);
    float inv = 1.f / (e0 + e1);
    out[idx] = d0[idx] * (e0 * inv) + d1[idx] * (e1 * inv);
}

// ---------------- host orchestration (4-lane stream overlap) ----------------
extern "C" void kernel_launch(void* const* d_in, const int* in_sizes, int n_in,
                              void* d_out, int out_size)
{
    (void)in_sizes; (void)n_in; (void)out_size;
    const float* R0     = (const float*)d_in[0];
    const float* T0     = (const float*)d_in[1];
    const float* inp    = (const float*)d_in[2];
    const float* enc0_w = (const float*)d_in[3];
    const float* enc0_b = (const float*)d_in[4];
    const float* enc1_w = (const float*)d_in[5];
    const float* enc1_b = (const float*)d_in[6];
    const float* offw[4] = {(const float*)d_in[7], (const float*)d_in[8],
                            (const float*)d_in[9], (const float*)d_in[10]};
    const float* defw[3] = {(const float*)d_in[11], (const float*)d_in[12],
                            (const float*)d_in[13]};
    const float* w0a = (const float*)d_in[14];
    const float* w0b = (const float*)d_in[15];
    const float* w0c = (const float*)d_in[16];
    const float* w1a = (const float*)d_in[17];
    const float* w1b = (const float*)d_in[18];
    const float* w1c = (const float*)d_in[19];
    const float* wx_w  = (const float*)d_in[20];
    const float* wx_b  = (const float*)d_in[21];
    const float* wxf_w = (const float*)d_in[22];
    const float* wxf_b = (const float*)d_in[23];
    const float* s1w = (const float*)d_in[24];
    const float* s2w = (const float*)d_in[25];
    const float* s3w = (const float*)d_in[26];
    float* out = (float*)d_out;

    float *xenc, *yenc, *def0, *def1, *swa, *swb;
    float *f512aP, *f512bP, *colsP, *offP, *cpartP, *f177P, *f177bP;
    float *wb1P, *wb2P, *wb3P, *fwP, *adwP, *s1oP, *s2oP;
    u16 *colshP, *colslP, *awhP, *awlP, *dwh, *dwl, *s1h, *s1l;
    cudaGetSymbolAddress((void**)&xenc,   g_xenc);
    cudaGetSymbolAddress((void**)&yenc,   g_yenc);
    cudaGetSymbolAddress((void**)&f512aP, g_f512a);
    cudaGetSymbolAddress((void**)&f512bP, g_f512b);
    cudaGetSymbolAddress((void**)&colsP,  g_cols);
    cudaGetSymbolAddress((void**)&colshP, g_colsh);
    cudaGetSymbolAddress((void**)&colslP, g_colsl);
    cudaGetSymbolAddress((void**)&awhP,   g_awh);
    cudaGetSymbolAddress((void**)&awlP,   g_awl);
    cudaGetSymbolAddress((void**)&dwh,    g_dwh);
    cudaGetSymbolAddress((void**)&dwl,    g_dwl);
    cudaGetSymbolAddress((void**)&s1h,    g_s1h);
    cudaGetSymbolAddress((void**)&s1l,    g_s1l);
    cudaGetSymbolAddress((void**)&offP,   g_offb);
    cudaGetSymbolAddress((void**)&cpartP, g_cpart);
    cudaGetSymbolAddress((void**)&f177P,  g_f177);
    cudaGetSymbolAddress((void**)&f177bP, g_f177b);
    cudaGetSymbolAddress((void**)&wb1P,   g_wb1);
    cudaGetSymbolAddress((void**)&wb2P,   g_wb2);
    cudaGetSymbolAddress((void**)&wb3P,   g_wb3);
    cudaGetSymbolAddress((void**)&fwP,    g_fwb);
    cudaGetSymbolAddress((void**)&adwP,   g_adw);
    cudaGetSymbolAddress((void**)&def0,   g_def0);
    cudaGetSymbolAddress((void**)&def1,   g_def1);
    cudaGetSymbolAddress((void**)&s1oP,   g_s1o);
    cudaGetSymbolAddress((void**)&s2oP,   g_s2o);
    cudaGetSymbolAddress((void**)&swa,    g_swa);
    cudaGetSymbolAddress((void**)&swb,    g_swb);

    // per-branch pointers
    auto F512A = [&](int br){ return f512aP + (long long)br * (2*512*HW2); };
    auto F512B = [&](int br){ return f512bP + (long long)br * (2*512*HW2); };
    auto COLS  = [&](int br){ return colsP  + (long long)br * (2*1600*HW2); };
    auto COLSH = [&](int br){ return colshP + (long long)br * (2LL*4608*HW2); };
    auto COLSL = [&](int br){ return colslP + (long long)br * (2LL*4608*HW2); };
    auto AWH   = [&](int br){ return awhP   + (long long)br * (2*256*2304); };
    auto AWL   = [&](int br){ return awlP   + (long long)br * (2*256*2304); };
    auto OFF   = [&](int br){ return offP   + (long long)br * (2*18*HW2); };
    auto CPART = [&](int br){ return cpartP + (long long)br * (16LL*2*18*HW2); };
    auto F177  = [&](int br){ return f177P  + (long long)br * (2*177*HW2); };
    auto F177B = [&](int br){ return f177bP + (long long)br * (2*177*HW2); };
    auto WB1   = [&](int br){ return wb1P + (long long)br * (2*64*576); };
    auto WB2   = [&](int br){ return wb2P + (long long)br * (2*64*144); };
    auto WB3   = [&](int br){ return wb3P + (long long)br * (2*256*36); };
    auto FW    = [&](int br){ return fwP  + (long long)br * (2*256); };
    auto ADW   = [&](int br){ return adwP + (long long)br * (2*256*HW2); };
    auto S1O   = [&](int br){ return s1oP + (long long)br * (2*128*HW2); };
    auto S2O   = [&](int br){ return s2oP + (long long)br * (2*64*HW2); };

    const long long imgStride = 2LL * 256 * HW2;
    const int DW = 512 * 4608;

    cudaStream_t sM = 0, sW0, sS1, sW1;
    cudaStreamCreateWithFlags(&sW0, cudaStreamNonBlocking);
    cudaStreamCreateWithFlags(&sS1, cudaStreamNonBlocking);
    cudaStreamCreateWithFlags(&sW1, cudaStreamNonBlocking);
    cudaEvent_t eInit, eW0, eW1, eB1;
    cudaEventCreateWithFlags(&eInit, cudaEventDisableTiming);
    cudaEventCreateWithFlags(&eW0,   cudaEventDisableTiming);
    cudaEventCreateWithFlags(&eW1,   cudaEventDisableTiming);
    cudaEventCreateWithFlags(&eB1,   cudaEventDisableTiming);

    auto GEMMTB = [&](cudaStream_t st, const u16* Ah, const u16* Al,
                      const u16* Bh, const u16* Bl, float* C,
                      int M, int N, int K,
                      long long sA, long long sB, long long sC, int relu) {
        gemm_bf3b<<<dim3(N / 64, M / 128, 2), 256, 0, st>>>(Ah, Al, Bh, Bl,
                                                            C, M, N, K, sA, sB, sC, relu);
    };
    auto GEMMA = [&](cudaStream_t st, const float* A, const float* Bm, float* C,
                     int M, int N, int K, long long sA, long long sB, long long sC,
                     const float* bias, int relu) {
        gemm_al<4><<<dim3(N / 64, M / 64, 2), 256, 0, st>>>(A, Bm, C, M, N, K,
                                                            sA, sB, sC, bias, relu);
    };
    auto GEMMF = [&](cudaStream_t st, const float* A, const float* Bm, float* C,
                     int M, int N, int K, long long sA, long long sB, long long sC,
                     const float* bias, int relu) {
        dim3 g((N + 63) / 64, (M + 63) / 64, 2);
        gemm64<<<g, dim3(16, 16), 0, st>>>(A, Bm, C, M, N, K, sA, sB, sC, bias, relu);
    };
    auto DIM2COL = [&](cudaStream_t st, const float* src, long long sB,
                       const float* offp, int C, int mode, int br) {
        dim3 g((HW2 + 255) / 256, 18, (C + 63) / 64);
        deform_im2col_k<<<g, 256, 0, st>>>(src, sB, offp, COLS(br),
                                           COLSH(br), COLSL(br), C, mode);
    };
    auto IM2COL = [&](cudaStream_t st, const float* src, long long sB, int C,
                      int H, int W, int KH, int KW, int stp, int pad,
                      int OH, int OW, int br) {
        dim3 g((OH * OW + 255) / 256, C * KH * KW, 2);
        im2col_g<<<g, 256, 0, st>>>(src, sB, COLS(br), C, H, W, KH, KW, stp, pad, OH, OW);
    };
    auto CONV18 = [&](cudaStream_t st, const float* in, long long inB,
                      const float* w, float* o, int br) {
        conv18_k<<<dim3(9, 16, 2), 256, 0, st>>>(in, inB, w, CPART(br), 512);
        reduce18_k<<<(2 * 18 * HW2 + 255) / 256, 256, 0, st>>>(CPART(br), o);
    };
    auto WBRANCH = [&](cudaStream_t st, const float* feat, const float* wa,
                       const float* wb, const float* wc, int Mc, int br) {
        IM2COL(st, feat, 177LL * HW2, 177, 48, 48, 5, 5, 2, 2, 24, 24, br);
        GEMMF(st, wa, COLS(br), WB1(br), 64, 576, 4425, 0, 4425LL * 576, 64LL * 576,
              nullptr, 1);
        IM2COL(st, WB1(br), 64LL * 576, 64, 24, 24, 5, 5, 2, 2, 12, 12, br);
        GEMMF(st, wb, COLS(br), WB2(br), 64, 144, 1600, 0, 1600LL * 144, 64LL * 144,
              nullptr, 1);
        IM2COL(st, WB2(br), 64LL * 144, 64, 12, 12, 3, 3, 2, 1, 6, 6, br);
        GEMMF(st, wc, COLS(br), WB3(br), Mc, 36, 576, 0, 576LL * 36,
              (long long)Mc * 36, nullptr, 0);
        int tot = 2 * Mc;
        mean36_k<<<(tot + 255) / 256, 256, 0, st>>>(WB3(br), FW(br), tot);
    };

    // ---- L0: hoisted weight splits + encoders ----
    for (int i = 0; i < 3; i++)
        convw_k<<<(DW + 255) / 256, 256, 0, sM>>>(defw[i], dwh + (long long)i * DW,
                                                  dwl + (long long)i * DW, DW);
    convw_k<<<(128 * 2304 + 255) / 256, 256, 0, sM>>>(s1w, s1h, s1l, 128 * 2304);
    GEMMA(sM, enc0_w, inp,             xenc, 64, HW2, 256, 0, imgStride, 64LL * HW2, enc0_b, 0);
    GEMMA(sM, enc1_w, inp + 256 * HW2, yenc, 64, HW2, 256, 0, imgStride, 64LL * HW2, enc1_b, 0);
    cudaEventRecord(eInit, sM);
    cudaStreamWaitEvent(sW0, eInit, 0);
    cudaStreamWaitEvent(sS1, eInit, 0);
    cudaStreamWaitEvent(sW1, eInit, 0);

    auto STSN = [&](cudaStream_t st, int br) {
        const float* imgA = (br == 0) ? inp : inp + 256 * HW2;
        const float* imgB = inp + 256 * HW2;
        int tot = 2 * 512 * HW2;
        concat_k<<<(tot + 255) / 256, 256, 0, st>>>(imgA, imgB, F512A(br), imgStride);
        float* cur = F512A(br); float* oth = F512B(br);
        for (int i = 0; i < 3; i++) {
            CONV18(st, cur, 512LL * HW2, offw[i], OFF(br), br);
            DIM2COL(st, cur, 512LL * HW2, OFF(br), 512, 1, br);
            GEMMTB(st, dwh + (long long)i * DW, dwl + (long long)i * DW,
                   COLSH(br), COLSL(br), oth, 512, HW2, 4608,
                   0, 4608LL * HW2, 512LL * HW2, 0);
            float* t = cur; cur = oth; oth = t;
        }
        CONV18(st, cur, 512LL * HW2, offw[3], OFF(br), br);
    };

    auto WEIGHT = [&](cudaStream_t st, int br) {
        const float* Ra = R0 + (br == 0 ? 0 : 64 * HW2);
        const float* Tb = T0 + 64 * HW2;
        const float* eA = (br == 0) ? xenc : yenc;
        const float* eB = yenc;
        int tot = 2 * 49 * HW2;
        corr_k<<<(tot + 255) / 256, 256, 0, st>>>(Ra, Tb, F177(br));
        tot = 2 * 64 * HW2;
        pack_k<<<(tot + 255) / 256, 256, 0, st>>>(eA, eB, F177(br));
        WBRANCH(st, F177(br), w0a, w0b, w0c, 177, br);
        tot = 2 * 177 * 1593;
        mkw_k<<<(tot + 255) / 256, 256, 0, st>>>(FW(br), wx_w, wx_b, ADW(br), 177, 1593, tot);
        DIM2COL(st, F177(br), 177LL * HW2, nullptr, 177, 0, br);
        GEMMF(st, ADW(br), COLS(br), F177B(br), 177, HW2, 1593,
              177LL * 1593, 1593LL * HW2, 177LL * HW2, nullptr, 1);
        WBRANCH(st, F177B(br), w1a, w1b, w1c, 256, br);
        tot = 2 * 256 * 2304;
        mkw_k<<<(tot + 255) / 256, 256, 0, st>>>(FW(br), wxf_w, wxf_b, ADW(br), 256, 2304, tot);
        convw_k<<<(2 * 256 * 2304 + 255) / 256, 256, 0, st>>>(ADW(br), AWH(br), AWL(br),
                                                              2 * 256 * 2304);
    };

    auto TAIL = [&](cudaStream_t st, int br, float* gdef, float* gsw) {
        const float* imgA = (br == 0) ? inp : inp + 256 * HW2;
        DIM2COL(st, imgA, imgStride, OFF(br), 256, 1, br);
        GEMMTB(st, AWH(br), AWL(br), COLSH(br), COLSL(br), gdef, 256, HW2, 2304,
               256LL * 2304, 2304LL * HW2, 256LL * HW2, 0);
        DIM2COL(st, gdef, 256LL * HW2, nullptr, 256, 1, br);
        GEMMTB(st, s1h, s1l, COLSH(br), COLSL(br), S1O(br), 128, HW2, 2304,
               0, 2304LL * HW2, 128LL * HW2, 1);
        DIM2COL(st, S1O(br), 128LL * HW2, nullptr, 128, 0, br);
        GEMMA(st, s2w, COLS(br), S2O(br), 64, HW2, 1152,
              0, 1152LL * HW2, 64LL * HW2, nullptr, 1);
        conv3x3_direct<<<dim3(9, 1, 2), 256, 0, st>>>(S2O(br), 64LL * HW2, s3w, gsw,
                                                      (long long)HW2, 64, 1);
    };

    // branch 0: stsn on L0 (sM), weight on sW0
    STSN(sM, 0);
    WEIGHT(sW0, 0);
    cudaEventRecord(eW0, sW0);
    cudaStreamWaitEvent(sM, eW0, 0);
    TAIL(sM, 0, def0, swa);

    // branch 1: stsn on sS1, weight on sW1
    STSN(sS1, 1);
    WEIGHT(sW1, 1);
    cudaEventRecord(eW1, sW1);
    cudaStreamWaitEvent(sS1, eW1, 0);
    TAIL(sS1, 1, def1, swb);
    cudaEventRecord(eB1, sS1);
    cudaStreamWaitEvent(sM, eB1, 0);

    {
        int tot = 2 * 256 * HW2;
        final_k<<<(tot + 255) / 256, 256, 0, sM>>>(def0, def1, swa, swb, out, tot);
    }

    cudaEventDestroy(eInit);
    cudaEventDestroy(eW0);
    cudaEventDestroy(eW1);
    cudaEventDestroy(eB1);
    cudaStreamDestroy(sW0);
    cudaStreamDestroy(sS1);
    cudaStreamDestroy(sW1);
}